// round 1
// baseline (speedup 1.0000x reference)
#include <cuda_runtime.h>
#include <math.h>

// ---------------- problem constants ----------------
#define NBATCH 4
#define NHEAD  8
#define BHN    (NBATCH*NHEAD)      // 32
#define NTOK   4096
#define CDIM   512
#define HD     64
#define MLAND  64
#define KSPLIT 16
#define SCALE  0.35355339059327373f   // 64^-0.25

// ---------------- device scratch (no cudaMalloc allowed) ----------------
__device__ float g_Q [BHN*NTOK*HD];        // scaled Q  [bh][n][d]
__device__ float g_K [BHN*NTOK*HD];        // scaled K
__device__ float g_V [BHN*NTOK*HD];
__device__ float g_Ql[BHN*MLAND*HD];
__device__ float g_Kl[BHN*MLAND*HD];
__device__ float g_K2[BHN*MLAND*MLAND];    // softmax(Ql Kl^T)
__device__ float g_W [BHN*MLAND*HD];       // inv(K2) @ (K3 @ V)
__device__ float g_S3[BHN*MLAND*NTOK];     // softmax(Ql K^T)
__device__ float g_Tpart[KSPLIT*BHN*MLAND*HD];
__device__ float g_T [BHN*MLAND*HD];       // K3 @ V
__device__ float g_X [NBATCH*NTOK*CDIM];   // attention output, [b][n][h*64+d]
__device__ float g_colmax;

// =====================================================================
// GEMM 1: QKV = x @ qkv_w^T ; scatter into Q/K/V with scale on Q,K.
// C[i,j] = sum_k A[i,k]*B[j,k];  M=16384, N=1536, K=512
// 128x128x16 tile, 256 threads, 8x8 per thread.
// =====================================================================
__global__ __launch_bounds__(256) void gemm_qkv(const float* __restrict__ A,
                                                const float* __restrict__ B) {
    __shared__ float As[16][128];
    __shared__ float Bs[16][128];
    const int K = 512;
    int tid = threadIdx.x;
    int rowBase = blockIdx.y * 128;
    int colBase = blockIdx.x * 128;
    int tx = tid & 15, ty = tid >> 4;
    int lr = tid >> 2;
    int lc = (tid & 3) << 2;
    float acc[8][8] = {};

    for (int k0 = 0; k0 < K; k0 += 16) {
#pragma unroll
        for (int r = 0; r < 2; r++) {
            int row = lr + r * 64;
            float4 va = *(const float4*)(A + (size_t)(rowBase + row) * K + k0 + lc);
            As[lc+0][row] = va.x; As[lc+1][row] = va.y;
            As[lc+2][row] = va.z; As[lc+3][row] = va.w;
            float4 vb = *(const float4*)(B + (size_t)(colBase + row) * K + k0 + lc);
            Bs[lc+0][row] = vb.x; Bs[lc+1][row] = vb.y;
            Bs[lc+2][row] = vb.z; Bs[lc+3][row] = vb.w;
        }
        __syncthreads();
#pragma unroll
        for (int kk = 0; kk < 16; kk++) {
            float ar[8], br[8];
            *(float4*)(ar)   = *(const float4*)(&As[kk][ty*8]);
            *(float4*)(ar+4) = *(const float4*)(&As[kk][ty*8+4]);
            *(float4*)(br)   = *(const float4*)(&Bs[kk][tx*8]);
            *(float4*)(br+4) = *(const float4*)(&Bs[kk][tx*8+4]);
#pragma unroll
            for (int i = 0; i < 8; i++)
#pragma unroll
                for (int j = 0; j < 8; j++)
                    acc[i][j] = fmaf(ar[i], br[j], acc[i][j]);
        }
        __syncthreads();
    }
#pragma unroll
    for (int i = 0; i < 8; i++) {
        int row = rowBase + ty * 8 + i;
        int b = row >> 12, n = row & 4095;
#pragma unroll
        for (int j = 0; j < 8; j++) {
            int col = colBase + tx * 8 + j;
            int which = col >> 9;           // 0:Q 1:K 2:V
            int h = (col >> 6) & 7;
            int d = col & 63;
            size_t idx = (((size_t)(b * 8 + h)) * NTOK + n) * HD + d;
            float v = acc[i][j];
            if (which == 0)      g_Q[idx] = v * SCALE;
            else if (which == 1) g_K[idx] = v * SCALE;
            else                 g_V[idx] = v;
        }
    }
}

// =====================================================================
// GEMM 2: out = g_X @ proj_w^T + proj_b ; M=16384, N=512, K=512
// =====================================================================
__global__ __launch_bounds__(256) void gemm_proj(const float* __restrict__ B,
                                                 const float* __restrict__ bias,
                                                 float* __restrict__ out) {
    __shared__ float As[16][128];
    __shared__ float Bs[16][128];
    const int K = 512;
    const float* A = g_X;
    int tid = threadIdx.x;
    int rowBase = blockIdx.y * 128;
    int colBase = blockIdx.x * 128;
    int tx = tid & 15, ty = tid >> 4;
    int lr = tid >> 2;
    int lc = (tid & 3) << 2;
    float acc[8][8] = {};

    for (int k0 = 0; k0 < K; k0 += 16) {
#pragma unroll
        for (int r = 0; r < 2; r++) {
            int row = lr + r * 64;
            float4 va = *(const float4*)(A + (size_t)(rowBase + row) * K + k0 + lc);
            As[lc+0][row] = va.x; As[lc+1][row] = va.y;
            As[lc+2][row] = va.z; As[lc+3][row] = va.w;
            float4 vb = *(const float4*)(B + (size_t)(colBase + row) * K + k0 + lc);
            Bs[lc+0][row] = vb.x; Bs[lc+1][row] = vb.y;
            Bs[lc+2][row] = vb.z; Bs[lc+3][row] = vb.w;
        }
        __syncthreads();
#pragma unroll
        for (int kk = 0; kk < 16; kk++) {
            float ar[8], br[8];
            *(float4*)(ar)   = *(const float4*)(&As[kk][ty*8]);
            *(float4*)(ar+4) = *(const float4*)(&As[kk][ty*8+4]);
            *(float4*)(br)   = *(const float4*)(&Bs[kk][tx*8]);
            *(float4*)(br+4) = *(const float4*)(&Bs[kk][tx*8+4]);
#pragma unroll
            for (int i = 0; i < 8; i++)
#pragma unroll
                for (int j = 0; j < 8; j++)
                    acc[i][j] = fmaf(ar[i], br[j], acc[i][j]);
        }
        __syncthreads();
    }
#pragma unroll
    for (int i = 0; i < 8; i++) {
        int row = rowBase + ty * 8 + i;
#pragma unroll
        for (int j = 0; j < 8; j++) {
            int col = colBase + tx * 8 + j;
            out[(size_t)row * 512 + col] = acc[i][j] + bias[col];
        }
    }
}

// =====================================================================
// Landmark pooling: mean over segments of 64 tokens.
// grid: BHN*MLAND blocks, 64 threads (d)
// =====================================================================
__global__ void pool_kernel() {
    int bm = blockIdx.x;
    int bh = bm >> 6, m = bm & 63;
    int d = threadIdx.x;
    const float* qp = g_Q + (((size_t)bh * NTOK) + m * 64) * HD + d;
    const float* kp = g_K + (((size_t)bh * NTOK) + m * 64) * HD + d;
    float sq = 0.f, sk = 0.f;
#pragma unroll 8
    for (int t = 0; t < 64; t++) { sq += qp[(size_t)t * HD]; sk += kp[(size_t)t * HD]; }
    g_Ql[(bh * 64 + m) * 64 + d] = sq * (1.f / 64.f);
    g_Kl[(bh * 64 + m) * 64 + d] = sk * (1.f / 64.f);
}

__global__ void reset_kernel() { g_colmax = 0.0f; }

// =====================================================================
// kernel_2 = softmax(Ql @ Kl^T), plus global max of column sums.
// 32 blocks, 256 threads
// =====================================================================
__global__ __launch_bounds__(256) void k2_kernel() {
    __shared__ float Qs[64][68];
    __shared__ float Ks[64][68];
    int bh = blockIdx.x, tid = threadIdx.x;
    for (int i = tid; i < 4096; i += 256) {
        Qs[i >> 6][i & 63] = g_Ql[bh * 4096 + i];
        Ks[i >> 6][i & 63] = g_Kl[bh * 4096 + i];
    }
    __syncthreads();
    int ty = tid >> 4, tx = tid & 15, r0 = ty * 4, c0 = tx * 4;
    float acc[4][4] = {};
    for (int k = 0; k < 64; k++) {
        float a[4], b[4];
#pragma unroll
        for (int i = 0; i < 4; i++) a[i] = Qs[r0 + i][k];
#pragma unroll
        for (int j = 0; j < 4; j++) b[j] = Ks[c0 + j][k];
#pragma unroll
        for (int i = 0; i < 4; i++)
#pragma unroll
            for (int j = 0; j < 4; j++) acc[i][j] = fmaf(a[i], b[j], acc[i][j]);
    }
    __syncthreads();
#pragma unroll
    for (int i = 0; i < 4; i++)
#pragma unroll
        for (int j = 0; j < 4; j++) Qs[r0 + i][c0 + j] = acc[i][j];
    __syncthreads();
    if (tid < 64) {
        float mx = -1e30f;
        for (int c = 0; c < 64; c++) mx = fmaxf(mx, Qs[tid][c]);
        float s = 0.f;
        for (int c = 0; c < 64; c++) { float e = expf(Qs[tid][c] - mx); Qs[tid][c] = e; s += e; }
        float inv = 1.f / s;
        for (int c = 0; c < 64; c++) {
            float v = Qs[tid][c] * inv;
            Qs[tid][c] = v;
            g_K2[bh * 4096 + tid * 64 + c] = v;
        }
    }
    __syncthreads();
    if (tid < 64) {
        float cs = 0.f;
        for (int r = 0; r < 64; r++) cs += Qs[r][tid];
        atomicMax((int*)&g_colmax, __float_as_int(cs));  // positive floats
    }
}

// =====================================================================
// kernel_3 scores: S3[bh][m][n] = Ql[bh][m]·K[bh][n]
// grid (64 n-tiles, 32 bh), 256 threads
// =====================================================================
__global__ __launch_bounds__(256) void k3_kernel() {
    __shared__ float Qs[64][68];
    __shared__ float Ks[64][68];
    int nt = blockIdx.x, bh = blockIdx.y, tid = threadIdx.x;
    for (int i = tid; i < 4096; i += 256) {
        Qs[i >> 6][i & 63] = g_Ql[bh * 4096 + i];
        Ks[i >> 6][i & 63] = g_K[(((size_t)bh * NTOK) + nt * 64) * HD + i];
    }
    __syncthreads();
    int ty = tid >> 4, tx = tid & 15, r0 = ty * 4, c0 = tx * 4;
    float acc[4][4] = {};
    for (int k = 0; k < 64; k++) {
        float a[4], b[4];
#pragma unroll
        for (int i = 0; i < 4; i++) a[i] = Qs[r0 + i][k];
#pragma unroll
        for (int j = 0; j < 4; j++) b[j] = Ks[c0 + j][k];
#pragma unroll
        for (int i = 0; i < 4; i++)
#pragma unroll
            for (int j = 0; j < 4; j++) acc[i][j] = fmaf(a[i], b[j], acc[i][j]);
    }
#pragma unroll
    for (int i = 0; i < 4; i++)
#pragma unroll
        for (int j = 0; j < 4; j++)
            g_S3[((size_t)bh * 64 + r0 + i) * NTOK + nt * 64 + c0 + j] = acc[i][j];
}

// =====================================================================
// row softmax over N=4096 for S3.  One block per row.
// =====================================================================
__global__ __launch_bounds__(256) void softmax3_kernel() {
    __shared__ float redA[8], redB[8];
    int row = blockIdx.x, tid = threadIdx.x;
    float* p = g_S3 + (size_t)row * NTOK;
    float v[16];
    float mx = -1e30f;
#pragma unroll
    for (int i = 0; i < 16; i++) { v[i] = p[tid + i * 256]; mx = fmaxf(mx, v[i]); }
#pragma unroll
    for (int o = 16; o; o >>= 1) mx = fmaxf(mx, __shfl_xor_sync(~0u, mx, o));
    if ((tid & 31) == 0) redA[tid >> 5] = mx;
    __syncthreads();
    mx = redA[0];
#pragma unroll
    for (int w = 1; w < 8; w++) mx = fmaxf(mx, redA[w]);
    float s = 0.f;
#pragma unroll
    for (int i = 0; i < 16; i++) { v[i] = expf(v[i] - mx); s += v[i]; }
#pragma unroll
    for (int o = 16; o; o >>= 1) s += __shfl_xor_sync(~0u, s, o);
    if ((tid & 31) == 0) redB[tid >> 5] = s;
    __syncthreads();
    s = 0.f;
#pragma unroll
    for (int w = 0; w < 8; w++) s += redB[w];
    float inv = 1.f / s;
#pragma unroll
    for (int i = 0; i < 16; i++) p[tid + i * 256] = v[i] * inv;
}

// =====================================================================
// T = K3 @ V, split-K over n (16 partials).  grid (16, 32), 256 thr.
// =====================================================================
__global__ __launch_bounds__(256) void tpart_kernel() {
    __shared__ float Ss[64][68];
    __shared__ float Vs[64][68];
    int ks = blockIdx.x, bh = blockIdx.y, tid = threadIdx.x;
    int ty = tid >> 4, tx = tid & 15, r0 = ty * 4, c0 = tx * 4;
    float acc[4][4] = {};
    for (int c4 = 0; c4 < 4; c4++) {
        int n0 = ks * 256 + c4 * 64;
        for (int i = tid; i < 4096; i += 256) {
            int m = i >> 6, nl = i & 63;
            Ss[m][nl]  = g_S3[((size_t)bh * 64 + m) * NTOK + n0 + nl];
            Vs[m][nl]  = g_V[(((size_t)bh * NTOK) + n0 + m) * HD + nl];
        }
        __syncthreads();
        for (int k = 0; k < 64; k++) {
            float a[4], b[4];
#pragma unroll
            for (int i = 0; i < 4; i++) a[i] = Ss[r0 + i][k];
            *(float4*)b = *(const float4*)&Vs[k][c0];
#pragma unroll
            for (int i = 0; i < 4; i++)
#pragma unroll
                for (int j = 0; j < 4; j++) acc[i][j] = fmaf(a[i], b[j], acc[i][j]);
        }
        __syncthreads();
    }
#pragma unroll
    for (int i = 0; i < 4; i++)
#pragma unroll
        for (int j = 0; j < 4; j++)
            g_Tpart[(((size_t)ks * BHN + bh) * 64 + r0 + i) * 64 + c0 + j] = acc[i][j];
}

__global__ void treduce_kernel() {
    int idx = blockIdx.x * 256 + threadIdx.x;   // 32*64*64 = 131072
    float s = 0.f;
#pragma unroll
    for (int ks = 0; ks < KSPLIT; ks++) s += g_Tpart[(size_t)ks * (BHN * MLAND * HD) + idx];
    g_T[idx] = s;
}

// =====================================================================
// Newton-Schulz inverse (6 iters) + W = Vinv @ T.  32 blocks, 256 thr.
// dynamic smem: 5 * 64 * 65 floats
// =====================================================================
__device__ __forceinline__ void mm64(const float* __restrict__ X,
                                     const float* __restrict__ Y,
                                     float* __restrict__ Z, int tid) {
    int ty = tid >> 4, tx = tid & 15, r0 = ty * 4, c0 = tx * 4;
    float acc[4][4] = {};
    for (int k = 0; k < 64; k++) {
        float a[4], b[4];
#pragma unroll
        for (int i = 0; i < 4; i++) a[i] = X[(r0 + i) * 65 + k];
#pragma unroll
        for (int j = 0; j < 4; j++) b[j] = Y[k * 65 + c0 + j];
#pragma unroll
        for (int i = 0; i < 4; i++)
#pragma unroll
            for (int j = 0; j < 4; j++) acc[i][j] = fmaf(a[i], b[j], acc[i][j]);
    }
#pragma unroll
    for (int i = 0; i < 4; i++)
#pragma unroll
        for (int j = 0; j < 4; j++) Z[(r0 + i) * 65 + c0 + j] = acc[i][j];
}

__global__ __launch_bounds__(256) void inv_kernel() {
    extern __shared__ float sh[];
    float* Km = sh;
    float* Vm = sh + 64 * 65;
    float* Am = sh + 2 * 64 * 65;
    float* T1 = sh + 3 * 64 * 65;
    float* T2 = sh + 4 * 64 * 65;
    int bh = blockIdx.x, tid = threadIdx.x;
    float ginv = 1.f / g_colmax;   // max row-sum == 1 (softmax rows)
    for (int i = tid; i < 4096; i += 256) {
        int r = i >> 6, c = i & 63;
        Km[r * 65 + c] = g_K2[bh * 4096 + r * 64 + c];
        Vm[r * 65 + c] = g_K2[bh * 4096 + c * 64 + r] * ginv;  // K^T / denom
    }
    for (int it = 0; it < 6; it++) {
        __syncthreads();
        mm64(Km, Vm, Am, tid);                    // A = K V
        __syncthreads();
        for (int i = tid; i < 4096; i += 256) {   // T1 = 7I - A
            int r = i >> 6, c = i & 63;
            T1[r * 65 + c] = (r == c ? 7.0f : 0.0f) - Am[r * 65 + c];
        }
        __syncthreads();
        mm64(Am, T1, T2, tid);                    // T2 = A(7I - A)
        __syncthreads();
        for (int i = tid; i < 4096; i += 256) {   // T2 = 15I - T2
            int r = i >> 6, c = i & 63;
            T2[r * 65 + c] = (r == c ? 15.0f : 0.0f) - T2[r * 65 + c];
        }
        __syncthreads();
        mm64(Am, T2, T1, tid);                    // T1 = A(15I - ...)
        __syncthreads();
        for (int i = tid; i < 4096; i += 256) {   // T1 = 13I - T1
            int r = i >> 6, c = i & 63;
            T1[r * 65 + c] = (r == c ? 13.0f : 0.0f) - T1[r * 65 + c];
        }
        __syncthreads();
        mm64(Vm, T1, T2, tid);                    // T2 = V(13I - ...)
        __syncthreads();
        for (int i = tid; i < 4096; i += 256) {
            int r = i >> 6, c = i & 63;
            Vm[r * 65 + c] = 0.25f * T2[r * 65 + c];
        }
    }
    __syncthreads();
    for (int i = tid; i < 4096; i += 256) {       // load T into Am
        int r = i >> 6, c = i & 63;
        Am[r * 65 + c] = g_T[bh * 4096 + i];
    }
    __syncthreads();
    mm64(Vm, Am, T1, tid);                        // W = Vinv @ T
    __syncthreads();
    for (int i = tid; i < 4096; i += 256) {
        int r = i >> 6, c = i & 63;
        g_W[bh * 4096 + i] = T1[r * 65 + c];
    }
}

// =====================================================================
// Final fused: softmax(Q @ Kl^T) @ W  -> g_X[b][n][h*64+d]
// grid (64 n-tiles, 32 bh), 256 threads; P kept in registers,
// row softmax + P broadcast via width-16 shuffles.
// =====================================================================
__global__ __launch_bounds__(256) void final_attn() {
    __shared__ float Qs[64][68];
    __shared__ float Bs[64][68];
    int nt = blockIdx.x, bh = blockIdx.y, tid = threadIdx.x;
    int b = bh >> 3, h = bh & 7;
    int ty = tid >> 4, tx = tid & 15, r0 = ty * 4, c0 = tx * 4;
    for (int i = tid; i < 4096; i += 256) {
        Qs[i >> 6][i & 63] = g_Q[(((size_t)bh * NTOK) + nt * 64) * HD + i];
        Bs[i >> 6][i & 63] = g_Kl[bh * 4096 + i];
    }
    __syncthreads();
    float s[4][4] = {};
    for (int k = 0; k < 64; k++) {
        float a[4], bb[4];
#pragma unroll
        for (int i = 0; i < 4; i++) a[i] = Qs[r0 + i][k];
#pragma unroll
        for (int j = 0; j < 4; j++) bb[j] = Bs[c0 + j][k];
#pragma unroll
        for (int i = 0; i < 4; i++)
#pragma unroll
            for (int j = 0; j < 4; j++) s[i][j] = fmaf(a[i], bb[j], s[i][j]);
    }
    // softmax per row; row i spread across 16 lanes (same ty, consecutive lanes)
#pragma unroll
    for (int i = 0; i < 4; i++) {
        float mx = fmaxf(fmaxf(s[i][0], s[i][1]), fmaxf(s[i][2], s[i][3]));
#pragma unroll
        for (int o = 8; o; o >>= 1) mx = fmaxf(mx, __shfl_xor_sync(~0u, mx, o, 16));
        float ss = 0.f;
#pragma unroll
        for (int j = 0; j < 4; j++) { s[i][j] = expf(s[i][j] - mx); ss += s[i][j]; }
#pragma unroll
        for (int o = 8; o; o >>= 1) ss += __shfl_xor_sync(~0u, ss, o, 16);
        float inv = 1.f / ss;
#pragma unroll
        for (int j = 0; j < 4; j++) s[i][j] *= inv;
    }
    __syncthreads();
    for (int i = tid; i < 4096; i += 256)     // reload Bs <- W
        Bs[i >> 6][i & 63] = g_W[bh * 4096 + i];
    __syncthreads();
    float acc[4][4] = {};
#pragma unroll
    for (int mo = 0; mo < 16; mo++) {
#pragma unroll
        for (int mi = 0; mi < 4; mi++) {
            float w[4];
            *(float4*)w = *(const float4*)&Bs[mo * 4 + mi][c0];
#pragma unroll
            for (int i = 0; i < 4; i++) {
                float pv = __shfl_sync(~0u, s[i][mi], mo, 16);
#pragma unroll
                for (int j = 0; j < 4; j++) acc[i][j] = fmaf(pv, w[j], acc[i][j]);
            }
        }
    }
#pragma unroll
    for (int i = 0; i < 4; i++)
#pragma unroll
        for (int j = 0; j < 4; j++)
            g_X[(((size_t)b * NTOK) + nt * 64 + r0 + i) * CDIM + h * 64 + c0 + j] = acc[i][j];
}

// =====================================================================
// host launcher
// =====================================================================
extern "C" void kernel_launch(void* const* d_in, const int* in_sizes, int n_in,
                              void* d_out, int out_size) {
    const float* x      = (const float*)d_in[0];
    const float* qkv_w  = (const float*)d_in[1];
    const float* proj_w = (const float*)d_in[2];
    const float* proj_b = (const float*)d_in[3];
    float* out = (float*)d_out;

    gemm_qkv<<<dim3(12, 128), 256>>>(x, qkv_w);
    pool_kernel<<<BHN * MLAND, 64>>>();
    reset_kernel<<<1, 1>>>();
    k2_kernel<<<BHN, 256>>>();
    k3_kernel<<<dim3(64, BHN), 256>>>();
    softmax3_kernel<<<BHN * MLAND, 256>>>();
    tpart_kernel<<<dim3(KSPLIT, BHN), 256>>>();
    treduce_kernel<<<(BHN * MLAND * HD) / 256, 256>>>();

    const int INV_SMEM = 5 * 64 * 65 * sizeof(float);
    cudaFuncSetAttribute(inv_kernel, cudaFuncAttributeMaxDynamicSharedMemorySize, INV_SMEM);
    inv_kernel<<<BHN, 256, INV_SMEM>>>();

    final_attn<<<dim3(64, BHN), 256>>>();
    gemm_proj<<<dim3(4, 128), 256>>>(proj_w, proj_b, out);
}

// round 3
// speedup vs baseline: 1.6766x; 1.6766x over previous
#include <cuda_runtime.h>
#include <cuda_bf16.h>
#include <math.h>
#include <stdint.h>

// ---------------- problem constants ----------------
#define NBATCH 4
#define NHEAD  8
#define BHN    (NBATCH*NHEAD)      // 32
#define NTOK   4096
#define CDIM   512
#define HD     64
#define MLAND  64
#define KSPLIT 16
#define SCALE  0.35355339059327373f   // 64^-0.25

// ---------------- device scratch (no cudaMalloc allowed) ----------------
__device__ float g_Q [BHN*NTOK*HD];
__device__ float g_K [BHN*NTOK*HD];
__device__ float g_V [BHN*NTOK*HD];
__device__ float g_Ql[BHN*MLAND*HD];
__device__ float g_Kl[BHN*MLAND*HD];
__device__ float g_K2[BHN*MLAND*MLAND];
__device__ float g_W [BHN*MLAND*HD];
__device__ float g_S3[BHN*MLAND*NTOK];
__device__ float g_Tpart[KSPLIT*BHN*MLAND*HD];
__device__ float g_T [BHN*MLAND*HD];
__device__ float g_colmax;

// bf16 hi/mid split buffers
__device__ __nv_bfloat16 g_xhi [16384*512];
__device__ __nv_bfloat16 g_xmid[16384*512];
__device__ __nv_bfloat16 g_whi [1536*512];
__device__ __nv_bfloat16 g_wmid[1536*512];
__device__ __nv_bfloat16 g_phi [512*512];
__device__ __nv_bfloat16 g_pmid[512*512];
__device__ __nv_bfloat16 g_Xhi [16384*512];
__device__ __nv_bfloat16 g_Xmid[16384*512];

// ==================== PTX helpers (compute_103-legal only) ====================
__device__ __forceinline__ uint32_t smem_u32(const void* p) {
    uint32_t a;
    asm("{ .reg .u64 t; cvta.to.shared.u64 t, %1; cvt.u32.u64 %0, t; }" : "=r"(a) : "l"(p));
    return a;
}
__device__ __forceinline__ void ldsm_x4(uint32_t& r0, uint32_t& r1, uint32_t& r2, uint32_t& r3,
                                        uint32_t addr) {
    asm volatile("ldmatrix.sync.aligned.m8n8.x4.shared.b16 {%0,%1,%2,%3}, [%4];"
                 : "=r"(r0), "=r"(r1), "=r"(r2), "=r"(r3) : "r"(addr));
}
__device__ __forceinline__ void mma16816(float* c, const uint32_t* a, const uint32_t* b) {
    asm volatile("mma.sync.aligned.m16n8k16.row.col.f32.bf16.bf16.f32 "
                 "{%0,%1,%2,%3}, {%4,%5,%6,%7}, {%8,%9}, {%0,%1,%2,%3};"
                 : "+f"(c[0]), "+f"(c[1]), "+f"(c[2]), "+f"(c[3])
                 : "r"(a[0]), "r"(a[1]), "r"(a[2]), "r"(a[3]), "r"(b[0]), "r"(b[1]));
}
#define CP_ASYNC(dst, src) asm volatile("cp.async.cg.shared.global [%0], [%1], 16;" :: "r"(dst), "l"(src))
#define CP_COMMIT()        asm volatile("cp.async.commit_group;" ::: "memory")
#define CP_WAIT1()         asm volatile("cp.async.wait_group 1;" ::: "memory")
#define CP_WAIT0()         asm volatile("cp.async.wait_group 0;" ::: "memory")

// ==================== bf16 3x-split HMMA GEMM ====================
// C[i,j] = sum_k A[i,k]*B[j,k]; A [M,512] hi/mid bf16, B [Nrows,512] hi/mid bf16.
// CTA tile 128x128, 8 warps (2 M x 4 N), warp tile 64x32. K chunk 32, cp.async 2-stage.
// MODE 0: QKV epilogue (scatter to g_Q/g_K/g_V with SCALE on Q,K)
// MODE 1: proj epilogue (out = C + bias)
#define PITCH 40                    // bf16 elems per smem row (32 + 8 pad -> 80B pitch)
#define MAT_BYTES (128*PITCH*2)     // 10240
#define SM_A_HI  0
#define SM_A_MID (1*MAT_BYTES)
#define SM_B_HI  (2*MAT_BYTES)
#define SM_B_MID (3*MAT_BYTES)
#define BUF_BYTES (4*MAT_BYTES)     // 40960
#define GEMM_SMEM (2*BUF_BYTES)     // 81920

__device__ __forceinline__ void load_stage(uint32_t bufb, int k0, size_t rowA0, size_t rowB0,
                                           const __nv_bfloat16* __restrict__ Ahi,
                                           const __nv_bfloat16* __restrict__ Amid,
                                           const __nv_bfloat16* __restrict__ Bhi,
                                           const __nv_bfloat16* __restrict__ Bmid,
                                           int tid) {
#pragma unroll
    for (int half = 0; half < 2; half++) {
        int c = tid + half * 256;            // 0..511
        int r = c >> 2, cc = (c & 3) * 8;
        uint32_t d = bufb + (uint32_t)(r * PITCH + cc) * 2;
        size_t goffA = (rowA0 + r) * 512 + k0 + cc;
        size_t goffB = (rowB0 + r) * 512 + k0 + cc;
        CP_ASYNC(d + SM_A_HI,  Ahi  + goffA);
        CP_ASYNC(d + SM_A_MID, Amid + goffA);
        CP_ASYNC(d + SM_B_HI,  Bhi  + goffB);
        CP_ASYNC(d + SM_B_MID, Bmid + goffB);
    }
    CP_COMMIT();
}

template<int MODE>
__global__ __launch_bounds__(256, 1) void hmma_gemm(
    const __nv_bfloat16* __restrict__ Ahi, const __nv_bfloat16* __restrict__ Amid,
    const __nv_bfloat16* __restrict__ Bhi, const __nv_bfloat16* __restrict__ Bmid,
    const float* __restrict__ bias, float* __restrict__ Cout)
{
    extern __shared__ __align__(128) char sm[];
    uint32_t sb = smem_u32(sm);
    int tid = threadIdx.x;
    int lane = tid & 31, wid = tid >> 5;
    int wm = wid >> 2, wn = wid & 3;
    size_t rowA0 = (size_t)blockIdx.y * 128;
    size_t rowB0 = (size_t)blockIdx.x * 128;

    float acc[4][4][4] = {};

    // ldmatrix lane addressing (within warp tile)
    int arow  = wm * 64 + (lane & 15);
    int akoff = (lane >> 4) * 8;
    int brow  = wn * 32 + (lane & 7) + ((lane >> 4) << 3);
    int bkoff = ((lane >> 3) & 1) * 8;

    load_stage(sb, 0, rowA0, rowB0, Ahi, Amid, Bhi, Bmid, tid);

    for (int t = 0; t < 16; t++) {
        if (t + 1 < 16) {
            load_stage(sb + ((t + 1) & 1) * BUF_BYTES, (t + 1) * 32, rowA0, rowB0,
                       Ahi, Amid, Bhi, Bmid, tid);
            CP_WAIT1();
        } else {
            CP_WAIT0();
        }
        __syncthreads();

        uint32_t base = sb + (t & 1) * BUF_BYTES;
#pragma unroll
        for (int kk = 0; kk < 32; kk += 16) {
            uint32_t ahi[4][4], amid[4][4];
#pragma unroll
            for (int mi = 0; mi < 4; mi++) {
                uint32_t off = (uint32_t)((arow + mi * 16) * PITCH + kk + akoff) * 2;
                ldsm_x4(ahi[mi][0], ahi[mi][1], ahi[mi][2], ahi[mi][3], base + SM_A_HI + off);
                ldsm_x4(amid[mi][0], amid[mi][1], amid[mi][2], amid[mi][3], base + SM_A_MID + off);
            }
            uint32_t bhi[4][2], bmid[4][2];
#pragma unroll
            for (int np = 0; np < 2; np++) {
                uint32_t off = (uint32_t)((brow + np * 16) * PITCH + kk + bkoff) * 2;
                uint32_t r0, r1, r2, r3;
                ldsm_x4(r0, r1, r2, r3, base + SM_B_HI + off);
                bhi[np * 2][0] = r0; bhi[np * 2][1] = r1;
                bhi[np * 2 + 1][0] = r2; bhi[np * 2 + 1][1] = r3;
                ldsm_x4(r0, r1, r2, r3, base + SM_B_MID + off);
                bmid[np * 2][0] = r0; bmid[np * 2][1] = r1;
                bmid[np * 2 + 1][0] = r2; bmid[np * 2 + 1][1] = r3;
            }
#pragma unroll
            for (int mi = 0; mi < 4; mi++)
#pragma unroll
                for (int ni = 0; ni < 4; ni++) {
                    mma16816(acc[mi][ni], ahi[mi], bhi[ni]);
                    mma16816(acc[mi][ni], ahi[mi], bmid[ni]);
                    mma16816(acc[mi][ni], amid[mi], bhi[ni]);
                }
        }
        __syncthreads();
    }

    // ---- epilogue: acc frag (c0,c1)=(row, col..col+1), (c2,c3)=(row+8, col..col+1)
    int colW = blockIdx.x * 128 + wn * 32 + 2 * (lane & 3);
    int rowW = blockIdx.y * 128 + wm * 64 + (lane >> 2);
#pragma unroll
    for (int ni = 0; ni < 4; ni++) {
        int col = colW + ni * 8;
#pragma unroll
        for (int mi = 0; mi < 4; mi++) {
            int row0 = rowW + mi * 16;
            if (MODE == 0) {
                int which = col >> 9;
                int h = (col >> 6) & 7;
                int d = col & 63;
                float m = (which == 2) ? 1.0f : SCALE;
                float* basep = (which == 0) ? g_Q : ((which == 1) ? g_K : g_V);
#pragma unroll
                for (int rr = 0; rr < 2; rr++) {
                    int row = row0 + rr * 8;
                    int b = row >> 12, n = row & 4095;
                    float2 v;
                    v.x = acc[mi][ni][rr * 2 + 0] * m;
                    v.y = acc[mi][ni][rr * 2 + 1] * m;
                    *(float2*)(basep + ((size_t)(b * 8 + h) * NTOK + n) * HD + d) = v;
                }
            } else {
                float2 bb = *(const float2*)(bias + col);
#pragma unroll
                for (int rr = 0; rr < 2; rr++) {
                    int row = row0 + rr * 8;
                    float2 v;
                    v.x = acc[mi][ni][rr * 2 + 0] + bb.x;
                    v.y = acc[mi][ni][rr * 2 + 1] + bb.y;
                    *(float2*)(Cout + (size_t)row * 512 + col) = v;
                }
            }
        }
    }
}

// ==================== fp32 -> bf16 hi/mid split ====================
__global__ void split_kernel(const float* __restrict__ src,
                             __nv_bfloat16* __restrict__ hi,
                             __nv_bfloat16* __restrict__ mid, int n4) {
    int i = blockIdx.x * 256 + threadIdx.x;
    if (i >= n4) return;
    float4 v = ((const float4*)src)[i];
    __nv_bfloat16 h0 = __float2bfloat16(v.x);
    __nv_bfloat16 h1 = __float2bfloat16(v.y);
    __nv_bfloat16 h2 = __float2bfloat16(v.z);
    __nv_bfloat16 h3 = __float2bfloat16(v.w);
    __nv_bfloat162* hp = (__nv_bfloat162*)hi;
    __nv_bfloat162* mp = (__nv_bfloat162*)mid;
    hp[i * 2 + 0] = __nv_bfloat162(h0, h1);
    hp[i * 2 + 1] = __nv_bfloat162(h2, h3);
    mp[i * 2 + 0] = __nv_bfloat162(__float2bfloat16(v.x - __bfloat162float(h0)),
                                   __float2bfloat16(v.y - __bfloat162float(h1)));
    mp[i * 2 + 1] = __nv_bfloat162(__float2bfloat16(v.z - __bfloat162float(h2)),
                                   __float2bfloat16(v.w - __bfloat162float(h3)));
}

// =====================================================================
// Landmark pooling: mean over segments of 64 tokens.
// =====================================================================
__global__ void pool_kernel() {
    int bm = blockIdx.x;
    int bh = bm >> 6, m = bm & 63;
    int d = threadIdx.x;
    const float* qp = g_Q + (((size_t)bh * NTOK) + m * 64) * HD + d;
    const float* kp = g_K + (((size_t)bh * NTOK) + m * 64) * HD + d;
    float sq = 0.f, sk = 0.f;
#pragma unroll 8
    for (int t = 0; t < 64; t++) { sq += qp[(size_t)t * HD]; sk += kp[(size_t)t * HD]; }
    g_Ql[(bh * 64 + m) * 64 + d] = sq * (1.f / 64.f);
    g_Kl[(bh * 64 + m) * 64 + d] = sk * (1.f / 64.f);
}

__global__ void reset_kernel() { g_colmax = 0.0f; }

// =====================================================================
// kernel_2 = softmax(Ql @ Kl^T), plus global max of column sums.
// =====================================================================
__global__ __launch_bounds__(256) void k2_kernel() {
    __shared__ float Qs[64][68];
    __shared__ float Ks[64][68];
    int bh = blockIdx.x, tid = threadIdx.x;
    for (int i = tid; i < 4096; i += 256) {
        Qs[i >> 6][i & 63] = g_Ql[bh * 4096 + i];
        Ks[i >> 6][i & 63] = g_Kl[bh * 4096 + i];
    }
    __syncthreads();
    int ty = tid >> 4, tx = tid & 15, r0 = ty * 4, c0 = tx * 4;
    float acc[4][4] = {};
    for (int k = 0; k < 64; k++) {
        float a[4], b[4];
#pragma unroll
        for (int i = 0; i < 4; i++) a[i] = Qs[r0 + i][k];
#pragma unroll
        for (int j = 0; j < 4; j++) b[j] = Ks[c0 + j][k];
#pragma unroll
        for (int i = 0; i < 4; i++)
#pragma unroll
            for (int j = 0; j < 4; j++) acc[i][j] = fmaf(a[i], b[j], acc[i][j]);
    }
    __syncthreads();
#pragma unroll
    for (int i = 0; i < 4; i++)
#pragma unroll
        for (int j = 0; j < 4; j++) Qs[r0 + i][c0 + j] = acc[i][j];
    __syncthreads();
    if (tid < 64) {
        float mx = -1e30f;
        for (int c = 0; c < 64; c++) mx = fmaxf(mx, Qs[tid][c]);
        float s = 0.f;
        for (int c = 0; c < 64; c++) { float e = expf(Qs[tid][c] - mx); Qs[tid][c] = e; s += e; }
        float inv = 1.f / s;
        for (int c = 0; c < 64; c++) {
            float v = Qs[tid][c] * inv;
            Qs[tid][c] = v;
            g_K2[bh * 4096 + tid * 64 + c] = v;
        }
    }
    __syncthreads();
    if (tid < 64) {
        float cs = 0.f;
        for (int r = 0; r < 64; r++) cs += Qs[r][tid];
        atomicMax((int*)&g_colmax, __float_as_int(cs));
    }
}

// =====================================================================
// kernel_3 scores: S3[bh][m][n] = Ql[bh][m]·K[bh][n]
// =====================================================================
__global__ __launch_bounds__(256) void k3_kernel() {
    __shared__ float Qs[64][68];
    __shared__ float Ks[64][68];
    int nt = blockIdx.x, bh = blockIdx.y, tid = threadIdx.x;
    for (int i = tid; i < 4096; i += 256) {
        Qs[i >> 6][i & 63] = g_Ql[bh * 4096 + i];
        Ks[i >> 6][i & 63] = g_K[(((size_t)bh * NTOK) + nt * 64) * HD + i];
    }
    __syncthreads();
    int ty = tid >> 4, tx = tid & 15, r0 = ty * 4, c0 = tx * 4;
    float acc[4][4] = {};
    for (int k = 0; k < 64; k++) {
        float a[4], b[4];
#pragma unroll
        for (int i = 0; i < 4; i++) a[i] = Qs[r0 + i][k];
#pragma unroll
        for (int j = 0; j < 4; j++) b[j] = Ks[c0 + j][k];
#pragma unroll
        for (int i = 0; i < 4; i++)
#pragma unroll
            for (int j = 0; j < 4; j++) acc[i][j] = fmaf(a[i], b[j], acc[i][j]);
    }
#pragma unroll
    for (int i = 0; i < 4; i++)
#pragma unroll
        for (int j = 0; j < 4; j++)
            g_S3[((size_t)bh * 64 + r0 + i) * NTOK + nt * 64 + c0 + j] = acc[i][j];
}

// =====================================================================
// row softmax over N=4096 for S3.
// =====================================================================
__global__ __launch_bounds__(256) void softmax3_kernel() {
    __shared__ float redA[8], redB[8];
    int row = blockIdx.x, tid = threadIdx.x;
    float* p = g_S3 + (size_t)row * NTOK;
    float v[16];
    float mx = -1e30f;
#pragma unroll
    for (int i = 0; i < 16; i++) { v[i] = p[tid + i * 256]; mx = fmaxf(mx, v[i]); }
#pragma unroll
    for (int o = 16; o; o >>= 1) mx = fmaxf(mx, __shfl_xor_sync(~0u, mx, o));
    if ((tid & 31) == 0) redA[tid >> 5] = mx;
    __syncthreads();
    mx = redA[0];
#pragma unroll
    for (int w = 1; w < 8; w++) mx = fmaxf(mx, redA[w]);
    float s = 0.f;
#pragma unroll
    for (int i = 0; i < 16; i++) { v[i] = expf(v[i] - mx); s += v[i]; }
#pragma unroll
    for (int o = 16; o; o >>= 1) s += __shfl_xor_sync(~0u, s, o);
    if ((tid & 31) == 0) redB[tid >> 5] = s;
    __syncthreads();
    s = 0.f;
#pragma unroll
    for (int w = 0; w < 8; w++) s += redB[w];
    float inv = 1.f / s;
#pragma unroll
    for (int i = 0; i < 16; i++) p[tid + i * 256] = v[i] * inv;
}

// =====================================================================
// T = K3 @ V, split-K over n (16 partials).
// =====================================================================
__global__ __launch_bounds__(256) void tpart_kernel() {
    __shared__ float Ss[64][68];
    __shared__ float Vs[64][68];
    int ks = blockIdx.x, bh = blockIdx.y, tid = threadIdx.x;
    int ty = tid >> 4, tx = tid & 15, r0 = ty * 4, c0 = tx * 4;
    float acc[4][4] = {};
    for (int c4 = 0; c4 < 4; c4++) {
        int n0 = ks * 256 + c4 * 64;
        for (int i = tid; i < 4096; i += 256) {
            int m = i >> 6, nl = i & 63;
            Ss[m][nl]  = g_S3[((size_t)bh * 64 + m) * NTOK + n0 + nl];
            Vs[m][nl]  = g_V[(((size_t)bh * NTOK) + n0 + m) * HD + nl];
        }
        __syncthreads();
        for (int k = 0; k < 64; k++) {
            float a[4], b[4];
#pragma unroll
            for (int i = 0; i < 4; i++) a[i] = Ss[r0 + i][k];
            *(float4*)b = *(const float4*)&Vs[k][c0];
#pragma unroll
            for (int i = 0; i < 4; i++)
#pragma unroll
                for (int j = 0; j < 4; j++) acc[i][j] = fmaf(a[i], b[j], acc[i][j]);
        }
        __syncthreads();
    }
#pragma unroll
    for (int i = 0; i < 4; i++)
#pragma unroll
        for (int j = 0; j < 4; j++)
            g_Tpart[(((size_t)ks * BHN + bh) * 64 + r0 + i) * 64 + c0 + j] = acc[i][j];
}

__global__ void treduce_kernel() {
    int idx = blockIdx.x * 256 + threadIdx.x;
    float s = 0.f;
#pragma unroll
    for (int ks = 0; ks < KSPLIT; ks++) s += g_Tpart[(size_t)ks * (BHN * MLAND * HD) + idx];
    g_T[idx] = s;
}

// =====================================================================
// Newton-Schulz inverse (6 iters) + W = Vinv @ T.
// =====================================================================
__device__ __forceinline__ void mm64(const float* __restrict__ X,
                                     const float* __restrict__ Y,
                                     float* __restrict__ Z, int tid) {
    int ty = tid >> 4, tx = tid & 15, r0 = ty * 4, c0 = tx * 4;
    float acc[4][4] = {};
    for (int k = 0; k < 64; k++) {
        float a[4], b[4];
#pragma unroll
        for (int i = 0; i < 4; i++) a[i] = X[(r0 + i) * 65 + k];
#pragma unroll
        for (int j = 0; j < 4; j++) b[j] = Y[k * 65 + c0 + j];
#pragma unroll
        for (int i = 0; i < 4; i++)
#pragma unroll
            for (int j = 0; j < 4; j++) acc[i][j] = fmaf(a[i], b[j], acc[i][j]);
    }
#pragma unroll
    for (int i = 0; i < 4; i++)
#pragma unroll
        for (int j = 0; j < 4; j++) Z[(r0 + i) * 65 + c0 + j] = acc[i][j];
}

__global__ __launch_bounds__(256) void inv_kernel() {
    extern __shared__ float sh[];
    float* Km = sh;
    float* Vm = sh + 64 * 65;
    float* Am = sh + 2 * 64 * 65;
    float* T1 = sh + 3 * 64 * 65;
    float* T2 = sh + 4 * 64 * 65;
    int bh = blockIdx.x, tid = threadIdx.x;
    float ginv = 1.f / g_colmax;
    for (int i = tid; i < 4096; i += 256) {
        int r = i >> 6, c = i & 63;
        Km[r * 65 + c] = g_K2[bh * 4096 + r * 64 + c];
        Vm[r * 65 + c] = g_K2[bh * 4096 + c * 64 + r] * ginv;
    }
    for (int it = 0; it < 6; it++) {
        __syncthreads();
        mm64(Km, Vm, Am, tid);
        __syncthreads();
        for (int i = tid; i < 4096; i += 256) {
            int r = i >> 6, c = i & 63;
            T1[r * 65 + c] = (r == c ? 7.0f : 0.0f) - Am[r * 65 + c];
        }
        __syncthreads();
        mm64(Am, T1, T2, tid);
        __syncthreads();
        for (int i = tid; i < 4096; i += 256) {
            int r = i >> 6, c = i & 63;
            T2[r * 65 + c] = (r == c ? 15.0f : 0.0f) - T2[r * 65 + c];
        }
        __syncthreads();
        mm64(Am, T2, T1, tid);
        __syncthreads();
        for (int i = tid; i < 4096; i += 256) {
            int r = i >> 6, c = i & 63;
            T1[r * 65 + c] = (r == c ? 13.0f : 0.0f) - T1[r * 65 + c];
        }
        __syncthreads();
        mm64(Vm, T1, T2, tid);
        __syncthreads();
        for (int i = tid; i < 4096; i += 256) {
            int r = i >> 6, c = i & 63;
            Vm[r * 65 + c] = 0.25f * T2[r * 65 + c];
        }
    }
    __syncthreads();
    for (int i = tid; i < 4096; i += 256) {
        int r = i >> 6, c = i & 63;
        Am[r * 65 + c] = g_T[bh * 4096 + i];
    }
    __syncthreads();
    mm64(Vm, Am, T1, tid);
    __syncthreads();
    for (int i = tid; i < 4096; i += 256) {
        int r = i >> 6, c = i & 63;
        g_W[bh * 4096 + i] = T1[r * 65 + c];
    }
}

// =====================================================================
// Final fused: softmax(Q @ Kl^T) @ W  -> g_Xhi/g_Xmid [b*4096+n][h*64+d] bf16
// =====================================================================
__global__ __launch_bounds__(256) void final_attn() {
    __shared__ float Qs[64][68];
    __shared__ float Bs[64][68];
    int nt = blockIdx.x, bh = blockIdx.y, tid = threadIdx.x;
    int b = bh >> 3, h = bh & 7;
    int ty = tid >> 4, tx = tid & 15, r0 = ty * 4, c0 = tx * 4;
    for (int i = tid; i < 4096; i += 256) {
        Qs[i >> 6][i & 63] = g_Q[(((size_t)bh * NTOK) + nt * 64) * HD + i];
        Bs[i >> 6][i & 63] = g_Kl[bh * 4096 + i];
    }
    __syncthreads();
    float s[4][4] = {};
    for (int k = 0; k < 64; k++) {
        float a[4], bb[4];
#pragma unroll
        for (int i = 0; i < 4; i++) a[i] = Qs[r0 + i][k];
#pragma unroll
        for (int j = 0; j < 4; j++) bb[j] = Bs[c0 + j][k];
#pragma unroll
        for (int i = 0; i < 4; i++)
#pragma unroll
            for (int j = 0; j < 4; j++) s[i][j] = fmaf(a[i], bb[j], s[i][j]);
    }
#pragma unroll
    for (int i = 0; i < 4; i++) {
        float mx = fmaxf(fmaxf(s[i][0], s[i][1]), fmaxf(s[i][2], s[i][3]));
#pragma unroll
        for (int o = 8; o; o >>= 1) mx = fmaxf(mx, __shfl_xor_sync(~0u, mx, o, 16));
        float ss = 0.f;
#pragma unroll
        for (int j = 0; j < 4; j++) { s[i][j] = expf(s[i][j] - mx); ss += s[i][j]; }
#pragma unroll
        for (int o = 8; o; o >>= 1) ss += __shfl_xor_sync(~0u, ss, o, 16);
        float inv = 1.f / ss;
#pragma unroll
        for (int j = 0; j < 4; j++) s[i][j] *= inv;
    }
    __syncthreads();
    for (int i = tid; i < 4096; i += 256)
        Bs[i >> 6][i & 63] = g_W[bh * 4096 + i];
    __syncthreads();
    float acc[4][4] = {};
#pragma unroll
    for (int mo = 0; mo < 16; mo++) {
#pragma unroll
        for (int mi = 0; mi < 4; mi++) {
            float w[4];
            *(float4*)w = *(const float4*)&Bs[mo * 4 + mi][c0];
#pragma unroll
            for (int i = 0; i < 4; i++) {
                float pv = __shfl_sync(~0u, s[i][mi], mo, 16);
#pragma unroll
                for (int j = 0; j < 4; j++) acc[i][j] = fmaf(pv, w[j], acc[i][j]);
            }
        }
    }
#pragma unroll
    for (int i = 0; i < 4; i++)
#pragma unroll
        for (int j = 0; j < 4; j++) {
            size_t idx = (((size_t)b * NTOK) + nt * 64 + r0 + i) * CDIM + h * 64 + c0 + j;
            float v = acc[i][j];
            __nv_bfloat16 hv = __float2bfloat16(v);
            g_Xhi[idx] = hv;
            g_Xmid[idx] = __float2bfloat16(v - __bfloat162float(hv));
        }
}

// =====================================================================
// host launcher
// =====================================================================
extern "C" void kernel_launch(void* const* d_in, const int* in_sizes, int n_in,
                              void* d_out, int out_size) {
    const float* x      = (const float*)d_in[0];
    const float* qkv_w  = (const float*)d_in[1];
    const float* proj_w = (const float*)d_in[2];
    const float* proj_b = (const float*)d_in[3];
    float* out = (float*)d_out;

    __nv_bfloat16 *xhi, *xmid, *whi, *wmid, *phi, *pmid, *Xhi, *Xmid;
    cudaGetSymbolAddress((void**)&xhi,  g_xhi);
    cudaGetSymbolAddress((void**)&xmid, g_xmid);
    cudaGetSymbolAddress((void**)&whi,  g_whi);
    cudaGetSymbolAddress((void**)&wmid, g_wmid);
    cudaGetSymbolAddress((void**)&phi,  g_phi);
    cudaGetSymbolAddress((void**)&pmid, g_pmid);
    cudaGetSymbolAddress((void**)&Xhi,  g_Xhi);
    cudaGetSymbolAddress((void**)&Xmid, g_Xmid);

    split_kernel<<<8192, 256>>>(x, xhi, xmid, 16384 * 512 / 4);
    split_kernel<<<768, 256>>>(qkv_w, whi, wmid, 1536 * 512 / 4);
    split_kernel<<<256, 256>>>(proj_w, phi, pmid, 512 * 512 / 4);

    cudaFuncSetAttribute(hmma_gemm<0>, cudaFuncAttributeMaxDynamicSharedMemorySize, GEMM_SMEM);
    cudaFuncSetAttribute(hmma_gemm<1>, cudaFuncAttributeMaxDynamicSharedMemorySize, GEMM_SMEM);

    hmma_gemm<0><<<dim3(12, 128), 256, GEMM_SMEM>>>(xhi, xmid, whi, wmid, nullptr, nullptr);

    pool_kernel<<<BHN * MLAND, 64>>>();
    reset_kernel<<<1, 1>>>();
    k2_kernel<<<BHN, 256>>>();
    k3_kernel<<<dim3(64, BHN), 256>>>();
    softmax3_kernel<<<BHN * MLAND, 256>>>();
    tpart_kernel<<<dim3(KSPLIT, BHN), 256>>>();
    treduce_kernel<<<(BHN * MLAND * HD) / 256, 256>>>();

    const int INV_SMEM = 5 * 64 * 65 * sizeof(float);
    cudaFuncSetAttribute(inv_kernel, cudaFuncAttributeMaxDynamicSharedMemorySize, INV_SMEM);
    inv_kernel<<<BHN, 256, INV_SMEM>>>();

    final_attn<<<dim3(64, BHN), 256>>>();

    hmma_gemm<1><<<dim3(4, 128), 256, GEMM_SMEM>>>(Xhi, Xmid, phi, pmid, proj_b, out);
}

// round 4
// speedup vs baseline: 1.9162x; 1.1429x over previous
#include <cuda_runtime.h>
#include <cuda_bf16.h>
#include <math.h>
#include <stdint.h>

// ---------------- problem constants ----------------
#define NBATCH 4
#define NHEAD  8
#define BHN    (NBATCH*NHEAD)      // 32
#define NTOK   4096
#define CDIM   512
#define HD     64
#define MLAND  64
#define KSPLIT 16
#define SCALE  0.35355339059327373f   // 64^-0.25

// ---------------- device scratch ----------------
__device__ float g_Q [BHN*NTOK*HD];
__device__ float g_K [BHN*NTOK*HD];
__device__ float g_V [BHN*NTOK*HD];
__device__ float g_Ql[BHN*MLAND*HD];
__device__ float g_Kl[BHN*MLAND*HD];
__device__ float g_K2[BHN*MLAND*MLAND];
__device__ float g_W [BHN*MLAND*HD];
__device__ float g_S3[BHN*MLAND*NTOK];
__device__ float g_Tpart[KSPLIT*BHN*MLAND*HD];
__device__ float g_T [BHN*MLAND*HD];
__device__ float g_colmax;

// bf16 hi/mid split buffers
__device__ __nv_bfloat16 g_xhi [16384*512];
__device__ __nv_bfloat16 g_xmid[16384*512];
__device__ __nv_bfloat16 g_whi [1536*512];
__device__ __nv_bfloat16 g_wmid[1536*512];
__device__ __nv_bfloat16 g_phi [512*512];
__device__ __nv_bfloat16 g_pmid[512*512];
__device__ __nv_bfloat16 g_Xhi [16384*512];
__device__ __nv_bfloat16 g_Xmid[16384*512];
// middle-stage bf16 operands
__device__ __nv_bfloat16 g_Khi [BHN*NTOK*HD];   // scaled K split, [bh][n][d]
__device__ __nv_bfloat16 g_Kmid[BHN*NTOK*HD];
__device__ __nv_bfloat16 g_Qlh [BHN*MLAND*HD];
__device__ __nv_bfloat16 g_Qlm [BHN*MLAND*HD];
__device__ __nv_bfloat16 g_Vth [BHN*HD*NTOK];   // V^T split, [bh][d][n]
__device__ __nv_bfloat16 g_Vtm [BHN*HD*NTOK];
__device__ __nv_bfloat16 g_S3h [BHN*MLAND*NTOK];
__device__ __nv_bfloat16 g_S3m [BHN*MLAND*NTOK];

// ==================== PTX helpers ====================
__device__ __forceinline__ uint32_t smem_u32(const void* p) {
    uint32_t a;
    asm("{ .reg .u64 t; cvta.to.shared.u64 t, %1; cvt.u32.u64 %0, t; }" : "=r"(a) : "l"(p));
    return a;
}
__device__ __forceinline__ void ldsm_x4(uint32_t& r0, uint32_t& r1, uint32_t& r2, uint32_t& r3,
                                        uint32_t addr) {
    asm volatile("ldmatrix.sync.aligned.m8n8.x4.shared.b16 {%0,%1,%2,%3}, [%4];"
                 : "=r"(r0), "=r"(r1), "=r"(r2), "=r"(r3) : "r"(addr));
}
__device__ __forceinline__ void mma16816(float* c, const uint32_t* a, const uint32_t* b) {
    asm volatile("mma.sync.aligned.m16n8k16.row.col.f32.bf16.bf16.f32 "
                 "{%0,%1,%2,%3}, {%4,%5,%6,%7}, {%8,%9}, {%0,%1,%2,%3};"
                 : "+f"(c[0]), "+f"(c[1]), "+f"(c[2]), "+f"(c[3])
                 : "r"(a[0]), "r"(a[1]), "r"(a[2]), "r"(a[3]), "r"(b[0]), "r"(b[1]));
}
#define CP_ASYNC(dst, src) asm volatile("cp.async.cg.shared.global [%0], [%1], 16;" :: "r"(dst), "l"(src))
#define CP_COMMIT()        asm volatile("cp.async.commit_group;" ::: "memory")
#define CP_WAIT1()         asm volatile("cp.async.wait_group 1;" ::: "memory")
#define CP_WAIT0()         asm volatile("cp.async.wait_group 0;" ::: "memory")

// ==================== bf16 3x-split HMMA GEMM (big GEMMs) ====================
#define PITCH 40
#define MAT_BYTES (128*PITCH*2)     // 10240
#define SM_A_HI  0
#define SM_A_MID (1*MAT_BYTES)
#define SM_B_HI  (2*MAT_BYTES)
#define SM_B_MID (3*MAT_BYTES)
#define BUF_BYTES (4*MAT_BYTES)     // 40960
#define GEMM_SMEM (2*BUF_BYTES)     // 81920

__device__ __forceinline__ void load_stage(uint32_t bufb, int k0, size_t rowA0, size_t rowB0,
                                           const __nv_bfloat16* __restrict__ Ahi,
                                           const __nv_bfloat16* __restrict__ Amid,
                                           const __nv_bfloat16* __restrict__ Bhi,
                                           const __nv_bfloat16* __restrict__ Bmid,
                                           int tid) {
#pragma unroll
    for (int half = 0; half < 2; half++) {
        int c = tid + half * 256;
        int r = c >> 2, cc = (c & 3) * 8;
        uint32_t d = bufb + (uint32_t)(r * PITCH + cc) * 2;
        size_t goffA = (rowA0 + r) * 512 + k0 + cc;
        size_t goffB = (rowB0 + r) * 512 + k0 + cc;
        CP_ASYNC(d + SM_A_HI,  Ahi  + goffA);
        CP_ASYNC(d + SM_A_MID, Amid + goffA);
        CP_ASYNC(d + SM_B_HI,  Bhi  + goffB);
        CP_ASYNC(d + SM_B_MID, Bmid + goffB);
    }
    CP_COMMIT();
}

template<int MODE>
__global__ __launch_bounds__(256, 2) void hmma_gemm(
    const __nv_bfloat16* __restrict__ Ahi, const __nv_bfloat16* __restrict__ Amid,
    const __nv_bfloat16* __restrict__ Bhi, const __nv_bfloat16* __restrict__ Bmid,
    const float* __restrict__ bias, float* __restrict__ Cout)
{
    extern __shared__ __align__(128) char sm[];
    uint32_t sb = smem_u32(sm);
    int tid = threadIdx.x;
    int lane = tid & 31, wid = tid >> 5;
    int wm = wid >> 2, wn = wid & 3;
    size_t rowA0 = (size_t)blockIdx.y * 128;
    size_t rowB0 = (size_t)blockIdx.x * 128;

    float acc[4][4][4] = {};

    int arow  = wm * 64 + (lane & 15);
    int akoff = (lane >> 4) * 8;
    int brow  = wn * 32 + (lane & 7) + ((lane >> 4) << 3);
    int bkoff = ((lane >> 3) & 1) * 8;

    load_stage(sb, 0, rowA0, rowB0, Ahi, Amid, Bhi, Bmid, tid);

    for (int t = 0; t < 16; t++) {
        if (t + 1 < 16) {
            load_stage(sb + ((t + 1) & 1) * BUF_BYTES, (t + 1) * 32, rowA0, rowB0,
                       Ahi, Amid, Bhi, Bmid, tid);
            CP_WAIT1();
        } else {
            CP_WAIT0();
        }
        __syncthreads();

        uint32_t base = sb + (t & 1) * BUF_BYTES;
#pragma unroll
        for (int kk = 0; kk < 32; kk += 16) {
            uint32_t bhi[4][2], bmid[4][2];
#pragma unroll
            for (int np = 0; np < 2; np++) {
                uint32_t off = (uint32_t)((brow + np * 16) * PITCH + kk + bkoff) * 2;
                uint32_t r0, r1, r2, r3;
                ldsm_x4(r0, r1, r2, r3, base + SM_B_HI + off);
                bhi[np * 2][0] = r0; bhi[np * 2][1] = r1;
                bhi[np * 2 + 1][0] = r2; bhi[np * 2 + 1][1] = r3;
                ldsm_x4(r0, r1, r2, r3, base + SM_B_MID + off);
                bmid[np * 2][0] = r0; bmid[np * 2][1] = r1;
                bmid[np * 2 + 1][0] = r2; bmid[np * 2 + 1][1] = r3;
            }
#pragma unroll
            for (int mi = 0; mi < 4; mi++) {
                uint32_t ahi[4], amid[4];
                uint32_t off = (uint32_t)((arow + mi * 16) * PITCH + kk + akoff) * 2;
                ldsm_x4(ahi[0], ahi[1], ahi[2], ahi[3], base + SM_A_HI + off);
                ldsm_x4(amid[0], amid[1], amid[2], amid[3], base + SM_A_MID + off);
#pragma unroll
                for (int ni = 0; ni < 4; ni++) {
                    mma16816(acc[mi][ni], ahi, bhi[ni]);
                    mma16816(acc[mi][ni], ahi, bmid[ni]);
                    mma16816(acc[mi][ni], amid, bhi[ni]);
                }
            }
        }
        __syncthreads();
    }

    int colW = blockIdx.x * 128 + wn * 32 + 2 * (lane & 3);
    int rowW = blockIdx.y * 128 + wm * 64 + (lane >> 2);
#pragma unroll
    for (int ni = 0; ni < 4; ni++) {
        int col = colW + ni * 8;
#pragma unroll
        for (int mi = 0; mi < 4; mi++) {
            int row0 = rowW + mi * 16;
            if (MODE == 0) {
                int which = col >> 9;
                int h = (col >> 6) & 7;
                int d = col & 63;
                float m = (which == 2) ? 1.0f : SCALE;
                float* basep = (which == 0) ? g_Q : ((which == 1) ? g_K : g_V);
#pragma unroll
                for (int rr = 0; rr < 2; rr++) {
                    int row = row0 + rr * 8;
                    int b = row >> 12, n = row & 4095;
                    float2 v;
                    v.x = acc[mi][ni][rr * 2 + 0] * m;
                    v.y = acc[mi][ni][rr * 2 + 1] * m;
                    size_t idx = ((size_t)(b * 8 + h) * NTOK + n) * HD + d;
                    *(float2*)(basep + idx) = v;
                    if (which == 1) {   // also store bf16 hi/mid of scaled K
                        __nv_bfloat16 h0 = __float2bfloat16(v.x);
                        __nv_bfloat16 h1 = __float2bfloat16(v.y);
                        *(__nv_bfloat162*)(g_Khi + idx) = __nv_bfloat162(h0, h1);
                        *(__nv_bfloat162*)(g_Kmid + idx) = __nv_bfloat162(
                            __float2bfloat16(v.x - __bfloat162float(h0)),
                            __float2bfloat16(v.y - __bfloat162float(h1)));
                    }
                }
            } else {
                float2 bb = *(const float2*)(bias + col);
#pragma unroll
                for (int rr = 0; rr < 2; rr++) {
                    int row = row0 + rr * 8;
                    float2 v;
                    v.x = acc[mi][ni][rr * 2 + 0] + bb.x;
                    v.y = acc[mi][ni][rr * 2 + 1] + bb.y;
                    *(float2*)(Cout + (size_t)row * 512 + col) = v;
                }
            }
        }
    }
}

// ==================== fp32 -> bf16 hi/mid split ====================
__global__ void split_kernel(const float* __restrict__ src,
                             __nv_bfloat16* __restrict__ hi,
                             __nv_bfloat16* __restrict__ mid, int n4) {
    int i = blockIdx.x * 256 + threadIdx.x;
    if (i >= n4) return;
    float4 v = ((const float4*)src)[i];
    __nv_bfloat16 h0 = __float2bfloat16(v.x);
    __nv_bfloat16 h1 = __float2bfloat16(v.y);
    __nv_bfloat16 h2 = __float2bfloat16(v.z);
    __nv_bfloat16 h3 = __float2bfloat16(v.w);
    __nv_bfloat162* hp = (__nv_bfloat162*)hi;
    __nv_bfloat162* mp = (__nv_bfloat162*)mid;
    hp[i * 2 + 0] = __nv_bfloat162(h0, h1);
    hp[i * 2 + 1] = __nv_bfloat162(h2, h3);
    mp[i * 2 + 0] = __nv_bfloat162(__float2bfloat16(v.x - __bfloat162float(h0)),
                                   __float2bfloat16(v.y - __bfloat162float(h1)));
    mp[i * 2 + 1] = __nv_bfloat162(__float2bfloat16(v.z - __bfloat162float(h2)),
                                   __float2bfloat16(v.w - __bfloat162float(h3)));
}

// =====================================================================
// Landmark pooling + Ql bf16 split
// =====================================================================
__global__ void pool_kernel() {
    int bm = blockIdx.x;
    int bh = bm >> 6, m = bm & 63;
    int d = threadIdx.x;
    const float* qp = g_Q + (((size_t)bh * NTOK) + m * 64) * HD + d;
    const float* kp = g_K + (((size_t)bh * NTOK) + m * 64) * HD + d;
    float sq = 0.f, sk = 0.f;
#pragma unroll 8
    for (int t = 0; t < 64; t++) { sq += qp[(size_t)t * HD]; sk += kp[(size_t)t * HD]; }
    float ql = sq * (1.f / 64.f);
    int idx = (bh * 64 + m) * 64 + d;
    g_Ql[idx] = ql;
    g_Kl[idx] = sk * (1.f / 64.f);
    __nv_bfloat16 h = __float2bfloat16(ql);
    g_Qlh[idx] = h;
    g_Qlm[idx] = __float2bfloat16(ql - __bfloat162float(h));
}

__global__ void reset_kernel() { g_colmax = 0.0f; }

// =====================================================================
// kernel_2 = softmax(Ql @ Kl^T) + colsum max
// =====================================================================
__global__ __launch_bounds__(256) void k2_kernel() {
    __shared__ float Qs[64][68];
    __shared__ float Ks[64][68];
    int bh = blockIdx.x, tid = threadIdx.x;
    for (int i = tid; i < 4096; i += 256) {
        Qs[i >> 6][i & 63] = g_Ql[bh * 4096 + i];
        Ks[i >> 6][i & 63] = g_Kl[bh * 4096 + i];
    }
    __syncthreads();
    int ty = tid >> 4, tx = tid & 15, r0 = ty * 4, c0 = tx * 4;
    float acc[4][4] = {};
    for (int k = 0; k < 64; k++) {
        float a[4], b[4];
#pragma unroll
        for (int i = 0; i < 4; i++) a[i] = Qs[r0 + i][k];
#pragma unroll
        for (int j = 0; j < 4; j++) b[j] = Ks[c0 + j][k];
#pragma unroll
        for (int i = 0; i < 4; i++)
#pragma unroll
            for (int j = 0; j < 4; j++) acc[i][j] = fmaf(a[i], b[j], acc[i][j]);
    }
    __syncthreads();
#pragma unroll
    for (int i = 0; i < 4; i++)
#pragma unroll
        for (int j = 0; j < 4; j++) Qs[r0 + i][c0 + j] = acc[i][j];
    __syncthreads();
    if (tid < 64) {
        float mx = -1e30f;
        for (int c = 0; c < 64; c++) mx = fmaxf(mx, Qs[tid][c]);
        float s = 0.f;
        for (int c = 0; c < 64; c++) { float e = expf(Qs[tid][c] - mx); Qs[tid][c] = e; s += e; }
        float inv = 1.f / s;
        for (int c = 0; c < 64; c++) {
            float v = Qs[tid][c] * inv;
            Qs[tid][c] = v;
            g_K2[bh * 4096 + tid * 64 + c] = v;
        }
    }
    __syncthreads();
    if (tid < 64) {
        float cs = 0.f;
        for (int r = 0; r < 64; r++) cs += Qs[r][tid];
        atomicMax((int*)&g_colmax, __float_as_int(cs));
    }
}

// =====================================================================
// k3 scores via tensor cores: S3[bh][m][n] = Ql·K, 3-term bf16 split.
// grid (16 n-tiles of 256, 32 bh), 256 threads (8 warps, each n32).
// =====================================================================
#define K3_PITCH 72
#define K3_QLH 0
#define K3_QLM (64*K3_PITCH*2)
#define K3_KH  (2*64*K3_PITCH*2)
#define K3_KM  (K3_KH + 256*K3_PITCH*2)
#define K3_SMEM (K3_KM + 256*K3_PITCH*2)   // 92160

__global__ __launch_bounds__(256) void k3_mma() {
    extern __shared__ __align__(128) char sm[];
    uint32_t sb = smem_u32(sm);
    int nt = blockIdx.x, bh = blockIdx.y, tid = threadIdx.x;
    int lane = tid & 31, wid = tid >> 5;

    // load Ql hi/mid (64x64) and K hi/mid (256x64)
    const uint4* qh = (const uint4*)(g_Qlh + bh * 4096);
    const uint4* qm = (const uint4*)(g_Qlm + bh * 4096);
#pragma unroll
    for (int it = 0; it < 2; it++) {
        int c = tid + it * 256;           // chunk of 8 elems
        int row = c >> 3, col = (c & 7) * 8;
        uint32_t off = (uint32_t)(row * K3_PITCH + col) * 2;
        *(uint4*)(sm + K3_QLH + off) = qh[c];
        *(uint4*)(sm + K3_QLM + off) = qm[c];
    }
    const uint4* kh = (const uint4*)(g_Khi + ((size_t)bh * NTOK + nt * 256) * 64);
    const uint4* km = (const uint4*)(g_Kmid + ((size_t)bh * NTOK + nt * 256) * 64);
#pragma unroll
    for (int it = 0; it < 8; it++) {
        int c = tid + it * 256;
        int row = c >> 3, col = (c & 7) * 8;
        uint32_t off = (uint32_t)(row * K3_PITCH + col) * 2;
        *(uint4*)(sm + K3_KH + off) = kh[c];
        *(uint4*)(sm + K3_KM + off) = km[c];
    }
    __syncthreads();

    int arow = lane & 15;
    int akoff = (lane >> 4) * 8;
    int brow = wid * 32 + (lane & 7) + ((lane >> 4) << 3);
    int bkoff = ((lane >> 3) & 1) * 8;

    float acc[4][4][4] = {};
#pragma unroll
    for (int kk = 0; kk < 64; kk += 16) {
        uint32_t bhi[4][2], bmid[4][2];
#pragma unroll
        for (int np = 0; np < 2; np++) {
            uint32_t off = (uint32_t)((brow + np * 16) * K3_PITCH + kk + bkoff) * 2;
            uint32_t r0, r1, r2, r3;
            ldsm_x4(r0, r1, r2, r3, sb + K3_KH + off);
            bhi[np * 2][0] = r0; bhi[np * 2][1] = r1;
            bhi[np * 2 + 1][0] = r2; bhi[np * 2 + 1][1] = r3;
            ldsm_x4(r0, r1, r2, r3, sb + K3_KM + off);
            bmid[np * 2][0] = r0; bmid[np * 2][1] = r1;
            bmid[np * 2 + 1][0] = r2; bmid[np * 2 + 1][1] = r3;
        }
#pragma unroll
        for (int mi = 0; mi < 4; mi++) {
            uint32_t ahi[4], amid[4];
            uint32_t off = (uint32_t)((arow + mi * 16) * K3_PITCH + kk + akoff) * 2;
            ldsm_x4(ahi[0], ahi[1], ahi[2], ahi[3], sb + K3_QLH + off);
            ldsm_x4(amid[0], amid[1], amid[2], amid[3], sb + K3_QLM + off);
#pragma unroll
            for (int ni = 0; ni < 4; ni++) {
                mma16816(acc[mi][ni], ahi, bhi[ni]);
                mma16816(acc[mi][ni], ahi, bmid[ni]);
                mma16816(acc[mi][ni], amid, bhi[ni]);
            }
        }
    }
    // store S3 fp32
#pragma unroll
    for (int mi = 0; mi < 4; mi++)
#pragma unroll
        for (int ni = 0; ni < 4; ni++)
#pragma unroll
            for (int rr = 0; rr < 2; rr++) {
                int row = mi * 16 + (lane >> 2) + rr * 8;
                int col = wid * 32 + ni * 8 + 2 * (lane & 3);
                float2 v;
                v.x = acc[mi][ni][rr * 2 + 0];
                v.y = acc[mi][ni][rr * 2 + 1];
                *(float2*)(g_S3 + ((size_t)bh * 64 + row) * NTOK + nt * 256 + col) = v;
            }
}

// =====================================================================
// row softmax over N=4096; emits bf16 hi/mid P
// =====================================================================
__global__ __launch_bounds__(256) void softmax3_kernel() {
    __shared__ float redA[8], redB[8];
    int row = blockIdx.x, tid = threadIdx.x;
    const float* p = g_S3 + (size_t)row * NTOK;
    float v[16];
    float mx = -1e30f;
#pragma unroll
    for (int i = 0; i < 16; i++) { v[i] = p[tid + i * 256]; mx = fmaxf(mx, v[i]); }
#pragma unroll
    for (int o = 16; o; o >>= 1) mx = fmaxf(mx, __shfl_xor_sync(~0u, mx, o));
    if ((tid & 31) == 0) redA[tid >> 5] = mx;
    __syncthreads();
    mx = redA[0];
#pragma unroll
    for (int w = 1; w < 8; w++) mx = fmaxf(mx, redA[w]);
    float s = 0.f;
#pragma unroll
    for (int i = 0; i < 16; i++) { v[i] = expf(v[i] - mx); s += v[i]; }
#pragma unroll
    for (int o = 16; o; o >>= 1) s += __shfl_xor_sync(~0u, s, o);
    if ((tid & 31) == 0) redB[tid >> 5] = s;
    __syncthreads();
    s = 0.f;
#pragma unroll
    for (int w = 0; w < 8; w++) s += redB[w];
    float inv = 1.f / s;
#pragma unroll
    for (int i = 0; i < 16; i++) {
        float pv = v[i] * inv;
        __nv_bfloat16 h = __float2bfloat16(pv);
        size_t idx = (size_t)row * NTOK + tid + i * 256;
        g_S3h[idx] = h;
        g_S3m[idx] = __float2bfloat16(pv - __bfloat162float(h));
    }
}

// =====================================================================
// V transpose: g_V [bh][n][d] fp32 -> g_Vth/g_Vtm [bh][d][n] bf16
// grid (64 n-tiles, 32 bh), 256 threads
// =====================================================================
__global__ __launch_bounds__(256) void vtrans_kernel() {
    __shared__ float sv[64][65];
    int nt = blockIdx.x, bh = blockIdx.y, tid = threadIdx.x;
    const float4* src = (const float4*)(g_V + (((size_t)bh * NTOK) + nt * 64) * 64);
#pragma unroll
    for (int it = 0; it < 4; it++) {
        int c = tid + it * 256;           // float4 chunk
        int row = c >> 4, col = (c & 15) * 4;
        float4 v = src[c];
        sv[row][col] = v.x; sv[row][col + 1] = v.y;
        sv[row][col + 2] = v.z; sv[row][col + 3] = v.w;
    }
    __syncthreads();
    int d = tid >> 2, n0 = (tid & 3) * 16;
    __nv_bfloat162* dh = (__nv_bfloat162*)(g_Vth + ((size_t)bh * 64 + d) * NTOK + nt * 64 + n0);
    __nv_bfloat162* dm = (__nv_bfloat162*)(g_Vtm + ((size_t)bh * 64 + d) * NTOK + nt * 64 + n0);
#pragma unroll
    for (int j = 0; j < 8; j++) {
        float a = sv[n0 + j * 2][d], b = sv[n0 + j * 2 + 1][d];
        __nv_bfloat16 ha = __float2bfloat16(a), hb = __float2bfloat16(b);
        dh[j] = __nv_bfloat162(ha, hb);
        dm[j] = __nv_bfloat162(__float2bfloat16(a - __bfloat162float(ha)),
                               __float2bfloat16(b - __bfloat162float(hb)));
    }
}

// =====================================================================
// T_part = P @ V via tensor cores.  grid (16 ks, 32 bh), 256 threads.
// A = P [64 m x 256 k] hi/mid, B = V^T [64 d x 256 k] hi/mid.
// 8 warps: 2M x 4N, warp tile 32x16. K processed in 2 halves of 128.
// =====================================================================
#define TP_PITCH 136
#define TP_SH 0
#define TP_SM (64*TP_PITCH*2)
#define TP_VH (2*64*TP_PITCH*2)
#define TP_VM (3*64*TP_PITCH*2)
#define TP_SMEM (4*64*TP_PITCH*2)   // 69632

__global__ __launch_bounds__(256) void tpart_mma() {
    extern __shared__ __align__(128) char sm[];
    uint32_t sb = smem_u32(sm);
    int ks = blockIdx.x, bh = blockIdx.y, tid = threadIdx.x;
    int lane = tid & 31, wid = tid >> 5;
    int wm = wid >> 2, wn = wid & 3;

    int arow = wm * 32 + (lane & 15);
    int akoff = (lane >> 4) * 8;
    int brow = wn * 16 + (lane & 7) + ((lane >> 4) << 3);
    int bkoff = ((lane >> 3) & 1) * 8;

    float acc[2][2][4] = {};

    for (int kh = 0; kh < 2; kh++) {
        size_t gk = (size_t)ks * 256 + kh * 128;
        const uint4* shp = (const uint4*)(g_S3h + ((size_t)bh * 64) * NTOK + gk);
        const uint4* smp = (const uint4*)(g_S3m + ((size_t)bh * 64) * NTOK + gk);
        const uint4* vhp = (const uint4*)(g_Vth + ((size_t)bh * 64) * NTOK + gk);
        const uint4* vmp = (const uint4*)(g_Vtm + ((size_t)bh * 64) * NTOK + gk);
        __syncthreads();
#pragma unroll
        for (int it = 0; it < 4; it++) {
            int c = tid + it * 256;        // 8-elem chunk: 64 rows x 16 chunks
            int row = c >> 4, col = (c & 15) * 8;
            uint32_t off = (uint32_t)(row * TP_PITCH + col) * 2;
            size_t gidx = (size_t)row * (NTOK / 8) + col / 8;   // uint4 index within row stride NTOK
            *(uint4*)(sm + TP_SH + off) = shp[gidx];
            *(uint4*)(sm + TP_SM + off) = smp[gidx];
            *(uint4*)(sm + TP_VH + off) = vhp[gidx];
            *(uint4*)(sm + TP_VM + off) = vmp[gidx];
        }
        __syncthreads();
#pragma unroll
        for (int kk = 0; kk < 128; kk += 16) {
            uint32_t bhi[2][2], bmid[2][2];
            {
                uint32_t off = (uint32_t)(brow * TP_PITCH + kk + bkoff) * 2;
                uint32_t r0, r1, r2, r3;
                ldsm_x4(r0, r1, r2, r3, sb + TP_VH + off);
                bhi[0][0] = r0; bhi[0][1] = r1; bhi[1][0] = r2; bhi[1][1] = r3;
                ldsm_x4(r0, r1, r2, r3, sb + TP_VM + off);
                bmid[0][0] = r0; bmid[0][1] = r1; bmid[1][0] = r2; bmid[1][1] = r3;
            }
#pragma unroll
            for (int mi = 0; mi < 2; mi++) {
                uint32_t ahi[4], amid[4];
                uint32_t off = (uint32_t)((arow + mi * 16) * TP_PITCH + kk + akoff) * 2;
                ldsm_x4(ahi[0], ahi[1], ahi[2], ahi[3], sb + TP_SH + off);
                ldsm_x4(amid[0], amid[1], amid[2], amid[3], sb + TP_SM + off);
#pragma unroll
                for (int ni = 0; ni < 2; ni++) {
                    mma16816(acc[mi][ni], ahi, bhi[ni]);
                    mma16816(acc[mi][ni], ahi, bmid[ni]);
                    mma16816(acc[mi][ni], amid, bhi[ni]);
                }
            }
        }
    }
#pragma unroll
    for (int mi = 0; mi < 2; mi++)
#pragma unroll
        for (int ni = 0; ni < 2; ni++)
#pragma unroll
            for (int rr = 0; rr < 2; rr++) {
                int row = wm * 32 + mi * 16 + (lane >> 2) + rr * 8;
                int col = wn * 16 + ni * 8 + 2 * (lane & 3);
                float2 v;
                v.x = acc[mi][ni][rr * 2 + 0];
                v.y = acc[mi][ni][rr * 2 + 1];
                *(float2*)(g_Tpart + (((size_t)ks * BHN + bh) * 64 + row) * 64 + col) = v;
            }
}

__global__ void treduce_kernel() {
    int idx = blockIdx.x * 256 + threadIdx.x;
    float s = 0.f;
#pragma unroll
    for (int ks = 0; ks < KSPLIT; ks++) s += g_Tpart[(size_t)ks * (BHN * MLAND * HD) + idx];
    g_T[idx] = s;
}

// =====================================================================
// Newton-Schulz inverse (6 iters) + W = Vinv @ T.
// =====================================================================
__device__ __forceinline__ void mm64(const float* __restrict__ X,
                                     const float* __restrict__ Y,
                                     float* __restrict__ Z, int tid) {
    int ty = tid >> 4, tx = tid & 15, r0 = ty * 4, c0 = tx * 4;
    float acc[4][4] = {};
    for (int k = 0; k < 64; k++) {
        float a[4], b[4];
#pragma unroll
        for (int i = 0; i < 4; i++) a[i] = X[(r0 + i) * 65 + k];
#pragma unroll
        for (int j = 0; j < 4; j++) b[j] = Y[k * 65 + c0 + j];
#pragma unroll
        for (int i = 0; i < 4; i++)
#pragma unroll
            for (int j = 0; j < 4; j++) acc[i][j] = fmaf(a[i], b[j], acc[i][j]);
    }
#pragma unroll
    for (int i = 0; i < 4; i++)
#pragma unroll
        for (int j = 0; j < 4; j++) Z[(r0 + i) * 65 + c0 + j] = acc[i][j];
}

__global__ __launch_bounds__(256) void inv_kernel() {
    extern __shared__ float sh[];
    float* Km = sh;
    float* Vm = sh + 64 * 65;
    float* Am = sh + 2 * 64 * 65;
    float* T1 = sh + 3 * 64 * 65;
    float* T2 = sh + 4 * 64 * 65;
    int bh = blockIdx.x, tid = threadIdx.x;
    float ginv = 1.f / g_colmax;
    for (int i = tid; i < 4096; i += 256) {
        int r = i >> 6, c = i & 63;
        Km[r * 65 + c] = g_K2[bh * 4096 + r * 64 + c];
        Vm[r * 65 + c] = g_K2[bh * 4096 + c * 64 + r] * ginv;
    }
    for (int it = 0; it < 6; it++) {
        __syncthreads();
        mm64(Km, Vm, Am, tid);
        __syncthreads();
        for (int i = tid; i < 4096; i += 256) {
            int r = i >> 6, c = i & 63;
            T1[r * 65 + c] = (r == c ? 7.0f : 0.0f) - Am[r * 65 + c];
        }
        __syncthreads();
        mm64(Am, T1, T2, tid);
        __syncthreads();
        for (int i = tid; i < 4096; i += 256) {
            int r = i >> 6, c = i & 63;
            T2[r * 65 + c] = (r == c ? 15.0f : 0.0f) - T2[r * 65 + c];
        }
        __syncthreads();
        mm64(Am, T2, T1, tid);
        __syncthreads();
        for (int i = tid; i < 4096; i += 256) {
            int r = i >> 6, c = i & 63;
            T1[r * 65 + c] = (r == c ? 13.0f : 0.0f) - T1[r * 65 + c];
        }
        __syncthreads();
        mm64(Vm, T1, T2, tid);
        __syncthreads();
        for (int i = tid; i < 4096; i += 256) {
            int r = i >> 6, c = i & 63;
            Vm[r * 65 + c] = 0.25f * T2[r * 65 + c];
        }
    }
    __syncthreads();
    for (int i = tid; i < 4096; i += 256) {
        int r = i >> 6, c = i & 63;
        Am[r * 65 + c] = g_T[bh * 4096 + i];
    }
    __syncthreads();
    mm64(Vm, Am, T1, tid);
    __syncthreads();
    for (int i = tid; i < 4096; i += 256) {
        int r = i >> 6, c = i & 63;
        g_W[bh * 4096 + i] = T1[r * 65 + c];
    }
}

// =====================================================================
// Final fused: softmax(Q @ Kl^T) @ W -> g_Xhi/g_Xmid bf16
// =====================================================================
__global__ __launch_bounds__(256) void final_attn() {
    __shared__ float Qs[64][68];
    __shared__ float Bs[64][68];
    int nt = blockIdx.x, bh = blockIdx.y, tid = threadIdx.x;
    int b = bh >> 3, h = bh & 7;
    int ty = tid >> 4, tx = tid & 15, r0 = ty * 4, c0 = tx * 4;
    for (int i = tid; i < 4096; i += 256) {
        Qs[i >> 6][i & 63] = g_Q[(((size_t)bh * NTOK) + nt * 64) * HD + i];
        Bs[i >> 6][i & 63] = g_Kl[bh * 4096 + i];
    }
    __syncthreads();
    float s[4][4] = {};
    for (int k = 0; k < 64; k++) {
        float a[4], bb[4];
#pragma unroll
        for (int i = 0; i < 4; i++) a[i] = Qs[r0 + i][k];
#pragma unroll
        for (int j = 0; j < 4; j++) bb[j] = Bs[c0 + j][k];
#pragma unroll
        for (int i = 0; i < 4; i++)
#pragma unroll
            for (int j = 0; j < 4; j++) s[i][j] = fmaf(a[i], bb[j], s[i][j]);
    }
#pragma unroll
    for (int i = 0; i < 4; i++) {
        float mx = fmaxf(fmaxf(s[i][0], s[i][1]), fmaxf(s[i][2], s[i][3]));
#pragma unroll
        for (int o = 8; o; o >>= 1) mx = fmaxf(mx, __shfl_xor_sync(~0u, mx, o, 16));
        float ss = 0.f;
#pragma unroll
        for (int j = 0; j < 4; j++) { s[i][j] = expf(s[i][j] - mx); ss += s[i][j]; }
#pragma unroll
        for (int o = 8; o; o >>= 1) ss += __shfl_xor_sync(~0u, ss, o, 16);
        float inv = 1.f / ss;
#pragma unroll
        for (int j = 0; j < 4; j++) s[i][j] *= inv;
    }
    __syncthreads();
    for (int i = tid; i < 4096; i += 256)
        Bs[i >> 6][i & 63] = g_W[bh * 4096 + i];
    __syncthreads();
    float acc[4][4] = {};
#pragma unroll
    for (int mo = 0; mo < 16; mo++) {
#pragma unroll
        for (int mi = 0; mi < 4; mi++) {
            float w[4];
            *(float4*)w = *(const float4*)&Bs[mo * 4 + mi][c0];
#pragma unroll
            for (int i = 0; i < 4; i++) {
                float pv = __shfl_sync(~0u, s[i][mi], mo, 16);
#pragma unroll
                for (int j = 0; j < 4; j++) acc[i][j] = fmaf(pv, w[j], acc[i][j]);
            }
        }
    }
#pragma unroll
    for (int i = 0; i < 4; i++)
#pragma unroll
        for (int j = 0; j < 4; j++) {
            size_t idx = (((size_t)b * NTOK) + nt * 64 + r0 + i) * CDIM + h * 64 + c0 + j;
            float v = acc[i][j];
            __nv_bfloat16 hv = __float2bfloat16(v);
            g_Xhi[idx] = hv;
            g_Xmid[idx] = __float2bfloat16(v - __bfloat162float(hv));
        }
}

// =====================================================================
// host launcher
// =====================================================================
extern "C" void kernel_launch(void* const* d_in, const int* in_sizes, int n_in,
                              void* d_out, int out_size) {
    const float* x      = (const float*)d_in[0];
    const float* qkv_w  = (const float*)d_in[1];
    const float* proj_w = (const float*)d_in[2];
    const float* proj_b = (const float*)d_in[3];
    float* out = (float*)d_out;

    __nv_bfloat16 *xhi, *xmid, *whi, *wmid, *phi, *pmid, *Xhi, *Xmid;
    cudaGetSymbolAddress((void**)&xhi,  g_xhi);
    cudaGetSymbolAddress((void**)&xmid, g_xmid);
    cudaGetSymbolAddress((void**)&whi,  g_whi);
    cudaGetSymbolAddress((void**)&wmid, g_wmid);
    cudaGetSymbolAddress((void**)&phi,  g_phi);
    cudaGetSymbolAddress((void**)&pmid, g_pmid);
    cudaGetSymbolAddress((void**)&Xhi,  g_Xhi);
    cudaGetSymbolAddress((void**)&Xmid, g_Xmid);

    split_kernel<<<8192, 256>>>(x, xhi, xmid, 16384 * 512 / 4);
    split_kernel<<<768, 256>>>(qkv_w, whi, wmid, 1536 * 512 / 4);
    split_kernel<<<256, 256>>>(proj_w, phi, pmid, 512 * 512 / 4);

    cudaFuncSetAttribute(hmma_gemm<0>, cudaFuncAttributeMaxDynamicSharedMemorySize, GEMM_SMEM);
    cudaFuncSetAttribute(hmma_gemm<1>, cudaFuncAttributeMaxDynamicSharedMemorySize, GEMM_SMEM);
    cudaFuncSetAttribute(k3_mma, cudaFuncAttributeMaxDynamicSharedMemorySize, K3_SMEM);
    cudaFuncSetAttribute(tpart_mma, cudaFuncAttributeMaxDynamicSharedMemorySize, TP_SMEM);

    hmma_gemm<0><<<dim3(12, 128), 256, GEMM_SMEM>>>(xhi, xmid, whi, wmid, nullptr, nullptr);

    pool_kernel<<<BHN * MLAND, 64>>>();
    reset_kernel<<<1, 1>>>();
    k2_kernel<<<BHN, 256>>>();
    k3_mma<<<dim3(16, BHN), 256, K3_SMEM>>>();
    softmax3_kernel<<<BHN * MLAND, 256>>>();
    vtrans_kernel<<<dim3(64, BHN), 256>>>();
    tpart_mma<<<dim3(KSPLIT, BHN), 256, TP_SMEM>>>();
    treduce_kernel<<<(BHN * MLAND * HD) / 256, 256>>>();

    const int INV_SMEM = 5 * 64 * 65 * sizeof(float);
    cudaFuncSetAttribute(inv_kernel, cudaFuncAttributeMaxDynamicSharedMemorySize, INV_SMEM);
    inv_kernel<<<BHN, 256, INV_SMEM>>>();

    final_attn<<<dim3(64, BHN), 256>>>();

    hmma_gemm<1><<<dim3(4, 128), 256, GEMM_SMEM>>>(Xhi, Xmid, phi, pmid, proj_b, out);
}

// round 5
// speedup vs baseline: 2.0629x; 1.0765x over previous
#include <cuda_runtime.h>
#include <cuda_bf16.h>
#include <math.h>
#include <stdint.h>

// ---------------- problem constants ----------------
#define NBATCH 4
#define NHEAD  8
#define BHN    (NBATCH*NHEAD)      // 32
#define NTOK   4096
#define CDIM   512
#define HD     64
#define MLAND  64
#define KSPLIT 16
#define SCALE  0.35355339059327373f   // 64^-0.25

// ---------------- device scratch ----------------
__device__ float g_Q [BHN*NTOK*HD];
__device__ float g_Ql[BHN*MLAND*HD];
__device__ float g_Kl[BHN*MLAND*HD];
__device__ float g_K2[BHN*MLAND*MLAND];
__device__ float g_W [BHN*MLAND*HD];
__device__ float g_S3[BHN*MLAND*NTOK];
__device__ float g_Tpart[KSPLIT*BHN*MLAND*HD];
__device__ float g_colmax;

// bf16 hi/mid split buffers
__device__ __nv_bfloat16 g_xhi [16384*512];
__device__ __nv_bfloat16 g_xmid[16384*512];
__device__ __nv_bfloat16 g_whi [1536*512];
__device__ __nv_bfloat16 g_wmid[1536*512];
__device__ __nv_bfloat16 g_phi [512*512];
__device__ __nv_bfloat16 g_pmid[512*512];
__device__ __nv_bfloat16 g_Xhi [16384*512];
__device__ __nv_bfloat16 g_Xmid[16384*512];
// middle-stage bf16 operands
__device__ __nv_bfloat16 g_Khi [BHN*NTOK*HD];   // scaled K split, [bh][n][d]
__device__ __nv_bfloat16 g_Kmid[BHN*NTOK*HD];
__device__ __nv_bfloat16 g_Vhi [BHN*NTOK*HD];   // V split, [bh][n][d]
__device__ __nv_bfloat16 g_Vmid[BHN*NTOK*HD];
__device__ __nv_bfloat16 g_Qlh [BHN*MLAND*HD];
__device__ __nv_bfloat16 g_Qlm [BHN*MLAND*HD];
__device__ __nv_bfloat16 g_S3h [BHN*MLAND*NTOK];
__device__ __nv_bfloat16 g_S3m [BHN*MLAND*NTOK];

// ==================== PTX helpers ====================
__device__ __forceinline__ uint32_t smem_u32(const void* p) {
    uint32_t a;
    asm("{ .reg .u64 t; cvta.to.shared.u64 t, %1; cvt.u32.u64 %0, t; }" : "=r"(a) : "l"(p));
    return a;
}
__device__ __forceinline__ void ldsm_x4(uint32_t& r0, uint32_t& r1, uint32_t& r2, uint32_t& r3,
                                        uint32_t addr) {
    asm volatile("ldmatrix.sync.aligned.m8n8.x4.shared.b16 {%0,%1,%2,%3}, [%4];"
                 : "=r"(r0), "=r"(r1), "=r"(r2), "=r"(r3) : "r"(addr));
}
__device__ __forceinline__ void ldsm_x4_t(uint32_t& r0, uint32_t& r1, uint32_t& r2, uint32_t& r3,
                                          uint32_t addr) {
    asm volatile("ldmatrix.sync.aligned.m8n8.x4.trans.shared.b16 {%0,%1,%2,%3}, [%4];"
                 : "=r"(r0), "=r"(r1), "=r"(r2), "=r"(r3) : "r"(addr));
}
__device__ __forceinline__ void mma16816(float* c, const uint32_t* a, const uint32_t* b) {
    asm volatile("mma.sync.aligned.m16n8k16.row.col.f32.bf16.bf16.f32 "
                 "{%0,%1,%2,%3}, {%4,%5,%6,%7}, {%8,%9}, {%0,%1,%2,%3};"
                 : "+f"(c[0]), "+f"(c[1]), "+f"(c[2]), "+f"(c[3])
                 : "r"(a[0]), "r"(a[1]), "r"(a[2]), "r"(a[3]), "r"(b[0]), "r"(b[1]));
}
#define CP_ASYNC(dst, src) asm volatile("cp.async.cg.shared.global [%0], [%1], 16;" :: "r"(dst), "l"(src))
#define CP_COMMIT()        asm volatile("cp.async.commit_group;" ::: "memory")
#define CP_WAIT1()         asm volatile("cp.async.wait_group 1;" ::: "memory")
#define CP_WAIT0()         asm volatile("cp.async.wait_group 0;" ::: "memory")

__device__ __forceinline__ void store_bf16_pair(__nv_bfloat16* hi, __nv_bfloat16* mid,
                                                float x, float y) {
    __nv_bfloat16 h0 = __float2bfloat16(x);
    __nv_bfloat16 h1 = __float2bfloat16(y);
    *(__nv_bfloat162*)hi = __nv_bfloat162(h0, h1);
    *(__nv_bfloat162*)mid = __nv_bfloat162(__float2bfloat16(x - __bfloat162float(h0)),
                                           __float2bfloat16(y - __bfloat162float(h1)));
}

// ==================== bf16 3x-split HMMA GEMM (big GEMMs) ====================
#define PITCH 40
#define MAT_BYTES (128*PITCH*2)     // 10240
#define SM_A_HI  0
#define SM_A_MID (1*MAT_BYTES)
#define SM_B_HI  (2*MAT_BYTES)
#define SM_B_MID (3*MAT_BYTES)
#define BUF_BYTES (4*MAT_BYTES)     // 40960
#define GEMM_SMEM (2*BUF_BYTES)     // 81920

__device__ __forceinline__ void load_stage(uint32_t bufb, int k0, size_t rowA0, size_t rowB0,
                                           const __nv_bfloat16* __restrict__ Ahi,
                                           const __nv_bfloat16* __restrict__ Amid,
                                           const __nv_bfloat16* __restrict__ Bhi,
                                           const __nv_bfloat16* __restrict__ Bmid,
                                           int tid) {
#pragma unroll
    for (int half = 0; half < 2; half++) {
        int c = tid + half * 256;
        int r = c >> 2, cc = (c & 3) * 8;
        uint32_t d = bufb + (uint32_t)(r * PITCH + cc) * 2;
        size_t goffA = (rowA0 + r) * 512 + k0 + cc;
        size_t goffB = (rowB0 + r) * 512 + k0 + cc;
        CP_ASYNC(d + SM_A_HI,  Ahi  + goffA);
        CP_ASYNC(d + SM_A_MID, Amid + goffA);
        CP_ASYNC(d + SM_B_HI,  Bhi  + goffB);
        CP_ASYNC(d + SM_B_MID, Bmid + goffB);
    }
    CP_COMMIT();
}

template<int MODE>
__global__ __launch_bounds__(256, 2) void hmma_gemm(
    const __nv_bfloat16* __restrict__ Ahi, const __nv_bfloat16* __restrict__ Amid,
    const __nv_bfloat16* __restrict__ Bhi, const __nv_bfloat16* __restrict__ Bmid,
    const float* __restrict__ bias, float* __restrict__ Cout)
{
    extern __shared__ __align__(128) char sm[];
    uint32_t sb = smem_u32(sm);
    int tid = threadIdx.x;
    int lane = tid & 31, wid = tid >> 5;
    int wm = wid >> 2, wn = wid & 3;
    size_t rowA0 = (size_t)blockIdx.y * 128;
    size_t rowB0 = (size_t)blockIdx.x * 128;

    float acc[4][4][4] = {};

    int arow  = wm * 64 + (lane & 15);
    int akoff = (lane >> 4) * 8;
    int brow  = wn * 32 + (lane & 7) + ((lane >> 4) << 3);
    int bkoff = ((lane >> 3) & 1) * 8;

    load_stage(sb, 0, rowA0, rowB0, Ahi, Amid, Bhi, Bmid, tid);

    for (int t = 0; t < 16; t++) {
        if (t + 1 < 16) {
            load_stage(sb + ((t + 1) & 1) * BUF_BYTES, (t + 1) * 32, rowA0, rowB0,
                       Ahi, Amid, Bhi, Bmid, tid);
            CP_WAIT1();
        } else {
            CP_WAIT0();
        }
        __syncthreads();

        uint32_t base = sb + (t & 1) * BUF_BYTES;
#pragma unroll
        for (int kk = 0; kk < 32; kk += 16) {
            uint32_t bhi[4][2], bmid[4][2];
#pragma unroll
            for (int np = 0; np < 2; np++) {
                uint32_t off = (uint32_t)((brow + np * 16) * PITCH + kk + bkoff) * 2;
                uint32_t r0, r1, r2, r3;
                ldsm_x4(r0, r1, r2, r3, base + SM_B_HI + off);
                bhi[np * 2][0] = r0; bhi[np * 2][1] = r1;
                bhi[np * 2 + 1][0] = r2; bhi[np * 2 + 1][1] = r3;
                ldsm_x4(r0, r1, r2, r3, base + SM_B_MID + off);
                bmid[np * 2][0] = r0; bmid[np * 2][1] = r1;
                bmid[np * 2 + 1][0] = r2; bmid[np * 2 + 1][1] = r3;
            }
#pragma unroll
            for (int mi = 0; mi < 4; mi++) {
                uint32_t ahi[4], amid[4];
                uint32_t off = (uint32_t)((arow + mi * 16) * PITCH + kk + akoff) * 2;
                ldsm_x4(ahi[0], ahi[1], ahi[2], ahi[3], base + SM_A_HI + off);
                ldsm_x4(amid[0], amid[1], amid[2], amid[3], base + SM_A_MID + off);
#pragma unroll
                for (int ni = 0; ni < 4; ni++) {
                    mma16816(acc[mi][ni], ahi, bhi[ni]);
                    mma16816(acc[mi][ni], ahi, bmid[ni]);
                    mma16816(acc[mi][ni], amid, bhi[ni]);
                }
            }
        }
        __syncthreads();
    }

    int colW = blockIdx.x * 128 + wn * 32 + 2 * (lane & 3);
    int rowW = blockIdx.y * 128 + wm * 64 + (lane >> 2);
#pragma unroll
    for (int ni = 0; ni < 4; ni++) {
        int col = colW + ni * 8;
#pragma unroll
        for (int mi = 0; mi < 4; mi++) {
            int row0 = rowW + mi * 16;
            if (MODE == 0) {
                int which = col >> 9;
                int h = (col >> 6) & 7;
                int d = col & 63;
#pragma unroll
                for (int rr = 0; rr < 2; rr++) {
                    int row = row0 + rr * 8;
                    int b = row >> 12, n = row & 4095;
                    size_t idx = ((size_t)(b * 8 + h) * NTOK + n) * HD + d;
                    float vx = acc[mi][ni][rr * 2 + 0];
                    float vy = acc[mi][ni][rr * 2 + 1];
                    if (which == 0) {           // Q: fp32, scaled
                        float2 v; v.x = vx * SCALE; v.y = vy * SCALE;
                        *(float2*)(g_Q + idx) = v;
                    } else if (which == 1) {    // K: bf16 hi/mid, scaled
                        store_bf16_pair(g_Khi + idx, g_Kmid + idx, vx * SCALE, vy * SCALE);
                    } else {                    // V: bf16 hi/mid
                        store_bf16_pair(g_Vhi + idx, g_Vmid + idx, vx, vy);
                    }
                }
            } else {
                float2 bb = *(const float2*)(bias + col);
#pragma unroll
                for (int rr = 0; rr < 2; rr++) {
                    int row = row0 + rr * 8;
                    float2 v;
                    v.x = acc[mi][ni][rr * 2 + 0] + bb.x;
                    v.y = acc[mi][ni][rr * 2 + 1] + bb.y;
                    *(float2*)(Cout + (size_t)row * 512 + col) = v;
                }
            }
        }
    }
}

// ==================== fp32 -> bf16 hi/mid split ====================
__global__ void split_kernel(const float* __restrict__ src,
                             __nv_bfloat16* __restrict__ hi,
                             __nv_bfloat16* __restrict__ mid, int n4) {
    int i = blockIdx.x * 256 + threadIdx.x;
    if (i >= n4) return;
    float4 v = ((const float4*)src)[i];
    store_bf16_pair(hi + i * 4,     mid + i * 4,     v.x, v.y);
    store_bf16_pair(hi + i * 4 + 2, mid + i * 4 + 2, v.z, v.w);
}

// =====================================================================
// Landmark pooling (+ colmax reset).  K mean reconstructed from hi+mid.
// =====================================================================
__global__ void pool_kernel() {
    if (blockIdx.x == 0 && threadIdx.x == 0) g_colmax = 0.0f;
    int bm = blockIdx.x;
    int bh = bm >> 6, m = bm & 63;
    int d = threadIdx.x;
    size_t base = (((size_t)bh * NTOK) + m * 64) * HD + d;
    float sq = 0.f, sk = 0.f;
#pragma unroll 8
    for (int t = 0; t < 64; t++) {
        sq += g_Q[base + (size_t)t * HD];
        sk += __bfloat162float(g_Khi[base + (size_t)t * HD])
            + __bfloat162float(g_Kmid[base + (size_t)t * HD]);
    }
    float ql = sq * (1.f / 64.f);
    int idx = (bh * 64 + m) * 64 + d;
    g_Ql[idx] = ql;
    g_Kl[idx] = sk * (1.f / 64.f);
    __nv_bfloat16 h = __float2bfloat16(ql);
    g_Qlh[idx] = h;
    g_Qlm[idx] = __float2bfloat16(ql - __bfloat162float(h));
}

// =====================================================================
// kernel_2 = softmax(Ql @ Kl^T) + colsum max
// =====================================================================
__global__ __launch_bounds__(256) void k2_kernel() {
    __shared__ float Qs[64][68];
    __shared__ float Ks[64][68];
    int bh = blockIdx.x, tid = threadIdx.x;
    for (int i = tid; i < 4096; i += 256) {
        Qs[i >> 6][i & 63] = g_Ql[bh * 4096 + i];
        Ks[i >> 6][i & 63] = g_Kl[bh * 4096 + i];
    }
    __syncthreads();
    int ty = tid >> 4, tx = tid & 15, r0 = ty * 4, c0 = tx * 4;
    float acc[4][4] = {};
    for (int k = 0; k < 64; k++) {
        float a[4], b[4];
#pragma unroll
        for (int i = 0; i < 4; i++) a[i] = Qs[r0 + i][k];
#pragma unroll
        for (int j = 0; j < 4; j++) b[j] = Ks[c0 + j][k];
#pragma unroll
        for (int i = 0; i < 4; i++)
#pragma unroll
            for (int j = 0; j < 4; j++) acc[i][j] = fmaf(a[i], b[j], acc[i][j]);
    }
    __syncthreads();
#pragma unroll
    for (int i = 0; i < 4; i++)
#pragma unroll
        for (int j = 0; j < 4; j++) Qs[r0 + i][c0 + j] = acc[i][j];
    __syncthreads();
    if (tid < 64) {
        float mx = -1e30f;
        for (int c = 0; c < 64; c++) mx = fmaxf(mx, Qs[tid][c]);
        float s = 0.f;
        for (int c = 0; c < 64; c++) { float e = expf(Qs[tid][c] - mx); Qs[tid][c] = e; s += e; }
        float inv = 1.f / s;
        for (int c = 0; c < 64; c++) {
            float v = Qs[tid][c] * inv;
            Qs[tid][c] = v;
            g_K2[bh * 4096 + tid * 64 + c] = v;
        }
    }
    __syncthreads();
    if (tid < 64) {
        float cs = 0.f;
        for (int r = 0; r < 64; r++) cs += Qs[r][tid];
        atomicMax((int*)&g_colmax, __float_as_int(cs));
    }
}

// =====================================================================
// k3 scores via tensor cores: S3 = Ql·K^T, 3-term bf16 split.
// =====================================================================
#define K3_PITCH 72
#define K3_QLH 0
#define K3_QLM (64*K3_PITCH*2)
#define K3_KH  (2*64*K3_PITCH*2)
#define K3_KM  (K3_KH + 256*K3_PITCH*2)
#define K3_SMEM (K3_KM + 256*K3_PITCH*2)   // 92160

__global__ __launch_bounds__(256) void k3_mma() {
    extern __shared__ __align__(128) char sm[];
    uint32_t sb = smem_u32(sm);
    int nt = blockIdx.x, bh = blockIdx.y, tid = threadIdx.x;
    int lane = tid & 31, wid = tid >> 5;

    const uint4* qh = (const uint4*)(g_Qlh + bh * 4096);
    const uint4* qm = (const uint4*)(g_Qlm + bh * 4096);
#pragma unroll
    for (int it = 0; it < 2; it++) {
        int c = tid + it * 256;
        int row = c >> 3, col = (c & 7) * 8;
        uint32_t off = (uint32_t)(row * K3_PITCH + col) * 2;
        *(uint4*)(sm + K3_QLH + off) = qh[c];
        *(uint4*)(sm + K3_QLM + off) = qm[c];
    }
    const uint4* kh = (const uint4*)(g_Khi + ((size_t)bh * NTOK + nt * 256) * 64);
    const uint4* km = (const uint4*)(g_Kmid + ((size_t)bh * NTOK + nt * 256) * 64);
#pragma unroll
    for (int it = 0; it < 8; it++) {
        int c = tid + it * 256;
        int row = c >> 3, col = (c & 7) * 8;
        uint32_t off = (uint32_t)(row * K3_PITCH + col) * 2;
        *(uint4*)(sm + K3_KH + off) = kh[c];
        *(uint4*)(sm + K3_KM + off) = km[c];
    }
    __syncthreads();

    int arow = lane & 15;
    int akoff = (lane >> 4) * 8;
    int brow = wid * 32 + (lane & 7) + ((lane >> 4) << 3);
    int bkoff = ((lane >> 3) & 1) * 8;

    float acc[4][4][4] = {};
#pragma unroll
    for (int kk = 0; kk < 64; kk += 16) {
        uint32_t bhi[4][2], bmid[4][2];
#pragma unroll
        for (int np = 0; np < 2; np++) {
            uint32_t off = (uint32_t)((brow + np * 16) * K3_PITCH + kk + bkoff) * 2;
            uint32_t r0, r1, r2, r3;
            ldsm_x4(r0, r1, r2, r3, sb + K3_KH + off);
            bhi[np * 2][0] = r0; bhi[np * 2][1] = r1;
            bhi[np * 2 + 1][0] = r2; bhi[np * 2 + 1][1] = r3;
            ldsm_x4(r0, r1, r2, r3, sb + K3_KM + off);
            bmid[np * 2][0] = r0; bmid[np * 2][1] = r1;
            bmid[np * 2 + 1][0] = r2; bmid[np * 2 + 1][1] = r3;
        }
#pragma unroll
        for (int mi = 0; mi < 4; mi++) {
            uint32_t ahi[4], amid[4];
            uint32_t off = (uint32_t)((arow + mi * 16) * K3_PITCH + kk + akoff) * 2;
            ldsm_x4(ahi[0], ahi[1], ahi[2], ahi[3], sb + K3_QLH + off);
            ldsm_x4(amid[0], amid[1], amid[2], amid[3], sb + K3_QLM + off);
#pragma unroll
            for (int ni = 0; ni < 4; ni++) {
                mma16816(acc[mi][ni], ahi, bhi[ni]);
                mma16816(acc[mi][ni], ahi, bmid[ni]);
                mma16816(acc[mi][ni], amid, bhi[ni]);
            }
        }
    }
#pragma unroll
    for (int mi = 0; mi < 4; mi++)
#pragma unroll
        for (int ni = 0; ni < 4; ni++)
#pragma unroll
            for (int rr = 0; rr < 2; rr++) {
                int row = mi * 16 + (lane >> 2) + rr * 8;
                int col = wid * 32 + ni * 8 + 2 * (lane & 3);
                float2 v;
                v.x = acc[mi][ni][rr * 2 + 0];
                v.y = acc[mi][ni][rr * 2 + 1];
                *(float2*)(g_S3 + ((size_t)bh * 64 + row) * NTOK + nt * 256 + col) = v;
            }
}

// =====================================================================
// row softmax over N=4096; emits bf16 hi/mid P
// =====================================================================
__global__ __launch_bounds__(256) void softmax3_kernel() {
    __shared__ float redA[8], redB[8];
    int row = blockIdx.x, tid = threadIdx.x;
    const float* p = g_S3 + (size_t)row * NTOK;
    float v[16];
    float mx = -1e30f;
#pragma unroll
    for (int i = 0; i < 16; i++) { v[i] = p[tid + i * 256]; mx = fmaxf(mx, v[i]); }
#pragma unroll
    for (int o = 16; o; o >>= 1) mx = fmaxf(mx, __shfl_xor_sync(~0u, mx, o));
    if ((tid & 31) == 0) redA[tid >> 5] = mx;
    __syncthreads();
    mx = redA[0];
#pragma unroll
    for (int w = 1; w < 8; w++) mx = fmaxf(mx, redA[w]);
    float s = 0.f;
#pragma unroll
    for (int i = 0; i < 16; i++) { v[i] = expf(v[i] - mx); s += v[i]; }
#pragma unroll
    for (int o = 16; o; o >>= 1) s += __shfl_xor_sync(~0u, s, o);
    if ((tid & 31) == 0) redB[tid >> 5] = s;
    __syncthreads();
    s = 0.f;
#pragma unroll
    for (int w = 0; w < 8; w++) s += redB[w];
    float inv = 1.f / s;
#pragma unroll
    for (int i = 0; i < 16; i++) {
        float pv = v[i] * inv;
        __nv_bfloat16 h = __float2bfloat16(pv);
        size_t idx = (size_t)row * NTOK + tid + i * 256;
        g_S3h[idx] = h;
        g_S3m[idx] = __float2bfloat16(pv - __bfloat162float(h));
    }
}

// =====================================================================
// T_part = P @ V via tensor cores, V as [k][d] with ldmatrix.trans.
// grid (16 ks, 32 bh), 256 threads; 8 warps: 2M x 4N, warp tile 32x16.
// =====================================================================
#define TP_SPITCH 136
#define TP_VPITCH 72
#define TP_SH 0
#define TP_SM (64*TP_SPITCH*2)                 // 17408
#define TP_VH (2*64*TP_SPITCH*2)               // 34816
#define TP_VM (TP_VH + 128*TP_VPITCH*2)        // 53248
#define TP_SMEM (TP_VM + 128*TP_VPITCH*2)      // 71680

__global__ __launch_bounds__(256) void tpart_mma() {
    extern __shared__ __align__(128) char sm[];
    uint32_t sb = smem_u32(sm);
    int ks = blockIdx.x, bh = blockIdx.y, tid = threadIdx.x;
    int lane = tid & 31, wid = tid >> 5;
    int wm = wid >> 2, wn = wid & 3;

    int arow = wm * 32 + (lane & 15);
    int akoff = (lane >> 4) * 8;
    // trans-B addressing: krow = kk + (lane&15), ncol = wn*16 + (lane>>4)*8
    int bk = lane & 15;
    int bn = wn * 16 + ((lane >> 4) << 3);

    float acc[2][2][4] = {};

    for (int kh = 0; kh < 2; kh++) {
        size_t gk = (size_t)ks * 256 + kh * 128;
        const uint4* shp = (const uint4*)(g_S3h + ((size_t)bh * 64) * NTOK + gk);
        const uint4* smp = (const uint4*)(g_S3m + ((size_t)bh * 64) * NTOK + gk);
        const uint4* vhp = (const uint4*)(g_Vhi + ((size_t)bh * NTOK + gk) * 64);
        const uint4* vmp = (const uint4*)(g_Vmid + ((size_t)bh * NTOK + gk) * 64);
        __syncthreads();
        // S tiles: 64 rows x 128 k (16 uint4/row)
#pragma unroll
        for (int it = 0; it < 4; it++) {
            int c = tid + it * 256;
            int row = c >> 4, col = (c & 15) * 8;
            uint32_t off = (uint32_t)(row * TP_SPITCH + col) * 2;
            size_t gidx = (size_t)row * (NTOK / 8) + (c & 15);
            *(uint4*)(sm + TP_SH + off) = shp[gidx];
            *(uint4*)(sm + TP_SM + off) = smp[gidx];
        }
        // V tiles: 128 rows (k) x 64 d (8 uint4/row)
#pragma unroll
        for (int it = 0; it < 4; it++) {
            int c = tid + it * 256;
            int row = c >> 3, col = (c & 7) * 8;
            uint32_t off = (uint32_t)(row * TP_VPITCH + col) * 2;
            *(uint4*)(sm + TP_VH + off) = vhp[c];
            *(uint4*)(sm + TP_VM + off) = vmp[c];
        }
        __syncthreads();
#pragma unroll
        for (int kk = 0; kk < 128; kk += 16) {
            uint32_t bhi[2][2], bmid[2][2];
            {
                uint32_t off = (uint32_t)((kk + bk) * TP_VPITCH + bn) * 2;
                uint32_t r0, r1, r2, r3;
                ldsm_x4_t(r0, r1, r2, r3, sb + TP_VH + off);
                bhi[0][0] = r0; bhi[0][1] = r1; bhi[1][0] = r2; bhi[1][1] = r3;
                ldsm_x4_t(r0, r1, r2, r3, sb + TP_VM + off);
                bmid[0][0] = r0; bmid[0][1] = r1; bmid[1][0] = r2; bmid[1][1] = r3;
            }
#pragma unroll
            for (int mi = 0; mi < 2; mi++) {
                uint32_t ahi[4], amid[4];
                uint32_t off = (uint32_t)((arow + mi * 16) * TP_SPITCH + kk + akoff) * 2;
                ldsm_x4(ahi[0], ahi[1], ahi[2], ahi[3], sb + TP_SH + off);
                ldsm_x4(amid[0], amid[1], amid[2], amid[3], sb + TP_SM + off);
#pragma unroll
                for (int ni = 0; ni < 2; ni++) {
                    mma16816(acc[mi][ni], ahi, bhi[ni]);
                    mma16816(acc[mi][ni], ahi, bmid[ni]);
                    mma16816(acc[mi][ni], amid, bhi[ni]);
                }
            }
        }
    }
#pragma unroll
    for (int mi = 0; mi < 2; mi++)
#pragma unroll
        for (int ni = 0; ni < 2; ni++)
#pragma unroll
            for (int rr = 0; rr < 2; rr++) {
                int row = wm * 32 + mi * 16 + (lane >> 2) + rr * 8;
                int col = wn * 16 + ni * 8 + 2 * (lane & 3);
                float2 v;
                v.x = acc[mi][ni][rr * 2 + 0];
                v.y = acc[mi][ni][rr * 2 + 1];
                *(float2*)(g_Tpart + (((size_t)ks * BHN + bh) * 64 + row) * 64 + col) = v;
            }
}

// =====================================================================
// Newton-Schulz inverse (6 iters) + W = Vinv @ T.  512 threads.
// Folds the Tpart reduction into its prologue.
// =====================================================================
__device__ __forceinline__ void mm64w(const float* __restrict__ X,
                                      const float* __restrict__ Y,
                                      float* __restrict__ Z, int tid) {
    int ty = tid >> 5, tx = tid & 31;       // 16 x 32
    int r0 = ty * 4, c0 = tx * 2;
    float acc[4][2] = {};
    for (int k = 0; k < 64; k++) {
        float a[4], b[2];
#pragma unroll
        for (int i = 0; i < 4; i++) a[i] = X[(r0 + i) * 65 + k];
        b[0] = Y[k * 65 + c0];
        b[1] = Y[k * 65 + c0 + 1];
#pragma unroll
        for (int i = 0; i < 4; i++) {
            acc[i][0] = fmaf(a[i], b[0], acc[i][0]);
            acc[i][1] = fmaf(a[i], b[1], acc[i][1]);
        }
    }
#pragma unroll
    for (int i = 0; i < 4; i++) {
        Z[(r0 + i) * 65 + c0] = acc[i][0];
        Z[(r0 + i) * 65 + c0 + 1] = acc[i][1];
    }
}

__global__ __launch_bounds__(512) void inv_kernel() {
    extern __shared__ float sh[];
    float* Km = sh;
    float* Vm = sh + 64 * 65;
    float* Am = sh + 2 * 64 * 65;
    float* T1 = sh + 3 * 64 * 65;
    float* T2 = sh + 4 * 64 * 65;
    int bh = blockIdx.x, tid = threadIdx.x;
    float ginv = 1.f / g_colmax;
    for (int i = tid; i < 4096; i += 512) {
        int r = i >> 6, c = i & 63;
        Km[r * 65 + c] = g_K2[bh * 4096 + r * 64 + c];
        Vm[r * 65 + c] = g_K2[bh * 4096 + c * 64 + r] * ginv;
        // fold treduce: sum 16 Tpart slices
        float s = 0.f;
#pragma unroll
        for (int ksp = 0; ksp < KSPLIT; ksp++)
            s += g_Tpart[(size_t)ksp * (BHN * MLAND * HD) + bh * 4096 + i];
        T2[r * 65 + c] = s;   // park T in T2's slot? T2 gets overwritten in iter — use separate store
    }
    __syncthreads();
    // move T out of T2 into global? No — keep T in registers is impossible; reuse g_W as temp
    for (int i = tid; i < 4096; i += 512) {
        int r = i >> 6, c = i & 63;
        g_W[bh * 4096 + i] = T2[r * 65 + c];   // stash T
    }
    for (int it = 0; it < 6; it++) {
        __syncthreads();
        mm64w(Km, Vm, Am, tid);
        __syncthreads();
        for (int i = tid; i < 4096; i += 512) {
            int r = i >> 6, c = i & 63;
            T1[r * 65 + c] = (r == c ? 7.0f : 0.0f) - Am[r * 65 + c];
        }
        __syncthreads();
        mm64w(Am, T1, T2, tid);
        __syncthreads();
        for (int i = tid; i < 4096; i += 512) {
            int r = i >> 6, c = i & 63;
            T2[r * 65 + c] = (r == c ? 15.0f : 0.0f) - T2[r * 65 + c];
        }
        __syncthreads();
        mm64w(Am, T2, T1, tid);
        __syncthreads();
        for (int i = tid; i < 4096; i += 512) {
            int r = i >> 6, c = i & 63;
            T1[r * 65 + c] = (r == c ? 13.0f : 0.0f) - T1[r * 65 + c];
        }
        __syncthreads();
        mm64w(Vm, T1, T2, tid);
        __syncthreads();
        for (int i = tid; i < 4096; i += 512) {
            int r = i >> 6, c = i & 63;
            Vm[r * 65 + c] = 0.25f * T2[r * 65 + c];
        }
    }
    __syncthreads();
    for (int i = tid; i < 4096; i += 512) {   // reload stashed T
        int r = i >> 6, c = i & 63;
        Am[r * 65 + c] = g_W[bh * 4096 + i];
    }
    __syncthreads();
    mm64w(Vm, Am, T1, tid);
    __syncthreads();
    for (int i = tid; i < 4096; i += 512) {
        int r = i >> 6, c = i & 63;
        g_W[bh * 4096 + i] = T1[r * 65 + c];
    }
}

// =====================================================================
// Final fused: softmax(Q @ Kl^T) @ W -> g_Xhi/g_Xmid bf16
// =====================================================================
__global__ __launch_bounds__(256) void final_attn() {
    __shared__ float Qs[64][68];
    __shared__ float Bs[64][68];
    int nt = blockIdx.x, bh = blockIdx.y, tid = threadIdx.x;
    int b = bh >> 3, h = bh & 7;
    int ty = tid >> 4, tx = tid & 15, r0 = ty * 4, c0 = tx * 4;
    for (int i = tid; i < 4096; i += 256) {
        Qs[i >> 6][i & 63] = g_Q[(((size_t)bh * NTOK) + nt * 64) * HD + i];
        Bs[i >> 6][i & 63] = g_Kl[bh * 4096 + i];
    }
    __syncthreads();
    float s[4][4] = {};
    for (int k = 0; k < 64; k++) {
        float a[4], bb[4];
#pragma unroll
        for (int i = 0; i < 4; i++) a[i] = Qs[r0 + i][k];
#pragma unroll
        for (int j = 0; j < 4; j++) bb[j] = Bs[c0 + j][k];
#pragma unroll
        for (int i = 0; i < 4; i++)
#pragma unroll
            for (int j = 0; j < 4; j++) s[i][j] = fmaf(a[i], bb[j], s[i][j]);
    }
#pragma unroll
    for (int i = 0; i < 4; i++) {
        float mx = fmaxf(fmaxf(s[i][0], s[i][1]), fmaxf(s[i][2], s[i][3]));
#pragma unroll
        for (int o = 8; o; o >>= 1) mx = fmaxf(mx, __shfl_xor_sync(~0u, mx, o, 16));
        float ss = 0.f;
#pragma unroll
        for (int j = 0; j < 4; j++) { s[i][j] = expf(s[i][j] - mx); ss += s[i][j]; }
#pragma unroll
        for (int o = 8; o; o >>= 1) ss += __shfl_xor_sync(~0u, ss, o, 16);
        float inv = 1.f / ss;
#pragma unroll
        for (int j = 0; j < 4; j++) s[i][j] *= inv;
    }
    __syncthreads();
    for (int i = tid; i < 4096; i += 256)
        Bs[i >> 6][i & 63] = g_W[bh * 4096 + i];
    __syncthreads();
    float acc[4][4] = {};
#pragma unroll
    for (int mo = 0; mo < 16; mo++) {
#pragma unroll
        for (int mi = 0; mi < 4; mi++) {
            float w[4];
            *(float4*)w = *(const float4*)&Bs[mo * 4 + mi][c0];
#pragma unroll
            for (int i = 0; i < 4; i++) {
                float pv = __shfl_sync(~0u, s[i][mi], mo, 16);
#pragma unroll
                for (int j = 0; j < 4; j++) acc[i][j] = fmaf(pv, w[j], acc[i][j]);
            }
        }
    }
#pragma unroll
    for (int i = 0; i < 4; i++)
#pragma unroll
        for (int j = 0; j < 4; j += 2) {
            size_t idx = (((size_t)b * NTOK) + nt * 64 + r0 + i) * CDIM + h * 64 + c0 + j;
            store_bf16_pair(g_Xhi + idx, g_Xmid + idx, acc[i][j], acc[i][j + 1]);
        }
}

// =====================================================================
// host launcher
// =====================================================================
extern "C" void kernel_launch(void* const* d_in, const int* in_sizes, int n_in,
                              void* d_out, int out_size) {
    const float* x      = (const float*)d_in[0];
    const float* qkv_w  = (const float*)d_in[1];
    const float* proj_w = (const float*)d_in[2];
    const float* proj_b = (const float*)d_in[3];
    float* out = (float*)d_out;

    __nv_bfloat16 *xhi, *xmid, *whi, *wmid, *phi, *pmid, *Xhi, *Xmid;
    cudaGetSymbolAddress((void**)&xhi,  g_xhi);
    cudaGetSymbolAddress((void**)&xmid, g_xmid);
    cudaGetSymbolAddress((void**)&whi,  g_whi);
    cudaGetSymbolAddress((void**)&wmid, g_wmid);
    cudaGetSymbolAddress((void**)&phi,  g_phi);
    cudaGetSymbolAddress((void**)&pmid, g_pmid);
    cudaGetSymbolAddress((void**)&Xhi,  g_Xhi);
    cudaGetSymbolAddress((void**)&Xmid, g_Xmid);

    split_kernel<<<8192, 256>>>(x, xhi, xmid, 16384 * 512 / 4);
    split_kernel<<<768, 256>>>(qkv_w, whi, wmid, 1536 * 512 / 4);
    split_kernel<<<256, 256>>>(proj_w, phi, pmid, 512 * 512 / 4);

    cudaFuncSetAttribute(hmma_gemm<0>, cudaFuncAttributeMaxDynamicSharedMemorySize, GEMM_SMEM);
    cudaFuncSetAttribute(hmma_gemm<1>, cudaFuncAttributeMaxDynamicSharedMemorySize, GEMM_SMEM);
    cudaFuncSetAttribute(k3_mma, cudaFuncAttributeMaxDynamicSharedMemorySize, K3_SMEM);
    cudaFuncSetAttribute(tpart_mma, cudaFuncAttributeMaxDynamicSharedMemorySize, TP_SMEM);

    hmma_gemm<0><<<dim3(12, 128), 256, GEMM_SMEM>>>(xhi, xmid, whi, wmid, nullptr, nullptr);

    pool_kernel<<<BHN * MLAND, 64>>>();
    k2_kernel<<<BHN, 256>>>();
    k3_mma<<<dim3(16, BHN), 256, K3_SMEM>>>();
    softmax3_kernel<<<BHN * MLAND, 256>>>();
    tpart_mma<<<dim3(KSPLIT, BHN), 256, TP_SMEM>>>();

    const int INV_SMEM = 5 * 64 * 65 * sizeof(float);
    cudaFuncSetAttribute(inv_kernel, cudaFuncAttributeMaxDynamicSharedMemorySize, INV_SMEM);
    inv_kernel<<<BHN, 512, INV_SMEM>>>();

    final_attn<<<dim3(64, BHN), 256>>>();

    hmma_gemm<1><<<dim3(4, 128), 256, GEMM_SMEM>>>(Xhi, Xmid, phi, pmid, proj_b, out);
}

// round 6
// speedup vs baseline: 2.4029x; 1.1648x over previous
#include <cuda_runtime.h>
#include <cuda_bf16.h>
#include <math.h>
#include <stdint.h>

// ---------------- problem constants ----------------
#define NBATCH 4
#define NHEAD  8
#define BHN    (NBATCH*NHEAD)      // 32
#define NTOK   4096
#define CDIM   512
#define HD     64
#define MLAND  64
#define KSPLIT 16
#define SCALE  0.35355339059327373f   // 64^-0.25

// ---------------- device scratch ----------------
__device__ float g_Ql[BHN*MLAND*HD];
__device__ float g_Kl[BHN*MLAND*HD];
__device__ float g_K2[BHN*MLAND*MLAND];
__device__ float g_W [BHN*MLAND*HD];          // fp32 stash inside inv
__device__ float g_S3[BHN*MLAND*NTOK];
__device__ float g_Tpart[KSPLIT*BHN*MLAND*HD];
__device__ float g_colmax;

// bf16 hi/mid split buffers
__device__ __nv_bfloat16 g_xhi [16384*512];
__device__ __nv_bfloat16 g_xmid[16384*512];
__device__ __nv_bfloat16 g_whi [1536*512];
__device__ __nv_bfloat16 g_wmid[1536*512];
__device__ __nv_bfloat16 g_phi [512*512];
__device__ __nv_bfloat16 g_pmid[512*512];
__device__ __nv_bfloat16 g_Xhi [16384*512];
__device__ __nv_bfloat16 g_Xmid[16384*512];
// middle-stage bf16 operands
__device__ __nv_bfloat16 g_Qhi [BHN*NTOK*HD];   // scaled Q split, [bh][n][d]
__device__ __nv_bfloat16 g_Qmid[BHN*NTOK*HD];
__device__ __nv_bfloat16 g_Khi [BHN*NTOK*HD];   // scaled K split
__device__ __nv_bfloat16 g_Kmid[BHN*NTOK*HD];
__device__ __nv_bfloat16 g_Vhi [BHN*NTOK*HD];
__device__ __nv_bfloat16 g_Vmid[BHN*NTOK*HD];
__device__ __nv_bfloat16 g_Qlh [BHN*MLAND*HD];
__device__ __nv_bfloat16 g_Qlm [BHN*MLAND*HD];
__device__ __nv_bfloat16 g_Klh [BHN*MLAND*HD];
__device__ __nv_bfloat16 g_Klm [BHN*MLAND*HD];
__device__ __nv_bfloat16 g_Whi [BHN*MLAND*HD];
__device__ __nv_bfloat16 g_Wmid[BHN*MLAND*HD];
__device__ __nv_bfloat16 g_S3h [BHN*MLAND*NTOK];
__device__ __nv_bfloat16 g_S3m [BHN*MLAND*NTOK];

// ==================== PTX helpers ====================
__device__ __forceinline__ uint32_t smem_u32(const void* p) {
    uint32_t a;
    asm("{ .reg .u64 t; cvta.to.shared.u64 t, %1; cvt.u32.u64 %0, t; }" : "=r"(a) : "l"(p));
    return a;
}
__device__ __forceinline__ void ldsm_x4(uint32_t& r0, uint32_t& r1, uint32_t& r2, uint32_t& r3,
                                        uint32_t addr) {
    asm volatile("ldmatrix.sync.aligned.m8n8.x4.shared.b16 {%0,%1,%2,%3}, [%4];"
                 : "=r"(r0), "=r"(r1), "=r"(r2), "=r"(r3) : "r"(addr));
}
__device__ __forceinline__ void ldsm_x4_t(uint32_t& r0, uint32_t& r1, uint32_t& r2, uint32_t& r3,
                                          uint32_t addr) {
    asm volatile("ldmatrix.sync.aligned.m8n8.x4.trans.shared.b16 {%0,%1,%2,%3}, [%4];"
                 : "=r"(r0), "=r"(r1), "=r"(r2), "=r"(r3) : "r"(addr));
}
__device__ __forceinline__ void mma16816(float* c, const uint32_t* a, const uint32_t* b) {
    asm volatile("mma.sync.aligned.m16n8k16.row.col.f32.bf16.bf16.f32 "
                 "{%0,%1,%2,%3}, {%4,%5,%6,%7}, {%8,%9}, {%0,%1,%2,%3};"
                 : "+f"(c[0]), "+f"(c[1]), "+f"(c[2]), "+f"(c[3])
                 : "r"(a[0]), "r"(a[1]), "r"(a[2]), "r"(a[3]), "r"(b[0]), "r"(b[1]));
}
#define CP_ASYNC(dst, src) asm volatile("cp.async.cg.shared.global [%0], [%1], 16;" :: "r"(dst), "l"(src))
#define CP_COMMIT()        asm volatile("cp.async.commit_group;" ::: "memory")
#define CP_WAIT1()         asm volatile("cp.async.wait_group 1;" ::: "memory")
#define CP_WAIT0()         asm volatile("cp.async.wait_group 0;" ::: "memory")

__device__ __forceinline__ void store_bf16_pair(__nv_bfloat16* hi, __nv_bfloat16* mid,
                                                float x, float y) {
    __nv_bfloat16 h0 = __float2bfloat16(x);
    __nv_bfloat16 h1 = __float2bfloat16(y);
    *(__nv_bfloat162*)hi = __nv_bfloat162(h0, h1);
    *(__nv_bfloat162*)mid = __nv_bfloat162(__float2bfloat16(x - __bfloat162float(h0)),
                                           __float2bfloat16(y - __bfloat162float(h1)));
}

// ==================== bf16 3x-split HMMA GEMM (big GEMMs) ====================
#define PITCH 40
#define MAT_BYTES (128*PITCH*2)
#define SM_A_HI  0
#define SM_A_MID (1*MAT_BYTES)
#define SM_B_HI  (2*MAT_BYTES)
#define SM_B_MID (3*MAT_BYTES)
#define BUF_BYTES (4*MAT_BYTES)
#define GEMM_SMEM (2*BUF_BYTES)

__device__ __forceinline__ void load_stage(uint32_t bufb, int k0, size_t rowA0, size_t rowB0,
                                           const __nv_bfloat16* __restrict__ Ahi,
                                           const __nv_bfloat16* __restrict__ Amid,
                                           const __nv_bfloat16* __restrict__ Bhi,
                                           const __nv_bfloat16* __restrict__ Bmid,
                                           int tid) {
#pragma unroll
    for (int half = 0; half < 2; half++) {
        int c = tid + half * 256;
        int r = c >> 2, cc = (c & 3) * 8;
        uint32_t d = bufb + (uint32_t)(r * PITCH + cc) * 2;
        size_t goffA = (rowA0 + r) * 512 + k0 + cc;
        size_t goffB = (rowB0 + r) * 512 + k0 + cc;
        CP_ASYNC(d + SM_A_HI,  Ahi  + goffA);
        CP_ASYNC(d + SM_A_MID, Amid + goffA);
        CP_ASYNC(d + SM_B_HI,  Bhi  + goffB);
        CP_ASYNC(d + SM_B_MID, Bmid + goffB);
    }
    CP_COMMIT();
}

template<int MODE>
__global__ __launch_bounds__(256, 2) void hmma_gemm(
    const __nv_bfloat16* __restrict__ Ahi, const __nv_bfloat16* __restrict__ Amid,
    const __nv_bfloat16* __restrict__ Bhi, const __nv_bfloat16* __restrict__ Bmid,
    const float* __restrict__ bias, float* __restrict__ Cout)
{
    extern __shared__ __align__(128) char sm[];
    uint32_t sb = smem_u32(sm);
    int tid = threadIdx.x;
    int lane = tid & 31, wid = tid >> 5;
    int wm = wid >> 2, wn = wid & 3;
    size_t rowA0 = (size_t)blockIdx.y * 128;
    size_t rowB0 = (size_t)blockIdx.x * 128;

    float acc[4][4][4] = {};

    int arow  = wm * 64 + (lane & 15);
    int akoff = (lane >> 4) * 8;
    int brow  = wn * 32 + (lane & 7) + ((lane >> 4) << 3);
    int bkoff = ((lane >> 3) & 1) * 8;

    load_stage(sb, 0, rowA0, rowB0, Ahi, Amid, Bhi, Bmid, tid);

    for (int t = 0; t < 16; t++) {
        if (t + 1 < 16) {
            load_stage(sb + ((t + 1) & 1) * BUF_BYTES, (t + 1) * 32, rowA0, rowB0,
                       Ahi, Amid, Bhi, Bmid, tid);
            CP_WAIT1();
        } else {
            CP_WAIT0();
        }
        __syncthreads();

        uint32_t base = sb + (t & 1) * BUF_BYTES;
#pragma unroll
        for (int kk = 0; kk < 32; kk += 16) {
            uint32_t bhi[4][2], bmid[4][2];
#pragma unroll
            for (int np = 0; np < 2; np++) {
                uint32_t off = (uint32_t)((brow + np * 16) * PITCH + kk + bkoff) * 2;
                uint32_t r0, r1, r2, r3;
                ldsm_x4(r0, r1, r2, r3, base + SM_B_HI + off);
                bhi[np * 2][0] = r0; bhi[np * 2][1] = r1;
                bhi[np * 2 + 1][0] = r2; bhi[np * 2 + 1][1] = r3;
                ldsm_x4(r0, r1, r2, r3, base + SM_B_MID + off);
                bmid[np * 2][0] = r0; bmid[np * 2][1] = r1;
                bmid[np * 2 + 1][0] = r2; bmid[np * 2 + 1][1] = r3;
            }
#pragma unroll
            for (int mi = 0; mi < 4; mi++) {
                uint32_t ahi[4], amid[4];
                uint32_t off = (uint32_t)((arow + mi * 16) * PITCH + kk + akoff) * 2;
                ldsm_x4(ahi[0], ahi[1], ahi[2], ahi[3], base + SM_A_HI + off);
                ldsm_x4(amid[0], amid[1], amid[2], amid[3], base + SM_A_MID + off);
#pragma unroll
                for (int ni = 0; ni < 4; ni++) {
                    mma16816(acc[mi][ni], ahi, bhi[ni]);
                    mma16816(acc[mi][ni], ahi, bmid[ni]);
                    mma16816(acc[mi][ni], amid, bhi[ni]);
                }
            }
        }
        __syncthreads();
    }

    int colW = blockIdx.x * 128 + wn * 32 + 2 * (lane & 3);
    int rowW = blockIdx.y * 128 + wm * 64 + (lane >> 2);
#pragma unroll
    for (int ni = 0; ni < 4; ni++) {
        int col = colW + ni * 8;
#pragma unroll
        for (int mi = 0; mi < 4; mi++) {
            int row0 = rowW + mi * 16;
            if (MODE == 0) {
                int which = col >> 9;
                int h = (col >> 6) & 7;
                int d = col & 63;
#pragma unroll
                for (int rr = 0; rr < 2; rr++) {
                    int row = row0 + rr * 8;
                    int b = row >> 12, n = row & 4095;
                    size_t idx = ((size_t)(b * 8 + h) * NTOK + n) * HD + d;
                    float vx = acc[mi][ni][rr * 2 + 0];
                    float vy = acc[mi][ni][rr * 2 + 1];
                    if (which == 0) {           // Q: bf16 hi/mid, scaled
                        store_bf16_pair(g_Qhi + idx, g_Qmid + idx, vx * SCALE, vy * SCALE);
                    } else if (which == 1) {    // K: bf16 hi/mid, scaled
                        store_bf16_pair(g_Khi + idx, g_Kmid + idx, vx * SCALE, vy * SCALE);
                    } else {                    // V: bf16 hi/mid
                        store_bf16_pair(g_Vhi + idx, g_Vmid + idx, vx, vy);
                    }
                }
            } else {
                float2 bb = *(const float2*)(bias + col);
#pragma unroll
                for (int rr = 0; rr < 2; rr++) {
                    int row = row0 + rr * 8;
                    float2 v;
                    v.x = acc[mi][ni][rr * 2 + 0] + bb.x;
                    v.y = acc[mi][ni][rr * 2 + 1] + bb.y;
                    *(float2*)(Cout + (size_t)row * 512 + col) = v;
                }
            }
        }
    }
}

// ==================== fp32 -> bf16 hi/mid split ====================
__global__ void split_kernel(const float* __restrict__ src,
                             __nv_bfloat16* __restrict__ hi,
                             __nv_bfloat16* __restrict__ mid, int n4) {
    int i = blockIdx.x * 256 + threadIdx.x;
    if (i >= n4) return;
    float4 v = ((const float4*)src)[i];
    store_bf16_pair(hi + i * 4,     mid + i * 4,     v.x, v.y);
    store_bf16_pair(hi + i * 4 + 2, mid + i * 4 + 2, v.z, v.w);
}

// =====================================================================
// Landmark pooling (+ colmax reset).  Q/K reconstructed from hi+mid.
// =====================================================================
__global__ void pool_kernel() {
    if (blockIdx.x == 0 && threadIdx.x == 0) g_colmax = 0.0f;
    int bm = blockIdx.x;
    int bh = bm >> 6, m = bm & 63;
    int d = threadIdx.x;
    size_t base = (((size_t)bh * NTOK) + m * 64) * HD + d;
    float sq = 0.f, sk = 0.f;
#pragma unroll 8
    for (int t = 0; t < 64; t++) {
        size_t p = base + (size_t)t * HD;
        sq += __bfloat162float(g_Qhi[p]) + __bfloat162float(g_Qmid[p]);
        sk += __bfloat162float(g_Khi[p]) + __bfloat162float(g_Kmid[p]);
    }
    float ql = sq * (1.f / 64.f);
    float kl = sk * (1.f / 64.f);
    int idx = (bh * 64 + m) * 64 + d;
    g_Ql[idx] = ql;
    g_Kl[idx] = kl;
    __nv_bfloat16 hq = __float2bfloat16(ql);
    g_Qlh[idx] = hq;
    g_Qlm[idx] = __float2bfloat16(ql - __bfloat162float(hq));
    __nv_bfloat16 hk = __float2bfloat16(kl);
    g_Klh[idx] = hk;
    g_Klm[idx] = __float2bfloat16(kl - __bfloat162float(hk));
}

// =====================================================================
// kernel_2 = softmax(Ql @ Kl^T) + colsum max
// =====================================================================
__global__ __launch_bounds__(256) void k2_kernel() {
    __shared__ float Qs[64][68];
    __shared__ float Ks[64][68];
    int bh = blockIdx.x, tid = threadIdx.x;
    for (int i = tid; i < 4096; i += 256) {
        Qs[i >> 6][i & 63] = g_Ql[bh * 4096 + i];
        Ks[i >> 6][i & 63] = g_Kl[bh * 4096 + i];
    }
    __syncthreads();
    int ty = tid >> 4, tx = tid & 15, r0 = ty * 4, c0 = tx * 4;
    float acc[4][4] = {};
    for (int k = 0; k < 64; k++) {
        float a[4], b[4];
#pragma unroll
        for (int i = 0; i < 4; i++) a[i] = Qs[r0 + i][k];
#pragma unroll
        for (int j = 0; j < 4; j++) b[j] = Ks[c0 + j][k];
#pragma unroll
        for (int i = 0; i < 4; i++)
#pragma unroll
            for (int j = 0; j < 4; j++) acc[i][j] = fmaf(a[i], b[j], acc[i][j]);
    }
    __syncthreads();
#pragma unroll
    for (int i = 0; i < 4; i++)
#pragma unroll
        for (int j = 0; j < 4; j++) Qs[r0 + i][c0 + j] = acc[i][j];
    __syncthreads();
    if (tid < 64) {
        float mx = -1e30f;
        for (int c = 0; c < 64; c++) mx = fmaxf(mx, Qs[tid][c]);
        float s = 0.f;
        for (int c = 0; c < 64; c++) { float e = __expf(Qs[tid][c] - mx); Qs[tid][c] = e; s += e; }
        float inv = 1.f / s;
        for (int c = 0; c < 64; c++) {
            float v = Qs[tid][c] * inv;
            Qs[tid][c] = v;
            g_K2[bh * 4096 + tid * 64 + c] = v;
        }
    }
    __syncthreads();
    if (tid < 64) {
        float cs = 0.f;
        for (int r = 0; r < 64; r++) cs += Qs[r][tid];
        atomicMax((int*)&g_colmax, __float_as_int(cs));
    }
}

// =====================================================================
// k3 scores via tensor cores: S3 = Ql·K^T, 3-term bf16 split.
// =====================================================================
#define K3_PITCH 72
#define K3_QLH 0
#define K3_QLM (64*K3_PITCH*2)
#define K3_KH  (2*64*K3_PITCH*2)
#define K3_KM  (K3_KH + 256*K3_PITCH*2)
#define K3_SMEM (K3_KM + 256*K3_PITCH*2)

__global__ __launch_bounds__(256) void k3_mma() {
    extern __shared__ __align__(128) char sm[];
    uint32_t sb = smem_u32(sm);
    int nt = blockIdx.x, bh = blockIdx.y, tid = threadIdx.x;
    int lane = tid & 31, wid = tid >> 5;

    const uint4* qh = (const uint4*)(g_Qlh + bh * 4096);
    const uint4* qm = (const uint4*)(g_Qlm + bh * 4096);
#pragma unroll
    for (int it = 0; it < 2; it++) {
        int c = tid + it * 256;
        int row = c >> 3, col = (c & 7) * 8;
        uint32_t off = (uint32_t)(row * K3_PITCH + col) * 2;
        *(uint4*)(sm + K3_QLH + off) = qh[c];
        *(uint4*)(sm + K3_QLM + off) = qm[c];
    }
    const uint4* kh = (const uint4*)(g_Khi + ((size_t)bh * NTOK + nt * 256) * 64);
    const uint4* km = (const uint4*)(g_Kmid + ((size_t)bh * NTOK + nt * 256) * 64);
#pragma unroll
    for (int it = 0; it < 8; it++) {
        int c = tid + it * 256;
        int row = c >> 3, col = (c & 7) * 8;
        uint32_t off = (uint32_t)(row * K3_PITCH + col) * 2;
        *(uint4*)(sm + K3_KH + off) = kh[c];
        *(uint4*)(sm + K3_KM + off) = km[c];
    }
    __syncthreads();

    int arow = lane & 15;
    int akoff = (lane >> 4) * 8;
    int brow = wid * 32 + (lane & 7) + ((lane >> 4) << 3);
    int bkoff = ((lane >> 3) & 1) * 8;

    float acc[4][4][4] = {};
#pragma unroll
    for (int kk = 0; kk < 64; kk += 16) {
        uint32_t bhi[4][2], bmid[4][2];
#pragma unroll
        for (int np = 0; np < 2; np++) {
            uint32_t off = (uint32_t)((brow + np * 16) * K3_PITCH + kk + bkoff) * 2;
            uint32_t r0, r1, r2, r3;
            ldsm_x4(r0, r1, r2, r3, sb + K3_KH + off);
            bhi[np * 2][0] = r0; bhi[np * 2][1] = r1;
            bhi[np * 2 + 1][0] = r2; bhi[np * 2 + 1][1] = r3;
            ldsm_x4(r0, r1, r2, r3, sb + K3_KM + off);
            bmid[np * 2][0] = r0; bmid[np * 2][1] = r1;
            bmid[np * 2 + 1][0] = r2; bmid[np * 2 + 1][1] = r3;
        }
#pragma unroll
        for (int mi = 0; mi < 4; mi++) {
            uint32_t ahi[4], amid[4];
            uint32_t off = (uint32_t)((arow + mi * 16) * K3_PITCH + kk + akoff) * 2;
            ldsm_x4(ahi[0], ahi[1], ahi[2], ahi[3], sb + K3_QLH + off);
            ldsm_x4(amid[0], amid[1], amid[2], amid[3], sb + K3_QLM + off);
#pragma unroll
            for (int ni = 0; ni < 4; ni++) {
                mma16816(acc[mi][ni], ahi, bhi[ni]);
                mma16816(acc[mi][ni], ahi, bmid[ni]);
                mma16816(acc[mi][ni], amid, bhi[ni]);
            }
        }
    }
#pragma unroll
    for (int mi = 0; mi < 4; mi++)
#pragma unroll
        for (int ni = 0; ni < 4; ni++)
#pragma unroll
            for (int rr = 0; rr < 2; rr++) {
                int row = mi * 16 + (lane >> 2) + rr * 8;
                int col = wid * 32 + ni * 8 + 2 * (lane & 3);
                float2 v;
                v.x = acc[mi][ni][rr * 2 + 0];
                v.y = acc[mi][ni][rr * 2 + 1];
                *(float2*)(g_S3 + ((size_t)bh * 64 + row) * NTOK + nt * 256 + col) = v;
            }
}

// =====================================================================
// row softmax over N=4096; emits bf16 hi/mid P
// =====================================================================
__global__ __launch_bounds__(256) void softmax3_kernel() {
    __shared__ float redA[8], redB[8];
    int row = blockIdx.x, tid = threadIdx.x;
    const float* p = g_S3 + (size_t)row * NTOK;
    float v[16];
    float mx = -1e30f;
#pragma unroll
    for (int i = 0; i < 16; i++) { v[i] = p[tid + i * 256]; mx = fmaxf(mx, v[i]); }
#pragma unroll
    for (int o = 16; o; o >>= 1) mx = fmaxf(mx, __shfl_xor_sync(~0u, mx, o));
    if ((tid & 31) == 0) redA[tid >> 5] = mx;
    __syncthreads();
    mx = redA[0];
#pragma unroll
    for (int w = 1; w < 8; w++) mx = fmaxf(mx, redA[w]);
    float s = 0.f;
#pragma unroll
    for (int i = 0; i < 16; i++) { v[i] = __expf(v[i] - mx); s += v[i]; }
#pragma unroll
    for (int o = 16; o; o >>= 1) s += __shfl_xor_sync(~0u, s, o);
    if ((tid & 31) == 0) redB[tid >> 5] = s;
    __syncthreads();
    s = 0.f;
#pragma unroll
    for (int w = 0; w < 8; w++) s += redB[w];
    float inv = 1.f / s;
#pragma unroll
    for (int i = 0; i < 16; i++) {
        float pv = v[i] * inv;
        __nv_bfloat16 h = __float2bfloat16(pv);
        size_t idx = (size_t)row * NTOK + tid + i * 256;
        g_S3h[idx] = h;
        g_S3m[idx] = __float2bfloat16(pv - __bfloat162float(h));
    }
}

// =====================================================================
// T_part = P @ V via tensor cores, V as [k][d] with ldmatrix.trans.
// =====================================================================
#define TP_SPITCH 136
#define TP_VPITCH 72
#define TP_SH 0
#define TP_SM (64*TP_SPITCH*2)
#define TP_VH (2*64*TP_SPITCH*2)
#define TP_VM (TP_VH + 128*TP_VPITCH*2)
#define TP_SMEM (TP_VM + 128*TP_VPITCH*2)

__global__ __launch_bounds__(256) void tpart_mma() {
    extern __shared__ __align__(128) char sm[];
    uint32_t sb = smem_u32(sm);
    int ks = blockIdx.x, bh = blockIdx.y, tid = threadIdx.x;
    int lane = tid & 31, wid = tid >> 5;
    int wm = wid >> 2, wn = wid & 3;

    int arow = wm * 32 + (lane & 15);
    int akoff = (lane >> 4) * 8;
    int bk = lane & 15;
    int bn = wn * 16 + ((lane >> 4) << 3);

    float acc[2][2][4] = {};

    for (int kh = 0; kh < 2; kh++) {
        size_t gk = (size_t)ks * 256 + kh * 128;
        const uint4* shp = (const uint4*)(g_S3h + ((size_t)bh * 64) * NTOK + gk);
        const uint4* smp = (const uint4*)(g_S3m + ((size_t)bh * 64) * NTOK + gk);
        const uint4* vhp = (const uint4*)(g_Vhi + ((size_t)bh * NTOK + gk) * 64);
        const uint4* vmp = (const uint4*)(g_Vmid + ((size_t)bh * NTOK + gk) * 64);
        __syncthreads();
#pragma unroll
        for (int it = 0; it < 4; it++) {
            int c = tid + it * 256;
            int row = c >> 4, col = (c & 15) * 8;
            uint32_t off = (uint32_t)(row * TP_SPITCH + col) * 2;
            size_t gidx = (size_t)row * (NTOK / 8) + (c & 15);
            *(uint4*)(sm + TP_SH + off) = shp[gidx];
            *(uint4*)(sm + TP_SM + off) = smp[gidx];
        }
#pragma unroll
        for (int it = 0; it < 4; it++) {
            int c = tid + it * 256;
            int row = c >> 3, col = (c & 7) * 8;
            uint32_t off = (uint32_t)(row * TP_VPITCH + col) * 2;
            *(uint4*)(sm + TP_VH + off) = vhp[c];
            *(uint4*)(sm + TP_VM + off) = vmp[c];
        }
        __syncthreads();
#pragma unroll
        for (int kk = 0; kk < 128; kk += 16) {
            uint32_t bhi[2][2], bmid[2][2];
            {
                uint32_t off = (uint32_t)((kk + bk) * TP_VPITCH + bn) * 2;
                uint32_t r0, r1, r2, r3;
                ldsm_x4_t(r0, r1, r2, r3, sb + TP_VH + off);
                bhi[0][0] = r0; bhi[0][1] = r1; bhi[1][0] = r2; bhi[1][1] = r3;
                ldsm_x4_t(r0, r1, r2, r3, sb + TP_VM + off);
                bmid[0][0] = r0; bmid[0][1] = r1; bmid[1][0] = r2; bmid[1][1] = r3;
            }
#pragma unroll
            for (int mi = 0; mi < 2; mi++) {
                uint32_t ahi[4], amid[4];
                uint32_t off = (uint32_t)((arow + mi * 16) * TP_SPITCH + kk + akoff) * 2;
                ldsm_x4(ahi[0], ahi[1], ahi[2], ahi[3], sb + TP_SH + off);
                ldsm_x4(amid[0], amid[1], amid[2], amid[3], sb + TP_SM + off);
#pragma unroll
                for (int ni = 0; ni < 2; ni++) {
                    mma16816(acc[mi][ni], ahi, bhi[ni]);
                    mma16816(acc[mi][ni], ahi, bmid[ni]);
                    mma16816(acc[mi][ni], amid, bhi[ni]);
                }
            }
        }
    }
#pragma unroll
    for (int mi = 0; mi < 2; mi++)
#pragma unroll
        for (int ni = 0; ni < 2; ni++)
#pragma unroll
            for (int rr = 0; rr < 2; rr++) {
                int row = wm * 32 + mi * 16 + (lane >> 2) + rr * 8;
                int col = wn * 16 + ni * 8 + 2 * (lane & 3);
                float2 v;
                v.x = acc[mi][ni][rr * 2 + 0];
                v.y = acc[mi][ni][rr * 2 + 1];
                *(float2*)(g_Tpart + (((size_t)ks * BHN + bh) * 64 + row) * 64 + col) = v;
            }
}

// =====================================================================
// Newton-Schulz inverse + W = Vinv @ T (bf16 hi/mid out).  512 threads.
// =====================================================================
__device__ __forceinline__ void mm64w(const float* __restrict__ X,
                                      const float* __restrict__ Y,
                                      float* __restrict__ Z, int tid) {
    int ty = tid >> 5, tx = tid & 31;
    int r0 = ty * 4, c0 = tx * 2;
    float acc[4][2] = {};
    for (int k = 0; k < 64; k++) {
        float a[4], b[2];
#pragma unroll
        for (int i = 0; i < 4; i++) a[i] = X[(r0 + i) * 65 + k];
        b[0] = Y[k * 65 + c0];
        b[1] = Y[k * 65 + c0 + 1];
#pragma unroll
        for (int i = 0; i < 4; i++) {
            acc[i][0] = fmaf(a[i], b[0], acc[i][0]);
            acc[i][1] = fmaf(a[i], b[1], acc[i][1]);
        }
    }
#pragma unroll
    for (int i = 0; i < 4; i++) {
        Z[(r0 + i) * 65 + c0] = acc[i][0];
        Z[(r0 + i) * 65 + c0 + 1] = acc[i][1];
    }
}

__global__ __launch_bounds__(512) void inv_kernel() {
    extern __shared__ float sh[];
    float* Km = sh;
    float* Vm = sh + 64 * 65;
    float* Am = sh + 2 * 64 * 65;
    float* T1 = sh + 3 * 64 * 65;
    float* T2 = sh + 4 * 64 * 65;
    int bh = blockIdx.x, tid = threadIdx.x;
    float ginv = 1.f / g_colmax;
    for (int i = tid; i < 4096; i += 512) {
        int r = i >> 6, c = i & 63;
        Km[r * 65 + c] = g_K2[bh * 4096 + r * 64 + c];
        Vm[r * 65 + c] = g_K2[bh * 4096 + c * 64 + r] * ginv;
        float s = 0.f;
#pragma unroll
        for (int ksp = 0; ksp < KSPLIT; ksp++)
            s += g_Tpart[(size_t)ksp * (BHN * MLAND * HD) + bh * 4096 + i];
        T2[r * 65 + c] = s;
    }
    __syncthreads();
    for (int i = tid; i < 4096; i += 512) {
        int r = i >> 6, c = i & 63;
        g_W[bh * 4096 + i] = T2[r * 65 + c];   // stash T
    }
    for (int it = 0; it < 6; it++) {
        __syncthreads();
        mm64w(Km, Vm, Am, tid);
        __syncthreads();
        for (int i = tid; i < 4096; i += 512) {
            int r = i >> 6, c = i & 63;
            T1[r * 65 + c] = (r == c ? 7.0f : 0.0f) - Am[r * 65 + c];
        }
        __syncthreads();
        mm64w(Am, T1, T2, tid);
        __syncthreads();
        for (int i = tid; i < 4096; i += 512) {
            int r = i >> 6, c = i & 63;
            T2[r * 65 + c] = (r == c ? 15.0f : 0.0f) - T2[r * 65 + c];
        }
        __syncthreads();
        mm64w(Am, T2, T1, tid);
        __syncthreads();
        for (int i = tid; i < 4096; i += 512) {
            int r = i >> 6, c = i & 63;
            T1[r * 65 + c] = (r == c ? 13.0f : 0.0f) - T1[r * 65 + c];
        }
        __syncthreads();
        mm64w(Vm, T1, T2, tid);
        __syncthreads();
        for (int i = tid; i < 4096; i += 512) {
            int r = i >> 6, c = i & 63;
            Vm[r * 65 + c] = 0.25f * T2[r * 65 + c];
        }
    }
    __syncthreads();
    for (int i = tid; i < 4096; i += 512) {
        int r = i >> 6, c = i & 63;
        Am[r * 65 + c] = g_W[bh * 4096 + i];
    }
    __syncthreads();
    mm64w(Vm, Am, T1, tid);
    __syncthreads();
    for (int i = tid * 2; i < 4096; i += 1024) {
        int r = i >> 6, c = i & 63;
        store_bf16_pair(g_Whi + bh * 4096 + i, g_Wmid + bh * 4096 + i,
                        T1[r * 65 + c], T1[r * 65 + c + 1]);
    }
}

// =====================================================================
// Final fused via tensor cores:
//   S = Q @ Kl^T (3-term bf16), softmax in smem, P bf16 hi/mid,
//   X = P @ W (3-term bf16, W as B via ldsm.trans) -> g_Xhi/g_Xmid
// grid (64 n-tiles, 32 bh), 256 threads, 8 warps (4 M x 2 N of 32)
// =====================================================================
#define FA_PITCH 72
#define FA_QH 0
#define FA_QM (64*FA_PITCH*2)       // 9216
#define FA_BH (2*64*FA_PITCH*2)     // 18432
#define FA_BM (3*64*FA_PITCH*2)     // 27648
#define FA_SS (4*64*FA_PITCH*2)     // 36864 (float [64][68])
#define FA_SMEM (FA_SS + 64*68*4)   // 54272

__global__ __launch_bounds__(256) void final_attn() {
    extern __shared__ __align__(128) char sm[];
    uint32_t sb = smem_u32(sm);
    float* Ss = (float*)(sm + FA_SS);
    int nt = blockIdx.x, bh = blockIdx.y, tid = threadIdx.x;
    int lane = tid & 31, wid = tid >> 5;
    int wm = wid >> 1, wn = wid & 1;
    int b = bh >> 3, h = bh & 7;

    // load Q tile (64 tokens x 64 d) and Kl (64 x 64), both hi/mid
    const uint4* qh = (const uint4*)(g_Qhi + (((size_t)bh * NTOK) + nt * 64) * 64);
    const uint4* qm = (const uint4*)(g_Qmid + (((size_t)bh * NTOK) + nt * 64) * 64);
    const uint4* kh = (const uint4*)(g_Klh + bh * 4096);
    const uint4* km = (const uint4*)(g_Klm + bh * 4096);
#pragma unroll
    for (int it = 0; it < 2; it++) {
        int c = tid + it * 256;
        int row = c >> 3, col = (c & 7) * 8;
        uint32_t off = (uint32_t)(row * FA_PITCH + col) * 2;
        *(uint4*)(sm + FA_QH + off) = qh[c];
        *(uint4*)(sm + FA_QM + off) = qm[c];
        *(uint4*)(sm + FA_BH + off) = kh[c];
        *(uint4*)(sm + FA_BM + off) = km[c];
    }
    __syncthreads();

    int arow = wm * 16 + (lane & 15);
    int akoff = (lane >> 4) * 8;
    int brow = wn * 32 + (lane & 7) + ((lane >> 4) << 3);
    int bkoff = ((lane >> 3) & 1) * 8;

    // ---- mma1: S = Q @ Kl^T ----
    float acc[4][4] = {};
#pragma unroll
    for (int kk = 0; kk < 64; kk += 16) {
        uint32_t bhi[4][2], bmid[4][2];
#pragma unroll
        for (int np = 0; np < 2; np++) {
            uint32_t off = (uint32_t)((brow + np * 16) * FA_PITCH + kk + bkoff) * 2;
            uint32_t r0, r1, r2, r3;
            ldsm_x4(r0, r1, r2, r3, sb + FA_BH + off);
            bhi[np * 2][0] = r0; bhi[np * 2][1] = r1;
            bhi[np * 2 + 1][0] = r2; bhi[np * 2 + 1][1] = r3;
            ldsm_x4(r0, r1, r2, r3, sb + FA_BM + off);
            bmid[np * 2][0] = r0; bmid[np * 2][1] = r1;
            bmid[np * 2 + 1][0] = r2; bmid[np * 2 + 1][1] = r3;
        }
        uint32_t ahi[4], amid[4];
        uint32_t off = (uint32_t)(arow * FA_PITCH + kk + akoff) * 2;
        ldsm_x4(ahi[0], ahi[1], ahi[2], ahi[3], sb + FA_QH + off);
        ldsm_x4(amid[0], amid[1], amid[2], amid[3], sb + FA_QM + off);
#pragma unroll
        for (int ni = 0; ni < 4; ni++) {
            mma16816(acc[ni], ahi, bhi[ni]);
            mma16816(acc[ni], ahi, bmid[ni]);
            mma16816(acc[ni], amid, bhi[ni]);
        }
    }
    // write S to smem
#pragma unroll
    for (int ni = 0; ni < 4; ni++)
#pragma unroll
        for (int rr = 0; rr < 2; rr++) {
            int row = wm * 16 + (lane >> 2) + rr * 8;
            int col = wn * 32 + ni * 8 + 2 * (lane & 3);
            Ss[row * 68 + col] = acc[ni][rr * 2 + 0];
            Ss[row * 68 + col + 1] = acc[ni][rr * 2 + 1];
        }
    __syncthreads();

    // load W hi/mid into B buffers (overwrite Kl)
    const uint4* wh = (const uint4*)(g_Whi + bh * 4096);
    const uint4* wmv = (const uint4*)(g_Wmid + bh * 4096);
#pragma unroll
    for (int it = 0; it < 2; it++) {
        int c = tid + it * 256;
        int row = c >> 3, col = (c & 7) * 8;
        uint32_t off = (uint32_t)(row * FA_PITCH + col) * 2;
        *(uint4*)(sm + FA_BH + off) = wh[c];
        *(uint4*)(sm + FA_BM + off) = wmv[c];
    }

    // softmax: thread handles row tid>>2, col quarter (tid&3)*16
    {
        int r = tid >> 2;
        int c0 = (tid & 3) * 16;
        float v[16];
        float mx = -1e30f;
#pragma unroll
        for (int j = 0; j < 16; j++) { v[j] = Ss[r * 68 + c0 + j]; mx = fmaxf(mx, v[j]); }
        mx = fmaxf(mx, __shfl_xor_sync(~0u, mx, 1, 4));
        mx = fmaxf(mx, __shfl_xor_sync(~0u, mx, 2, 4));
        float s = 0.f;
#pragma unroll
        for (int j = 0; j < 16; j++) { v[j] = __expf(v[j] - mx); s += v[j]; }
        s += __shfl_xor_sync(~0u, s, 1, 4);
        s += __shfl_xor_sync(~0u, s, 2, 4);
        float inv = 1.f / s;
        // write P (bf16 hi/mid) into Q buffers
#pragma unroll
        for (int j = 0; j < 16; j += 2) {
            float p0 = v[j] * inv, p1 = v[j + 1] * inv;
            uint32_t off = (uint32_t)(r * FA_PITCH + c0 + j) * 2;
            store_bf16_pair((__nv_bfloat16*)(sm + FA_QH + off),
                            (__nv_bfloat16*)(sm + FA_QM + off), p0, p1);
        }
    }
    __syncthreads();

    // ---- mma2: X = P @ W  (W[k][j] via ldsm.trans) ----
    int bk = lane & 15;
    int bn = wn * 32 + ((lane >> 4) << 3);
    float acc2[4][4] = {};
#pragma unroll
    for (int kk = 0; kk < 64; kk += 16) {
        uint32_t bhi[4][2], bmid[4][2];
#pragma unroll
        for (int half = 0; half < 2; half++) {
            uint32_t off = (uint32_t)((kk + bk) * FA_PITCH + bn + half * 16) * 2;
            uint32_t r0, r1, r2, r3;
            ldsm_x4_t(r0, r1, r2, r3, sb + FA_BH + off);
            bhi[half * 2][0] = r0; bhi[half * 2][1] = r1;
            bhi[half * 2 + 1][0] = r2; bhi[half * 2 + 1][1] = r3;
            ldsm_x4_t(r0, r1, r2, r3, sb + FA_BM + off);
            bmid[half * 2][0] = r0; bmid[half * 2][1] = r1;
            bmid[half * 2 + 1][0] = r2; bmid[half * 2 + 1][1] = r3;
        }
        uint32_t ahi[4], amid[4];
        uint32_t off = (uint32_t)(arow * FA_PITCH + kk + akoff) * 2;
        ldsm_x4(ahi[0], ahi[1], ahi[2], ahi[3], sb + FA_QH + off);
        ldsm_x4(amid[0], amid[1], amid[2], amid[3], sb + FA_QM + off);
#pragma unroll
        for (int ni = 0; ni < 4; ni++) {
            mma16816(acc2[ni], ahi, bhi[ni]);
            mma16816(acc2[ni], ahi, bmid[ni]);
            mma16816(acc2[ni], amid, bhi[ni]);
        }
    }
    // store X bf16 hi/mid
#pragma unroll
    for (int ni = 0; ni < 4; ni++)
#pragma unroll
        for (int rr = 0; rr < 2; rr++) {
            int row = wm * 16 + (lane >> 2) + rr * 8;
            int col = wn * 32 + ni * 8 + 2 * (lane & 3);
            size_t idx = (((size_t)b * NTOK) + nt * 64 + row) * CDIM + h * 64 + col;
            store_bf16_pair(g_Xhi + idx, g_Xmid + idx,
                            acc2[ni][rr * 2 + 0], acc2[ni][rr * 2 + 1]);
        }
}

// =====================================================================
// host launcher
// =====================================================================
extern "C" void kernel_launch(void* const* d_in, const int* in_sizes, int n_in,
                              void* d_out, int out_size) {
    const float* x      = (const float*)d_in[0];
    const float* qkv_w  = (const float*)d_in[1];
    const float* proj_w = (const float*)d_in[2];
    const float* proj_b = (const float*)d_in[3];
    float* out = (float*)d_out;

    __nv_bfloat16 *xhi, *xmid, *whi, *wmid, *phi, *pmid, *Xhi, *Xmid;
    cudaGetSymbolAddress((void**)&xhi,  g_xhi);
    cudaGetSymbolAddress((void**)&xmid, g_xmid);
    cudaGetSymbolAddress((void**)&whi,  g_whi);
    cudaGetSymbolAddress((void**)&wmid, g_wmid);
    cudaGetSymbolAddress((void**)&phi,  g_phi);
    cudaGetSymbolAddress((void**)&pmid, g_pmid);
    cudaGetSymbolAddress((void**)&Xhi,  g_Xhi);
    cudaGetSymbolAddress((void**)&Xmid, g_Xmid);

    split_kernel<<<8192, 256>>>(x, xhi, xmid, 16384 * 512 / 4);
    split_kernel<<<768, 256>>>(qkv_w, whi, wmid, 1536 * 512 / 4);
    split_kernel<<<256, 256>>>(proj_w, phi, pmid, 512 * 512 / 4);

    cudaFuncSetAttribute(hmma_gemm<0>, cudaFuncAttributeMaxDynamicSharedMemorySize, GEMM_SMEM);
    cudaFuncSetAttribute(hmma_gemm<1>, cudaFuncAttributeMaxDynamicSharedMemorySize, GEMM_SMEM);
    cudaFuncSetAttribute(k3_mma, cudaFuncAttributeMaxDynamicSharedMemorySize, K3_SMEM);
    cudaFuncSetAttribute(tpart_mma, cudaFuncAttributeMaxDynamicSharedMemorySize, TP_SMEM);
    cudaFuncSetAttribute(final_attn, cudaFuncAttributeMaxDynamicSharedMemorySize, FA_SMEM);

    hmma_gemm<0><<<dim3(12, 128), 256, GEMM_SMEM>>>(xhi, xmid, whi, wmid, nullptr, nullptr);

    pool_kernel<<<BHN * MLAND, 64>>>();
    k2_kernel<<<BHN, 256>>>();
    k3_mma<<<dim3(16, BHN), 256, K3_SMEM>>>();
    softmax3_kernel<<<BHN * MLAND, 256>>>();
    tpart_mma<<<dim3(KSPLIT, BHN), 256, TP_SMEM>>>();

    const int INV_SMEM = 5 * 64 * 65 * sizeof(float);
    cudaFuncSetAttribute(inv_kernel, cudaFuncAttributeMaxDynamicSharedMemorySize, INV_SMEM);
    inv_kernel<<<BHN, 512, INV_SMEM>>>();

    final_attn<<<dim3(64, BHN), 256, FA_SMEM>>>();

    hmma_gemm<1><<<dim3(4, 128), 256, GEMM_SMEM>>>(Xhi, Xmid, phi, pmid, proj_b, out);
}

// round 7
// speedup vs baseline: 2.4158x; 1.0054x over previous
#include <cuda_runtime.h>
#include <cuda_bf16.h>
#include <math.h>
#include <stdint.h>

// ---------------- problem constants ----------------
#define NBATCH 4
#define NHEAD  8
#define BHN    (NBATCH*NHEAD)      // 32
#define NTOK   4096
#define CDIM   512
#define HD     64
#define MLAND  64
#define KSPLIT 16
#define SCALE  0.35355339059327373f   // 64^-0.25

// ---------------- device scratch ----------------
__device__ float g_Ql[BHN*MLAND*HD];
__device__ float g_Kl[BHN*MLAND*HD];
__device__ float g_K2[BHN*MLAND*MLAND];
__device__ float g_W [BHN*MLAND*HD];          // fp32 stash inside inv
__device__ float g_Tpart[KSPLIT*BHN*MLAND*HD];
__device__ float2 g_stats[BHN*MLAND*KSPLIT];  // (rowmax_t, rowsumexp_t)
__device__ float g_colmax;

// bf16 hi/mid split buffers
__device__ __nv_bfloat16 g_xhi [16384*512];
__device__ __nv_bfloat16 g_xmid[16384*512];
__device__ __nv_bfloat16 g_whi [1536*512];
__device__ __nv_bfloat16 g_wmid[1536*512];
__device__ __nv_bfloat16 g_phi [512*512];
__device__ __nv_bfloat16 g_pmid[512*512];
__device__ __nv_bfloat16 g_Xhi [16384*512];
__device__ __nv_bfloat16 g_Xmid[16384*512];
// middle-stage bf16 operands
__device__ __nv_bfloat16 g_Qhi [BHN*NTOK*HD];   // scaled Q split, [bh][n][d]
__device__ __nv_bfloat16 g_Qmid[BHN*NTOK*HD];
__device__ __nv_bfloat16 g_Khi [BHN*NTOK*HD];   // scaled K split
__device__ __nv_bfloat16 g_Kmid[BHN*NTOK*HD];
__device__ __nv_bfloat16 g_Vhi [BHN*NTOK*HD];
__device__ __nv_bfloat16 g_Vmid[BHN*NTOK*HD];
__device__ __nv_bfloat16 g_Qlh [BHN*MLAND*HD];
__device__ __nv_bfloat16 g_Qlm [BHN*MLAND*HD];
__device__ __nv_bfloat16 g_Klh [BHN*MLAND*HD];
__device__ __nv_bfloat16 g_Klm [BHN*MLAND*HD];
__device__ __nv_bfloat16 g_Whi [BHN*MLAND*HD];
__device__ __nv_bfloat16 g_Wmid[BHN*MLAND*HD];

// ==================== PTX helpers ====================
__device__ __forceinline__ uint32_t smem_u32(const void* p) {
    uint32_t a;
    asm("{ .reg .u64 t; cvta.to.shared.u64 t, %1; cvt.u32.u64 %0, t; }" : "=r"(a) : "l"(p));
    return a;
}
__device__ __forceinline__ void ldsm_x4(uint32_t& r0, uint32_t& r1, uint32_t& r2, uint32_t& r3,
                                        uint32_t addr) {
    asm volatile("ldmatrix.sync.aligned.m8n8.x4.shared.b16 {%0,%1,%2,%3}, [%4];"
                 : "=r"(r0), "=r"(r1), "=r"(r2), "=r"(r3) : "r"(addr));
}
__device__ __forceinline__ void ldsm_x4_t(uint32_t& r0, uint32_t& r1, uint32_t& r2, uint32_t& r3,
                                          uint32_t addr) {
    asm volatile("ldmatrix.sync.aligned.m8n8.x4.trans.shared.b16 {%0,%1,%2,%3}, [%4];"
                 : "=r"(r0), "=r"(r1), "=r"(r2), "=r"(r3) : "r"(addr));
}
__device__ __forceinline__ void mma16816(float* c, const uint32_t* a, const uint32_t* b) {
    asm volatile("mma.sync.aligned.m16n8k16.row.col.f32.bf16.bf16.f32 "
                 "{%0,%1,%2,%3}, {%4,%5,%6,%7}, {%8,%9}, {%0,%1,%2,%3};"
                 : "+f"(c[0]), "+f"(c[1]), "+f"(c[2]), "+f"(c[3])
                 : "r"(a[0]), "r"(a[1]), "r"(a[2]), "r"(a[3]), "r"(b[0]), "r"(b[1]));
}
#define CP_ASYNC(dst, src) asm volatile("cp.async.cg.shared.global [%0], [%1], 16;" :: "r"(dst), "l"(src))
#define CP_COMMIT()        asm volatile("cp.async.commit_group;" ::: "memory")
#define CP_WAIT1()         asm volatile("cp.async.wait_group 1;" ::: "memory")
#define CP_WAIT0()         asm volatile("cp.async.wait_group 0;" ::: "memory")

__device__ __forceinline__ void store_bf16_pair(__nv_bfloat16* hi, __nv_bfloat16* mid,
                                                float x, float y) {
    __nv_bfloat16 h0 = __float2bfloat16(x);
    __nv_bfloat16 h1 = __float2bfloat16(y);
    *(__nv_bfloat162*)hi = __nv_bfloat162(h0, h1);
    *(__nv_bfloat162*)mid = __nv_bfloat162(__float2bfloat16(x - __bfloat162float(h0)),
                                           __float2bfloat16(y - __bfloat162float(h1)));
}

// ==================== bf16 3x-split HMMA GEMM (big GEMMs) ====================
#define PITCH 40
#define MAT_BYTES (128*PITCH*2)
#define SM_A_HI  0
#define SM_A_MID (1*MAT_BYTES)
#define SM_B_HI  (2*MAT_BYTES)
#define SM_B_MID (3*MAT_BYTES)
#define BUF_BYTES (4*MAT_BYTES)
#define GEMM_SMEM (2*BUF_BYTES)

__device__ __forceinline__ void load_stage(uint32_t bufb, int k0, size_t rowA0, size_t rowB0,
                                           const __nv_bfloat16* __restrict__ Ahi,
                                           const __nv_bfloat16* __restrict__ Amid,
                                           const __nv_bfloat16* __restrict__ Bhi,
                                           const __nv_bfloat16* __restrict__ Bmid,
                                           int tid) {
#pragma unroll
    for (int half = 0; half < 2; half++) {
        int c = tid + half * 256;
        int r = c >> 2, cc = (c & 3) * 8;
        uint32_t d = bufb + (uint32_t)(r * PITCH + cc) * 2;
        size_t goffA = (rowA0 + r) * 512 + k0 + cc;
        size_t goffB = (rowB0 + r) * 512 + k0 + cc;
        CP_ASYNC(d + SM_A_HI,  Ahi  + goffA);
        CP_ASYNC(d + SM_A_MID, Amid + goffA);
        CP_ASYNC(d + SM_B_HI,  Bhi  + goffB);
        CP_ASYNC(d + SM_B_MID, Bmid + goffB);
    }
    CP_COMMIT();
}

template<int MODE>
__global__ __launch_bounds__(256, 2) void hmma_gemm(
    const __nv_bfloat16* __restrict__ Ahi, const __nv_bfloat16* __restrict__ Amid,
    const __nv_bfloat16* __restrict__ Bhi, const __nv_bfloat16* __restrict__ Bmid,
    const float* __restrict__ bias, float* __restrict__ Cout)
{
    extern __shared__ __align__(128) char sm[];
    uint32_t sb = smem_u32(sm);
    int tid = threadIdx.x;
    int lane = tid & 31, wid = tid >> 5;
    int wm = wid >> 2, wn = wid & 3;
    size_t rowA0 = (size_t)blockIdx.y * 128;
    size_t rowB0 = (size_t)blockIdx.x * 128;

    float acc[4][4][4] = {};

    int arow  = wm * 64 + (lane & 15);
    int akoff = (lane >> 4) * 8;
    int brow  = wn * 32 + (lane & 7) + ((lane >> 4) << 3);
    int bkoff = ((lane >> 3) & 1) * 8;

    load_stage(sb, 0, rowA0, rowB0, Ahi, Amid, Bhi, Bmid, tid);

    for (int t = 0; t < 16; t++) {
        if (t + 1 < 16) {
            load_stage(sb + ((t + 1) & 1) * BUF_BYTES, (t + 1) * 32, rowA0, rowB0,
                       Ahi, Amid, Bhi, Bmid, tid);
            CP_WAIT1();
        } else {
            CP_WAIT0();
        }
        __syncthreads();

        uint32_t base = sb + (t & 1) * BUF_BYTES;
#pragma unroll
        for (int kk = 0; kk < 32; kk += 16) {
            uint32_t bhi[4][2], bmid[4][2];
#pragma unroll
            for (int np = 0; np < 2; np++) {
                uint32_t off = (uint32_t)((brow + np * 16) * PITCH + kk + bkoff) * 2;
                uint32_t r0, r1, r2, r3;
                ldsm_x4(r0, r1, r2, r3, base + SM_B_HI + off);
                bhi[np * 2][0] = r0; bhi[np * 2][1] = r1;
                bhi[np * 2 + 1][0] = r2; bhi[np * 2 + 1][1] = r3;
                ldsm_x4(r0, r1, r2, r3, base + SM_B_MID + off);
                bmid[np * 2][0] = r0; bmid[np * 2][1] = r1;
                bmid[np * 2 + 1][0] = r2; bmid[np * 2 + 1][1] = r3;
            }
#pragma unroll
            for (int mi = 0; mi < 4; mi++) {
                uint32_t ahi[4], amid[4];
                uint32_t off = (uint32_t)((arow + mi * 16) * PITCH + kk + akoff) * 2;
                ldsm_x4(ahi[0], ahi[1], ahi[2], ahi[3], base + SM_A_HI + off);
                ldsm_x4(amid[0], amid[1], amid[2], amid[3], base + SM_A_MID + off);
#pragma unroll
                for (int ni = 0; ni < 4; ni++) {
                    mma16816(acc[mi][ni], ahi, bhi[ni]);
                    mma16816(acc[mi][ni], ahi, bmid[ni]);
                    mma16816(acc[mi][ni], amid, bhi[ni]);
                }
            }
        }
        __syncthreads();
    }

    int colW = blockIdx.x * 128 + wn * 32 + 2 * (lane & 3);
    int rowW = blockIdx.y * 128 + wm * 64 + (lane >> 2);
#pragma unroll
    for (int ni = 0; ni < 4; ni++) {
        int col = colW + ni * 8;
#pragma unroll
        for (int mi = 0; mi < 4; mi++) {
            int row0 = rowW + mi * 16;
            if (MODE == 0) {
                int which = col >> 9;
                int h = (col >> 6) & 7;
                int d = col & 63;
#pragma unroll
                for (int rr = 0; rr < 2; rr++) {
                    int row = row0 + rr * 8;
                    int b = row >> 12, n = row & 4095;
                    size_t idx = ((size_t)(b * 8 + h) * NTOK + n) * HD + d;
                    float vx = acc[mi][ni][rr * 2 + 0];
                    float vy = acc[mi][ni][rr * 2 + 1];
                    if (which == 0) {
                        store_bf16_pair(g_Qhi + idx, g_Qmid + idx, vx * SCALE, vy * SCALE);
                    } else if (which == 1) {
                        store_bf16_pair(g_Khi + idx, g_Kmid + idx, vx * SCALE, vy * SCALE);
                    } else {
                        store_bf16_pair(g_Vhi + idx, g_Vmid + idx, vx, vy);
                    }
                }
            } else {
                float2 bb = *(const float2*)(bias + col);
#pragma unroll
                for (int rr = 0; rr < 2; rr++) {
                    int row = row0 + rr * 8;
                    float2 v;
                    v.x = acc[mi][ni][rr * 2 + 0] + bb.x;
                    v.y = acc[mi][ni][rr * 2 + 1] + bb.y;
                    *(float2*)(Cout + (size_t)row * 512 + col) = v;
                }
            }
        }
    }
}

// ==================== fp32 -> bf16 hi/mid split ====================
__global__ void split_kernel(const float* __restrict__ src,
                             __nv_bfloat16* __restrict__ hi,
                             __nv_bfloat16* __restrict__ mid, int n4) {
    int i = blockIdx.x * 256 + threadIdx.x;
    if (i >= n4) return;
    float4 v = ((const float4*)src)[i];
    store_bf16_pair(hi + i * 4,     mid + i * 4,     v.x, v.y);
    store_bf16_pair(hi + i * 4 + 2, mid + i * 4 + 2, v.z, v.w);
}

// =====================================================================
// Landmark pooling (+ colmax reset).
// =====================================================================
__global__ void pool_kernel() {
    if (blockIdx.x == 0 && threadIdx.x == 0) g_colmax = 0.0f;
    int bm = blockIdx.x;
    int bh = bm >> 6, m = bm & 63;
    int d = threadIdx.x;
    size_t base = (((size_t)bh * NTOK) + m * 64) * HD + d;
    float sq = 0.f, sk = 0.f;
#pragma unroll 8
    for (int t = 0; t < 64; t++) {
        size_t p = base + (size_t)t * HD;
        sq += __bfloat162float(g_Qhi[p]) + __bfloat162float(g_Qmid[p]);
        sk += __bfloat162float(g_Khi[p]) + __bfloat162float(g_Kmid[p]);
    }
    float ql = sq * (1.f / 64.f);
    float kl = sk * (1.f / 64.f);
    int idx = (bh * 64 + m) * 64 + d;
    g_Ql[idx] = ql;
    g_Kl[idx] = kl;
    __nv_bfloat16 hq = __float2bfloat16(ql);
    g_Qlh[idx] = hq;
    g_Qlm[idx] = __float2bfloat16(ql - __bfloat162float(hq));
    __nv_bfloat16 hk = __float2bfloat16(kl);
    g_Klh[idx] = hk;
    g_Klm[idx] = __float2bfloat16(kl - __bfloat162float(hk));
}

// =====================================================================
// kernel_2 = softmax(Ql @ Kl^T) + colsum max
// =====================================================================
__global__ __launch_bounds__(256) void k2_kernel() {
    __shared__ float Qs[64][68];
    __shared__ float Ks[64][68];
    int bh = blockIdx.x, tid = threadIdx.x;
    for (int i = tid; i < 4096; i += 256) {
        Qs[i >> 6][i & 63] = g_Ql[bh * 4096 + i];
        Ks[i >> 6][i & 63] = g_Kl[bh * 4096 + i];
    }
    __syncthreads();
    int ty = tid >> 4, tx = tid & 15, r0 = ty * 4, c0 = tx * 4;
    float acc[4][4] = {};
    for (int k = 0; k < 64; k++) {
        float a[4], b[4];
#pragma unroll
        for (int i = 0; i < 4; i++) a[i] = Qs[r0 + i][k];
#pragma unroll
        for (int j = 0; j < 4; j++) b[j] = Ks[c0 + j][k];
#pragma unroll
        for (int i = 0; i < 4; i++)
#pragma unroll
            for (int j = 0; j < 4; j++) acc[i][j] = fmaf(a[i], b[j], acc[i][j]);
    }
    __syncthreads();
#pragma unroll
    for (int i = 0; i < 4; i++)
#pragma unroll
        for (int j = 0; j < 4; j++) Qs[r0 + i][c0 + j] = acc[i][j];
    __syncthreads();
    if (tid < 64) {
        float mx = -1e30f;
        for (int c = 0; c < 64; c++) mx = fmaxf(mx, Qs[tid][c]);
        float s = 0.f;
        for (int c = 0; c < 64; c++) { float e = __expf(Qs[tid][c] - mx); Qs[tid][c] = e; s += e; }
        float inv = 1.f / s;
        for (int c = 0; c < 64; c++) {
            float v = Qs[tid][c] * inv;
            Qs[tid][c] = v;
            g_K2[bh * 4096 + tid * 64 + c] = v;
        }
    }
    __syncthreads();
    if (tid < 64) {
        float cs = 0.f;
        for (int r = 0; r < 64; r++) cs += Qs[r][tid];
        atomicMax((int*)&g_colmax, __float_as_int(cs));
    }
}

// =====================================================================
// FUSED: S = Ql@K^T (tile of 256 tokens) -> per-tile softmax stats ->
//        P = exp(S - m_t) -> Tpart_t = P @ V.   grid (16, 32), 256 thr.
// Combine (rescale by exp(m_t - m_glob) / sum_glob) happens in inv_kernel.
// =====================================================================
#define AT_QPITCH 72
#define AT_PPITCH 264
#define AT_QH 0
#define AT_QM 9216
#define AT_KH 18432                      // 256*72*2 = 36864
#define AT_KM 55296
#define AT_PH 0                          // P 64x264 bf16 = 33792 (overlaps dead Q/K)
#define AT_PM 33792
#define AT_VH 92160                      // 128*72*2 = 18432
#define AT_VM 110592
#define AT_SMEM 129024

__global__ __launch_bounds__(256) void attn3_fused() {
    extern __shared__ __align__(128) char sm[];
    __shared__ float s_red[64][9];
    __shared__ float s_rowmax[64];
    uint32_t sb = smem_u32(sm);
    int ks = blockIdx.x, bh = blockIdx.y, tid = threadIdx.x;
    int lane = tid & 31, wid = tid >> 5;

    // ---- phase 1: load Ql + K tile, S = Ql @ K^T ----
    const uint4* qh = (const uint4*)(g_Qlh + bh * 4096);
    const uint4* qm = (const uint4*)(g_Qlm + bh * 4096);
#pragma unroll
    for (int it = 0; it < 2; it++) {
        int c = tid + it * 256;
        int row = c >> 3, col = (c & 7) * 8;
        uint32_t off = (uint32_t)(row * AT_QPITCH + col) * 2;
        *(uint4*)(sm + AT_QH + off) = qh[c];
        *(uint4*)(sm + AT_QM + off) = qm[c];
    }
    const uint4* kh = (const uint4*)(g_Khi + ((size_t)bh * NTOK + ks * 256) * 64);
    const uint4* km = (const uint4*)(g_Kmid + ((size_t)bh * NTOK + ks * 256) * 64);
#pragma unroll
    for (int it = 0; it < 8; it++) {
        int c = tid + it * 256;
        int row = c >> 3, col = (c & 7) * 8;
        uint32_t off = (uint32_t)(row * AT_QPITCH + col) * 2;
        *(uint4*)(sm + AT_KH + off) = kh[c];
        *(uint4*)(sm + AT_KM + off) = km[c];
    }
    __syncthreads();

    int arow = lane & 15;
    int akoff = (lane >> 4) * 8;
    int brow = wid * 32 + (lane & 7) + ((lane >> 4) << 3);
    int bkoff = ((lane >> 3) & 1) * 8;

    float acc[4][4][4] = {};
#pragma unroll
    for (int kk = 0; kk < 64; kk += 16) {
        uint32_t bhi[4][2], bmid[4][2];
#pragma unroll
        for (int np = 0; np < 2; np++) {
            uint32_t off = (uint32_t)((brow + np * 16) * AT_QPITCH + kk + bkoff) * 2;
            uint32_t r0, r1, r2, r3;
            ldsm_x4(r0, r1, r2, r3, sb + AT_KH + off);
            bhi[np * 2][0] = r0; bhi[np * 2][1] = r1;
            bhi[np * 2 + 1][0] = r2; bhi[np * 2 + 1][1] = r3;
            ldsm_x4(r0, r1, r2, r3, sb + AT_KM + off);
            bmid[np * 2][0] = r0; bmid[np * 2][1] = r1;
            bmid[np * 2 + 1][0] = r2; bmid[np * 2 + 1][1] = r3;
        }
#pragma unroll
        for (int mi = 0; mi < 4; mi++) {
            uint32_t ahi[4], amid[4];
            uint32_t off = (uint32_t)((arow + mi * 16) * AT_QPITCH + kk + akoff) * 2;
            ldsm_x4(ahi[0], ahi[1], ahi[2], ahi[3], sb + AT_QH + off);
            ldsm_x4(amid[0], amid[1], amid[2], amid[3], sb + AT_QM + off);
#pragma unroll
            for (int ni = 0; ni < 4; ni++) {
                mma16816(acc[mi][ni], ahi, bhi[ni]);
                mma16816(acc[mi][ni], ahi, bmid[ni]);
                mma16816(acc[mi][ni], amid, bhi[ni]);
            }
        }
    }

    // ---- phase 2: per-tile row max (rows: mi*16 + (lane>>2) + rr*8) ----
#pragma unroll
    for (int mi = 0; mi < 4; mi++)
#pragma unroll
        for (int rr = 0; rr < 2; rr++) {
            float m = -1e30f;
#pragma unroll
            for (int ni = 0; ni < 4; ni++) {
                m = fmaxf(m, acc[mi][ni][rr * 2 + 0]);
                m = fmaxf(m, acc[mi][ni][rr * 2 + 1]);
            }
            m = fmaxf(m, __shfl_xor_sync(~0u, m, 1, 4));
            m = fmaxf(m, __shfl_xor_sync(~0u, m, 2, 4));
            if ((lane & 3) == 0)
                s_red[mi * 16 + (lane >> 2) + rr * 8][wid] = m;
        }
    __syncthreads();
    if (tid < 64) {
        float m = s_red[tid][0];
#pragma unroll
        for (int w = 1; w < 8; w++) m = fmaxf(m, s_red[tid][w]);
        s_rowmax[tid] = m;
    }
    __syncthreads();

    // ---- phase 3: p = exp(s - m_tile); row sums; write stats ----
#pragma unroll
    for (int mi = 0; mi < 4; mi++)
#pragma unroll
        for (int rr = 0; rr < 2; rr++) {
            int row = mi * 16 + (lane >> 2) + rr * 8;
            float m = s_rowmax[row];
            float s = 0.f;
#pragma unroll
            for (int ni = 0; ni < 4; ni++) {
                float p0 = __expf(acc[mi][ni][rr * 2 + 0] - m);
                float p1 = __expf(acc[mi][ni][rr * 2 + 1] - m);
                acc[mi][ni][rr * 2 + 0] = p0;
                acc[mi][ni][rr * 2 + 1] = p1;
                s += p0 + p1;
            }
            s += __shfl_xor_sync(~0u, s, 1, 4);
            s += __shfl_xor_sync(~0u, s, 2, 4);
            if ((lane & 3) == 0) s_red[row][wid] = s;
        }
    __syncthreads();
    if (tid < 64) {
        float s = 0.f;
#pragma unroll
        for (int w = 0; w < 8; w++) s += s_red[tid][w];
        g_stats[((size_t)bh * 64 + tid) * KSPLIT + ks] = make_float2(s_rowmax[tid], s);
    }

    // ---- phase 4: store P (bf16 hi/mid) to smem [row][col], pitch 264 ----
    // (overwrites Ql/K buffers; all reads of those finished above)
    __syncthreads();
#pragma unroll
    for (int mi = 0; mi < 4; mi++)
#pragma unroll
        for (int ni = 0; ni < 4; ni++)
#pragma unroll
            for (int rr = 0; rr < 2; rr++) {
                int row = mi * 16 + (lane >> 2) + rr * 8;
                int col = wid * 32 + ni * 8 + 2 * (lane & 3);
                uint32_t off = (uint32_t)(row * AT_PPITCH + col) * 2;
                store_bf16_pair((__nv_bfloat16*)(sm + AT_PH + off),
                                (__nv_bfloat16*)(sm + AT_PM + off),
                                acc[mi][ni][rr * 2 + 0], acc[mi][ni][rr * 2 + 1]);
            }

    // ---- phase 5: Tpart = P @ V (V halves streamed; ldsm.trans B) ----
    int wm = wid >> 2, wn = wid & 3;
    int arow2 = wm * 32 + (lane & 15);
    int bk = lane & 15;
    int bn = wn * 16 + ((lane >> 4) << 3);
    float acc2[2][2][4] = {};

    for (int khalf = 0; khalf < 2; khalf++) {
        size_t gk = (size_t)ks * 256 + khalf * 128;
        const uint4* vhp = (const uint4*)(g_Vhi + ((size_t)bh * NTOK + gk) * 64);
        const uint4* vmp = (const uint4*)(g_Vmid + ((size_t)bh * NTOK + gk) * 64);
        __syncthreads();
#pragma unroll
        for (int it = 0; it < 4; it++) {
            int c = tid + it * 256;
            int row = c >> 3, col = (c & 7) * 8;
            uint32_t off = (uint32_t)(row * AT_QPITCH + col) * 2;
            *(uint4*)(sm + AT_VH + off) = vhp[c];
            *(uint4*)(sm + AT_VM + off) = vmp[c];
        }
        __syncthreads();
#pragma unroll
        for (int kk = 0; kk < 128; kk += 16) {
            uint32_t bhi[2][2], bmid[2][2];
            {
                uint32_t off = (uint32_t)((kk + bk) * AT_QPITCH + bn) * 2;
                uint32_t r0, r1, r2, r3;
                ldsm_x4_t(r0, r1, r2, r3, sb + AT_VH + off);
                bhi[0][0] = r0; bhi[0][1] = r1; bhi[1][0] = r2; bhi[1][1] = r3;
                ldsm_x4_t(r0, r1, r2, r3, sb + AT_VM + off);
                bmid[0][0] = r0; bmid[0][1] = r1; bmid[1][0] = r2; bmid[1][1] = r3;
            }
#pragma unroll
            for (int mi = 0; mi < 2; mi++) {
                uint32_t ahi[4], amid[4];
                uint32_t off = (uint32_t)((arow2 + mi * 16) * AT_PPITCH
                                          + khalf * 128 + kk + akoff) * 2;
                ldsm_x4(ahi[0], ahi[1], ahi[2], ahi[3], sb + AT_PH + off);
                ldsm_x4(amid[0], amid[1], amid[2], amid[3], sb + AT_PM + off);
#pragma unroll
                for (int ni = 0; ni < 2; ni++) {
                    mma16816(acc2[mi][ni], ahi, bhi[ni]);
                    mma16816(acc2[mi][ni], ahi, bmid[ni]);
                    mma16816(acc2[mi][ni], amid, bhi[ni]);
                }
            }
        }
    }
#pragma unroll
    for (int mi = 0; mi < 2; mi++)
#pragma unroll
        for (int ni = 0; ni < 2; ni++)
#pragma unroll
            for (int rr = 0; rr < 2; rr++) {
                int row = wm * 32 + mi * 16 + (lane >> 2) + rr * 8;
                int col = wn * 16 + ni * 8 + 2 * (lane & 3);
                float2 v;
                v.x = acc2[mi][ni][rr * 2 + 0];
                v.y = acc2[mi][ni][rr * 2 + 1];
                *(float2*)(g_Tpart + (((size_t)ks * BHN + bh) * 64 + row) * 64 + col) = v;
            }
}

// =====================================================================
// Newton-Schulz inverse + W = Vinv @ T.  512 threads.
// Prologue: split-softmax combine of Tpart with g_stats.
// =====================================================================
__device__ __forceinline__ void mm64w(const float* __restrict__ X,
                                      const float* __restrict__ Y,
                                      float* __restrict__ Z, int tid) {
    int ty = tid >> 5, tx = tid & 31;
    int r0 = ty * 4, c0 = tx * 2;
    float acc[4][2] = {};
    for (int k = 0; k < 64; k++) {
        float a[4], b[2];
#pragma unroll
        for (int i = 0; i < 4; i++) a[i] = X[(r0 + i) * 65 + k];
        b[0] = Y[k * 65 + c0];
        b[1] = Y[k * 65 + c0 + 1];
#pragma unroll
        for (int i = 0; i < 4; i++) {
            acc[i][0] = fmaf(a[i], b[0], acc[i][0]);
            acc[i][1] = fmaf(a[i], b[1], acc[i][1]);
        }
    }
#pragma unroll
    for (int i = 0; i < 4; i++) {
        Z[(r0 + i) * 65 + c0] = acc[i][0];
        Z[(r0 + i) * 65 + c0 + 1] = acc[i][1];
    }
}

__global__ __launch_bounds__(512) void inv_kernel() {
    extern __shared__ float sh[];
    __shared__ float sc[64][17];
    __shared__ float sinv[64];
    float* Km = sh;
    float* Vm = sh + 64 * 65;
    float* Am = sh + 2 * 64 * 65;
    float* T1 = sh + 3 * 64 * 65;
    float* T2 = sh + 4 * 64 * 65;
    int bh = blockIdx.x, tid = threadIdx.x;
    float ginv = 1.f / g_colmax;

    // softmax combine factors per row
    if (tid < 64) {
        int row = tid;
        float2 st[KSPLIT];
        float m = -1e30f;
#pragma unroll
        for (int t = 0; t < KSPLIT; t++) {
            st[t] = g_stats[((size_t)bh * 64 + row) * KSPLIT + t];
            m = fmaxf(m, st[t].x);
        }
        float sum = 0.f;
#pragma unroll
        for (int t = 0; t < KSPLIT; t++) {
            float e = __expf(st[t].x - m);
            sc[row][t] = e;
            sum += e * st[t].y;
        }
        sinv[row] = 1.f / sum;
    }
    __syncthreads();

    for (int i = tid; i < 4096; i += 512) {
        int r = i >> 6, c = i & 63;
        Km[r * 65 + c] = g_K2[bh * 4096 + r * 64 + c];
        Vm[r * 65 + c] = g_K2[bh * 4096 + c * 64 + r] * ginv;
        float s = 0.f;
#pragma unroll
        for (int t = 0; t < KSPLIT; t++)
            s = fmaf(g_Tpart[(size_t)t * (BHN * MLAND * HD) + bh * 4096 + i], sc[r][t], s);
        g_W[bh * 4096 + i] = s * sinv[r];   // stash combined T
    }
    for (int it = 0; it < 6; it++) {
        __syncthreads();
        mm64w(Km, Vm, Am, tid);
        __syncthreads();
        for (int i = tid; i < 4096; i += 512) {
            int r = i >> 6, c = i & 63;
            T1[r * 65 + c] = (r == c ? 7.0f : 0.0f) - Am[r * 65 + c];
        }
        __syncthreads();
        mm64w(Am, T1, T2, tid);
        __syncthreads();
        for (int i = tid; i < 4096; i += 512) {
            int r = i >> 6, c = i & 63;
            T2[r * 65 + c] = (r == c ? 15.0f : 0.0f) - T2[r * 65 + c];
        }
        __syncthreads();
        mm64w(Am, T2, T1, tid);
        __syncthreads();
        for (int i = tid; i < 4096; i += 512) {
            int r = i >> 6, c = i & 63;
            T1[r * 65 + c] = (r == c ? 13.0f : 0.0f) - T1[r * 65 + c];
        }
        __syncthreads();
        mm64w(Vm, T1, T2, tid);
        __syncthreads();
        for (int i = tid; i < 4096; i += 512) {
            int r = i >> 6, c = i & 63;
            Vm[r * 65 + c] = 0.25f * T2[r * 65 + c];
        }
    }
    __syncthreads();
    for (int i = tid; i < 4096; i += 512) {
        int r = i >> 6, c = i & 63;
        Am[r * 65 + c] = g_W[bh * 4096 + i];
    }
    __syncthreads();
    mm64w(Vm, Am, T1, tid);
    __syncthreads();
    for (int i = tid * 2; i < 4096; i += 1024) {
        int r = i >> 6, c = i & 63;
        store_bf16_pair(g_Whi + bh * 4096 + i, g_Wmid + bh * 4096 + i,
                        T1[r * 65 + c], T1[r * 65 + c + 1]);
    }
}

// =====================================================================
// Final fused via tensor cores (unchanged from round 6)
// =====================================================================
#define FA_PITCH 72
#define FA_QH 0
#define FA_QM (64*FA_PITCH*2)
#define FA_BH (2*64*FA_PITCH*2)
#define FA_BM (3*64*FA_PITCH*2)
#define FA_SS (4*64*FA_PITCH*2)
#define FA_SMEM (FA_SS + 64*68*4)

__global__ __launch_bounds__(256) void final_attn() {
    extern __shared__ __align__(128) char sm[];
    uint32_t sb = smem_u32(sm);
    float* Ss = (float*)(sm + FA_SS);
    int nt = blockIdx.x, bh = blockIdx.y, tid = threadIdx.x;
    int lane = tid & 31, wid = tid >> 5;
    int wm = wid >> 1, wn = wid & 1;
    int b = bh >> 3, h = bh & 7;

    const uint4* qh = (const uint4*)(g_Qhi + (((size_t)bh * NTOK) + nt * 64) * 64);
    const uint4* qm = (const uint4*)(g_Qmid + (((size_t)bh * NTOK) + nt * 64) * 64);
    const uint4* kh = (const uint4*)(g_Klh + bh * 4096);
    const uint4* km = (const uint4*)(g_Klm + bh * 4096);
#pragma unroll
    for (int it = 0; it < 2; it++) {
        int c = tid + it * 256;
        int row = c >> 3, col = (c & 7) * 8;
        uint32_t off = (uint32_t)(row * FA_PITCH + col) * 2;
        *(uint4*)(sm + FA_QH + off) = qh[c];
        *(uint4*)(sm + FA_QM + off) = qm[c];
        *(uint4*)(sm + FA_BH + off) = kh[c];
        *(uint4*)(sm + FA_BM + off) = km[c];
    }
    __syncthreads();

    int arow = wm * 16 + (lane & 15);
    int akoff = (lane >> 4) * 8;
    int brow = wn * 32 + (lane & 7) + ((lane >> 4) << 3);
    int bkoff = ((lane >> 3) & 1) * 8;

    float acc[4][4] = {};
#pragma unroll
    for (int kk = 0; kk < 64; kk += 16) {
        uint32_t bhi[4][2], bmid[4][2];
#pragma unroll
        for (int np = 0; np < 2; np++) {
            uint32_t off = (uint32_t)((brow + np * 16) * FA_PITCH + kk + bkoff) * 2;
            uint32_t r0, r1, r2, r3;
            ldsm_x4(r0, r1, r2, r3, sb + FA_BH + off);
            bhi[np * 2][0] = r0; bhi[np * 2][1] = r1;
            bhi[np * 2 + 1][0] = r2; bhi[np * 2 + 1][1] = r3;
            ldsm_x4(r0, r1, r2, r3, sb + FA_BM + off);
            bmid[np * 2][0] = r0; bmid[np * 2][1] = r1;
            bmid[np * 2 + 1][0] = r2; bmid[np * 2 + 1][1] = r3;
        }
        uint32_t ahi[4], amid[4];
        uint32_t off = (uint32_t)(arow * FA_PITCH + kk + akoff) * 2;
        ldsm_x4(ahi[0], ahi[1], ahi[2], ahi[3], sb + FA_QH + off);
        ldsm_x4(amid[0], amid[1], amid[2], amid[3], sb + FA_QM + off);
#pragma unroll
        for (int ni = 0; ni < 4; ni++) {
            mma16816(acc[ni], ahi, bhi[ni]);
            mma16816(acc[ni], ahi, bmid[ni]);
            mma16816(acc[ni], amid, bhi[ni]);
        }
    }
#pragma unroll
    for (int ni = 0; ni < 4; ni++)
#pragma unroll
        for (int rr = 0; rr < 2; rr++) {
            int row = wm * 16 + (lane >> 2) + rr * 8;
            int col = wn * 32 + ni * 8 + 2 * (lane & 3);
            Ss[row * 68 + col] = acc[ni][rr * 2 + 0];
            Ss[row * 68 + col + 1] = acc[ni][rr * 2 + 1];
        }
    __syncthreads();

    const uint4* wh = (const uint4*)(g_Whi + bh * 4096);
    const uint4* wmv = (const uint4*)(g_Wmid + bh * 4096);
#pragma unroll
    for (int it = 0; it < 2; it++) {
        int c = tid + it * 256;
        int row = c >> 3, col = (c & 7) * 8;
        uint32_t off = (uint32_t)(row * FA_PITCH + col) * 2;
        *(uint4*)(sm + FA_BH + off) = wh[c];
        *(uint4*)(sm + FA_BM + off) = wmv[c];
    }

    {
        int r = tid >> 2;
        int c0 = (tid & 3) * 16;
        float v[16];
        float mx = -1e30f;
#pragma unroll
        for (int j = 0; j < 16; j++) { v[j] = Ss[r * 68 + c0 + j]; mx = fmaxf(mx, v[j]); }
        mx = fmaxf(mx, __shfl_xor_sync(~0u, mx, 1, 4));
        mx = fmaxf(mx, __shfl_xor_sync(~0u, mx, 2, 4));
        float s = 0.f;
#pragma unroll
        for (int j = 0; j < 16; j++) { v[j] = __expf(v[j] - mx); s += v[j]; }
        s += __shfl_xor_sync(~0u, s, 1, 4);
        s += __shfl_xor_sync(~0u, s, 2, 4);
        float inv = 1.f / s;
#pragma unroll
        for (int j = 0; j < 16; j += 2) {
            float p0 = v[j] * inv, p1 = v[j + 1] * inv;
            uint32_t off = (uint32_t)(r * FA_PITCH + c0 + j) * 2;
            store_bf16_pair((__nv_bfloat16*)(sm + FA_QH + off),
                            (__nv_bfloat16*)(sm + FA_QM + off), p0, p1);
        }
    }
    __syncthreads();

    int bk = lane & 15;
    int bn = wn * 32 + ((lane >> 4) << 3);
    float acc2[4][4] = {};
#pragma unroll
    for (int kk = 0; kk < 64; kk += 16) {
        uint32_t bhi[4][2], bmid[4][2];
#pragma unroll
        for (int half = 0; half < 2; half++) {
            uint32_t off = (uint32_t)((kk + bk) * FA_PITCH + bn + half * 16) * 2;
            uint32_t r0, r1, r2, r3;
            ldsm_x4_t(r0, r1, r2, r3, sb + FA_BH + off);
            bhi[half * 2][0] = r0; bhi[half * 2][1] = r1;
            bhi[half * 2 + 1][0] = r2; bhi[half * 2 + 1][1] = r3;
            ldsm_x4_t(r0, r1, r2, r3, sb + FA_BM + off);
            bmid[half * 2][0] = r0; bmid[half * 2][1] = r1;
            bmid[half * 2 + 1][0] = r2; bmid[half * 2 + 1][1] = r3;
        }
        uint32_t ahi[4], amid[4];
        uint32_t off = (uint32_t)(arow * FA_PITCH + kk + akoff) * 2;
        ldsm_x4(ahi[0], ahi[1], ahi[2], ahi[3], sb + FA_QH + off);
        ldsm_x4(amid[0], amid[1], amid[2], amid[3], sb + FA_QM + off);
#pragma unroll
        for (int ni = 0; ni < 4; ni++) {
            mma16816(acc2[ni], ahi, bhi[ni]);
            mma16816(acc2[ni], ahi, bmid[ni]);
            mma16816(acc2[ni], amid, bhi[ni]);
        }
    }
#pragma unroll
    for (int ni = 0; ni < 4; ni++)
#pragma unroll
        for (int rr = 0; rr < 2; rr++) {
            int row = wm * 16 + (lane >> 2) + rr * 8;
            int col = wn * 32 + ni * 8 + 2 * (lane & 3);
            size_t idx = (((size_t)b * NTOK) + nt * 64 + row) * CDIM + h * 64 + col;
            store_bf16_pair(g_Xhi + idx, g_Xmid + idx,
                            acc2[ni][rr * 2 + 0], acc2[ni][rr * 2 + 1]);
        }
}

// =====================================================================
// host launcher
// =====================================================================
extern "C" void kernel_launch(void* const* d_in, const int* in_sizes, int n_in,
                              void* d_out, int out_size) {
    const float* x      = (const float*)d_in[0];
    const float* qkv_w  = (const float*)d_in[1];
    const float* proj_w = (const float*)d_in[2];
    const float* proj_b = (const float*)d_in[3];
    float* out = (float*)d_out;

    __nv_bfloat16 *xhi, *xmid, *whi, *wmid, *phi, *pmid, *Xhi, *Xmid;
    cudaGetSymbolAddress((void**)&xhi,  g_xhi);
    cudaGetSymbolAddress((void**)&xmid, g_xmid);
    cudaGetSymbolAddress((void**)&whi,  g_whi);
    cudaGetSymbolAddress((void**)&wmid, g_wmid);
    cudaGetSymbolAddress((void**)&phi,  g_phi);
    cudaGetSymbolAddress((void**)&pmid, g_pmid);
    cudaGetSymbolAddress((void**)&Xhi,  g_Xhi);
    cudaGetSymbolAddress((void**)&Xmid, g_Xmid);

    split_kernel<<<8192, 256>>>(x, xhi, xmid, 16384 * 512 / 4);
    split_kernel<<<768, 256>>>(qkv_w, whi, wmid, 1536 * 512 / 4);
    split_kernel<<<256, 256>>>(proj_w, phi, pmid, 512 * 512 / 4);

    cudaFuncSetAttribute(hmma_gemm<0>, cudaFuncAttributeMaxDynamicSharedMemorySize, GEMM_SMEM);
    cudaFuncSetAttribute(hmma_gemm<1>, cudaFuncAttributeMaxDynamicSharedMemorySize, GEMM_SMEM);
    cudaFuncSetAttribute(attn3_fused, cudaFuncAttributeMaxDynamicSharedMemorySize, AT_SMEM);
    cudaFuncSetAttribute(final_attn, cudaFuncAttributeMaxDynamicSharedMemorySize, FA_SMEM);

    hmma_gemm<0><<<dim3(12, 128), 256, GEMM_SMEM>>>(xhi, xmid, whi, wmid, nullptr, nullptr);

    pool_kernel<<<BHN * MLAND, 64>>>();
    k2_kernel<<<BHN, 256>>>();
    attn3_fused<<<dim3(KSPLIT, BHN), 256, AT_SMEM>>>();

    const int INV_SMEM = 5 * 64 * 65 * sizeof(float);
    cudaFuncSetAttribute(inv_kernel, cudaFuncAttributeMaxDynamicSharedMemorySize, INV_SMEM);
    inv_kernel<<<BHN, 512, INV_SMEM>>>();

    final_attn<<<dim3(64, BHN), 256, FA_SMEM>>>();

    hmma_gemm<1><<<dim3(4, 128), 256, GEMM_SMEM>>>(Xhi, Xmid, phi, pmid, proj_b, out);
}